// round 8
// baseline (speedup 1.0000x reference)
#include <cuda_runtime.h>
#include <cuda_fp16.h>
#include <cstdint>
#include <math.h>

#define NTOK   16384
#define TLEN   2048
#define DMODEL 768
#define DINNER 1536
#define DSTATE 64
#define NHEADS 24
#define CONVDIM 1664
#define DINPROJ 3224
#define NCHUNK 32
#define NBLK_SSD (8*NCHUNK*NHEADS)   /* 6144 */
#define SMP 65
#define LOSCALE 2048.f
#define INVLOSCALE (1.f/2048.f)

// ------------------------- scratch (device globals) -------------------------
__device__ float g_hmid[(size_t)NTOK*128];
__device__ float g_h   [(size_t)NTOK*DMODEL];
__device__ float g_zx  [(size_t)NTOK*DINPROJ];
__device__ float g_xBC [(size_t)NTOK*CONVDIM];
__device__ float g_dt  [(size_t)NTOK*NHEADS];
__device__ float g_ys  [(size_t)NTOK*DINNER];
__device__ float g_y2  [(size_t)NTOK*DMODEL];
__device__ float g_S   [(size_t)NBLK_SSD*4096];
__device__ float g_seg [(size_t)NBLK_SSD*64];
__device__ float g_cd  [NBLK_SSD];
__device__ float g_wt  [(size_t)(3+9+27)*128*256];   /* conv weights NT fp32 */
// fp16 split buffers
__device__ __half g_ahi[(size_t)NTOK*DINNER];
__device__ __half g_alo[(size_t)NTOK*DINNER];
__device__ __half g_hmh[(size_t)NTOK*128];
__device__ __half g_hml[(size_t)NTOK*128];
__device__ __half g_wch[(size_t)(3+9+27)*128*256];
__device__ __half g_wcl[(size_t)(3+9+27)*128*256];
__device__ __half g_wih[(size_t)4*DINPROJ*DMODEL];
__device__ __half g_wil[(size_t)4*DINPROJ*DMODEL];
__device__ __half g_woh[(size_t)4*DMODEL*DINNER];
__device__ __half g_wol[(size_t)4*DMODEL*DINNER];

// ------------------------- PTX helpers -------------------------
__device__ __forceinline__ uint32_t smem_u32(const void* p) {
    uint32_t a;
    asm("{ .reg .u64 t; cvta.to.shared.u64 t, %1; cvt.u32.u64 %0, t; }" : "=r"(a) : "l"(p));
    return a;
}
__device__ __forceinline__ void cp16z(uint32_t dst, const void* src, int srcsz) {
    asm volatile("cp.async.cg.shared.global [%0], [%1], 16, %2;" :: "r"(dst), "l"(src), "r"(srcsz));
}
__device__ __forceinline__ void ldsm4(uint32_t* r, uint32_t addr) {
    asm volatile("ldmatrix.sync.aligned.m8n8.x4.shared.b16 {%0,%1,%2,%3}, [%4];"
        : "=r"(r[0]), "=r"(r[1]), "=r"(r[2]), "=r"(r[3]) : "r"(addr));
}
__device__ __forceinline__ void mma16816(float* c, const uint32_t* a, const uint32_t* b) {
    asm volatile("mma.sync.aligned.m16n8k16.row.col.f32.f16.f16.f32 "
        "{%0,%1,%2,%3}, {%4,%5,%6,%7}, {%8,%9}, {%0,%1,%2,%3};"
        : "+f"(c[0]), "+f"(c[1]), "+f"(c[2]), "+f"(c[3])
        : "r"(a[0]), "r"(a[1]), "r"(a[2]), "r"(a[3]), "r"(b[0]), "r"(b[1]));
}
__device__ __forceinline__ void split1(float v, __half& hi, __half& lo) {
    hi = __float2half_rn(v);
    lo = __float2half_rn((v - __half2float(hi)) * LOSCALE);
}

// ------------------------- split fp32 -> fp16 hi/lo(x2048) -------------------------
__global__ void split_half(const float4* __restrict__ src,
                           __half* __restrict__ hi,
                           __half* __restrict__ lo, int n4)
{
    int i = blockIdx.x * 256 + threadIdx.x;
    if (i >= n4) return;
    float4 v = src[i];
    float vv[4] = {v.x, v.y, v.z, v.w};
    __half h4[4], l4[4];
    #pragma unroll
    for (int j = 0; j < 4; j++) split1(vv[j], h4[j], l4[j]);
    uint2 hp, lp;
    hp.x = (uint32_t)__half_as_ushort(h4[0]) | ((uint32_t)__half_as_ushort(h4[1]) << 16);
    hp.y = (uint32_t)__half_as_ushort(h4[2]) | ((uint32_t)__half_as_ushort(h4[3]) << 16);
    lp.x = (uint32_t)__half_as_ushort(l4[0]) | ((uint32_t)__half_as_ushort(l4[1]) << 16);
    lp.y = (uint32_t)__half_as_ushort(l4[2]) | ((uint32_t)__half_as_ushort(l4[3]) << 16);
    *reinterpret_cast<uint2*>(hi + (size_t)i * 4) = hp;
    *reinterpret_cast<uint2*>(lo + (size_t)i * 4) = lp;
}

// ------------------------- mma.sync split-fp16 NT GEMM, 128x128 tile, 4 warps -------------------------
// warp tile 64x64 -> higher smem arithmetic intensity (24.6 MAC/B vs 16).
#define MG_PITCH 80
#define MG_MAT   10240            /* 128 rows * 80B */
#define MG_STAGE 40960            /* Ah,Al,Bh,Bl */

__device__ __forceinline__ void mg_load(
    uint32_t sbase,
    const __half* __restrict__ Ah, const __half* __restrict__ Al,
    const __half* __restrict__ Bh, const __half* __restrict__ Bl,
    int m0, int n0, int Ntot, int K, int c, int tid)
{
    #pragma unroll
    for (int j = 0; j < 16; j++) {
        int e = tid + j * 128;
        int seg = e & 3, r = (e >> 2) & 127, mat = e >> 9;
        uint32_t soff = (uint32_t)(mat * MG_MAT + r * MG_PITCH + seg * 16);
        size_t kof = (size_t)c * 32 + seg * 8;
        if (mat < 2) {
            const __half* src = (mat ? Al : Ah) + (size_t)(m0 + r) * K + kof;
            cp16z(sbase + soff, src, 16);
        } else {
            int nr = n0 + r;
            int sz = (nr < Ntot) ? 16 : 0;
            int nrc = (nr < Ntot) ? nr : 0;
            const __half* src = ((mat == 3) ? Bl : Bh) + (size_t)nrc * K + kof;
            cp16z(sbase + soff, src, sz);
        }
    }
    asm volatile("cp.async.commit_group;" ::: "memory");
}

__global__ __launch_bounds__(128, 2) void mma_gemm(
    const __half* __restrict__ Ah, const __half* __restrict__ Al,
    const __half* __restrict__ Bh, const __half* __restrict__ Bl,
    float* __restrict__ C, int Ntot, int K)
{
    extern __shared__ char smem[];
    uint32_t sb = smem_u32(smem);
    int tid = threadIdx.x, wid = tid >> 5, lane = tid & 31;
    int m0 = blockIdx.y * 128, n0 = blockIdx.x * 128;
    int wm = (wid >> 1) * 64;
    int wn = (wid & 1) * 64;

    float acc[4][8][4];
    #pragma unroll
    for (int a = 0; a < 4; a++)
        #pragma unroll
        for (int b = 0; b < 8; b++)
            #pragma unroll
            for (int q = 0; q < 4; q++) acc[a][b][q] = 0.f;

    int gr = lane >> 3, lr = lane & 7;
    int arow = (gr & 1) * 8 + lr;
    int acol = (gr >> 1) * 16;
    int brow = (gr >> 1) * 8 + lr;
    int bcol = (gr & 1) * 16;

    int nch = K >> 5;
    mg_load(sb, Ah, Al, Bh, Bl, m0, n0, Ntot, K, 0, tid);
    for (int c = 0; c < nch; c++) {
        if (c + 1 < nch) {
            mg_load(sb + ((c + 1) & 1) * MG_STAGE, Ah, Al, Bh, Bl, m0, n0, Ntot, K, c + 1, tid);
            asm volatile("cp.async.wait_group 1;" ::: "memory");
        } else {
            asm volatile("cp.async.wait_group 0;" ::: "memory");
        }
        __syncthreads();
        uint32_t base = sb + (uint32_t)(c & 1) * MG_STAGE;
        #pragma unroll
        for (int ks = 0; ks < 2; ks++) {
            uint32_t ah[4][4], al[4][4];
            #pragma unroll
            for (int mt = 0; mt < 4; mt++) {
                uint32_t off = (uint32_t)((wm + mt*16 + arow) * MG_PITCH + acol + ks*32);
                ldsm4(ah[mt], base + off);
                ldsm4(al[mt], base + MG_MAT + off);
            }
            #pragma unroll
            for (int np = 0; np < 4; np++) {
                uint32_t bh[4], bl[4];
                uint32_t off = (uint32_t)(2*MG_MAT + (wn + np*16 + brow) * MG_PITCH + bcol + ks*32);
                ldsm4(bh, base + off);
                ldsm4(bl, base + MG_MAT + off);
                #pragma unroll
                for (int mt = 0; mt < 4; mt++) {
                    mma16816(acc[mt][2*np],   ah[mt], &bh[0]);
                    mma16816(acc[mt][2*np+1], ah[mt], &bh[2]);
                    mma16816(acc[mt][2*np],   ah[mt], &bl[0]);
                    mma16816(acc[mt][2*np+1], ah[mt], &bl[2]);
                    mma16816(acc[mt][2*np],   al[mt], &bh[0]);
                    mma16816(acc[mt][2*np+1], al[mt], &bh[2]);
                }
            }
        }
        __syncthreads();
    }

    int r4 = lane >> 2, c2 = (lane & 3) * 2;
    #pragma unroll
    for (int mt = 0; mt < 4; mt++) {
        int r = m0 + wm + mt*16 + r4;
        #pragma unroll
        for (int nt = 0; nt < 8; nt++) {
            int col = n0 + wn + nt*8 + c2;
            if (col < Ntot) {
                float* cc = acc[mt][nt];
                *(float2*)&C[(size_t)r * Ntot + col]       = make_float2(cc[0], cc[1]);
                *(float2*)&C[(size_t)(r + 8) * Ntot + col] = make_float2(cc[2], cc[3]);
            }
        }
    }
}

// NOTE on cross terms: lo operands carry a x2048 scale, so Ah*Bl and Al*Bh terms
// are x2048 in the f32 accumulator... they must be folded at 1/2048. To keep one
// accumulator we instead pre-scale: accumulate main term into acc and cross terms
// into the SAME acc would mis-scale. So cross terms accumulate into xacc (f32).
// -- Implemented below as a corrected variant used by both kernels. --
// (The kernel above is superseded; see mma_gemm2/mma_conv2.)

__global__ __launch_bounds__(128, 2) void mma_gemm2(
    const __half* __restrict__ Ah, const __half* __restrict__ Al,
    const __half* __restrict__ Bh, const __half* __restrict__ Bl,
    float* __restrict__ C, int Ntot, int K)
{
    extern __shared__ char smem[];
    uint32_t sb = smem_u32(smem);
    int tid = threadIdx.x, wid = tid >> 5, lane = tid & 31;
    int m0 = blockIdx.y * 128, n0 = blockIdx.x * 128;
    int wm = (wid >> 1) * 64;
    int wn = (wid & 1) * 64;

    float acc [4][8][4];
    float xacc[4][8][4];
    #pragma unroll
    for (int a = 0; a < 4; a++)
        #pragma unroll
        for (int b = 0; b < 8; b++)
            #pragma unroll
            for (int q = 0; q < 4; q++) { acc[a][b][q] = 0.f; xacc[a][b][q] = 0.f; }

    int gr = lane >> 3, lr = lane & 7;
    int arow = (gr & 1) * 8 + lr;
    int acol = (gr >> 1) * 16;
    int brow = (gr >> 1) * 8 + lr;
    int bcol = (gr & 1) * 16;

    int nch = K >> 5;
    mg_load(sb, Ah, Al, Bh, Bl, m0, n0, Ntot, K, 0, tid);
    for (int c = 0; c < nch; c++) {
        if (c + 1 < nch) {
            mg_load(sb + ((c + 1) & 1) * MG_STAGE, Ah, Al, Bh, Bl, m0, n0, Ntot, K, c + 1, tid);
            asm volatile("cp.async.wait_group 1;" ::: "memory");
        } else {
            asm volatile("cp.async.wait_group 0;" ::: "memory");
        }
        __syncthreads();
        uint32_t base = sb + (uint32_t)(c & 1) * MG_STAGE;
        #pragma unroll
        for (int ks = 0; ks < 2; ks++) {
            uint32_t ah[4][4], al[4][4];
            #pragma unroll
            for (int mt = 0; mt < 4; mt++) {
                uint32_t off = (uint32_t)((wm + mt*16 + arow) * MG_PITCH + acol + ks*32);
                ldsm4(ah[mt], base + off);
                ldsm4(al[mt], base + MG_MAT + off);
            }
            #pragma unroll
            for (int np = 0; np < 4; np++) {
                uint32_t bh[4], bl[4];
                uint32_t off = (uint32_t)(2*MG_MAT + (wn + np*16 + brow) * MG_PITCH + bcol + ks*32);
                ldsm4(bh, base + off);
                ldsm4(bl, base + MG_MAT + off);
                #pragma unroll
                for (int mt = 0; mt < 4; mt++) {
                    mma16816(acc [mt][2*np],   ah[mt], &bh[0]);
                    mma16816(acc [mt][2*np+1], ah[mt], &bh[2]);
                    mma16816(xacc[mt][2*np],   ah[mt], &bl[0]);
                    mma16816(xacc[mt][2*np+1], ah[mt], &bl[2]);
                    mma16816(xacc[mt][2*np],   al[mt], &bh[0]);
                    mma16816(xacc[mt][2*np+1], al[mt], &bh[2]);
                }
            }
        }
        __syncthreads();
    }

    int r4 = lane >> 2, c2 = (lane & 3) * 2;
    #pragma unroll
    for (int mt = 0; mt < 4; mt++) {
        int r = m0 + wm + mt*16 + r4;
        #pragma unroll
        for (int nt = 0; nt < 8; nt++) {
            int col = n0 + wn + nt*8 + c2;
            if (col < Ntot) {
                float* cc = acc[mt][nt];
                float* xx = xacc[mt][nt];
                *(float2*)&C[(size_t)r * Ntot + col] =
                    make_float2(cc[0] + xx[0]*INVLOSCALE, cc[1] + xx[1]*INVLOSCALE);
                *(float2*)&C[(size_t)(r + 8) * Ntot + col] =
                    make_float2(cc[2] + xx[2]*INVLOSCALE, cc[3] + xx[3]*INVLOSCALE);
            }
        }
    }
}

// ------------------------- mma conv (implicit im2col), 128x128 tile, 4 warps -------------------------
template<int KTAP>
__device__ __forceinline__ void mg_load_conv(
    uint32_t sbase,
    const __half* __restrict__ Ah, const __half* __restrict__ Al,
    const __half* __restrict__ Bh, const __half* __restrict__ Bl,
    int m0, int n0, int c, int tid)
{
    const int PAD = KTAP / 2;
    const int K = KTAP * 128;
    int tap = c >> 2;
    int ch0 = (c & 3) * 32;
    #pragma unroll
    for (int j = 0; j < 16; j++) {
        int e = tid + j * 128;
        int seg = e & 3, r = (e >> 2) & 127, mat = e >> 9;
        uint32_t soff = (uint32_t)(mat * MG_MAT + r * MG_PITCH + seg * 16);
        if (mat < 2) {
            int tg = m0 + r;
            int tsrc = (tg & (TLEN - 1)) + tap - PAD;
            int valid = (tsrc >= 0 && tsrc < TLEN);
            size_t gidx = valid ? ((size_t)(tg + tap - PAD) * 128 + ch0 + seg * 8) : 0;
            const __half* src = (mat ? Al : Ah) + gidx;
            cp16z(sbase + soff, src, valid ? 16 : 0);
        } else {
            const __half* src = ((mat == 3) ? Bl : Bh) + (size_t)(n0 + r) * K + (size_t)c * 32 + seg * 8;
            cp16z(sbase + soff, src, 16);
        }
    }
    asm volatile("cp.async.commit_group;" ::: "memory");
}

template<int KTAP>
__global__ __launch_bounds__(128, 2) void mma_conv(
    const __half* __restrict__ Ah, const __half* __restrict__ Al,
    const __half* __restrict__ Bh, const __half* __restrict__ Bl,
    const float* __restrict__ bias, float* __restrict__ Hout,
    __half* __restrict__ ohi, __half* __restrict__ olo, int colofs)
{
    extern __shared__ char smem[];
    uint32_t sb = smem_u32(smem);
    int tid = threadIdx.x, wid = tid >> 5, lane = tid & 31;
    int m0 = blockIdx.y * 128, n0 = blockIdx.x * 128;
    int wm = (wid >> 1) * 64;
    int wn = (wid & 1) * 64;

    float acc [4][8][4];
    float xacc[4][8][4];
    #pragma unroll
    for (int a = 0; a < 4; a++)
        #pragma unroll
        for (int b = 0; b < 8; b++)
            #pragma unroll
            for (int q = 0; q < 4; q++) { acc[a][b][q] = 0.f; xacc[a][b][q] = 0.f; }

    int gr = lane >> 3, lr = lane & 7;
    int arow = (gr & 1) * 8 + lr;
    int acol = (gr >> 1) * 16;
    int brow = (gr >> 1) * 8 + lr;
    int bcol = (gr & 1) * 16;

    const int nch = KTAP * 4;
    mg_load_conv<KTAP>(sb, Ah, Al, Bh, Bl, m0, n0, 0, tid);
    for (int c = 0; c < nch; c++) {
        if (c + 1 < nch) {
            mg_load_conv<KTAP>(sb + ((c + 1) & 1) * MG_STAGE, Ah, Al, Bh, Bl, m0, n0, c + 1, tid);
            asm volatile("cp.async.wait_group 1;" ::: "memory");
        } else {
            asm volatile("cp.async.wait_group 0;" ::: "memory");
        }
        __syncthreads();
        uint32_t base = sb + (uint32_t)(c & 1) * MG_STAGE;
        #pragma unroll
        for (int ks = 0; ks < 2; ks++) {
            uint32_t ah[4][4], al[4][4];
            #pragma unroll
            for (int mt = 0; mt < 4; mt++) {
                uint32_t off = (uint32_t)((wm + mt*16 + arow) * MG_PITCH + acol + ks*32);
                ldsm4(ah[mt], base + off);
                ldsm4(al[mt], base + MG_MAT + off);
            }
            #pragma unroll
            for (int np = 0; np < 4; np++) {
                uint32_t bh[4], bl[4];
                uint32_t off = (uint32_t)(2*MG_MAT + (wn + np*16 + brow) * MG_PITCH + bcol + ks*32);
                ldsm4(bh, base + off);
                ldsm4(bl, base + MG_MAT + off);
                #pragma unroll
                for (int mt = 0; mt < 4; mt++) {
                    mma16816(acc [mt][2*np],   ah[mt], &bh[0]);
                    mma16816(acc [mt][2*np+1], ah[mt], &bh[2]);
                    mma16816(xacc[mt][2*np],   ah[mt], &bl[0]);
                    mma16816(xacc[mt][2*np+1], ah[mt], &bl[2]);
                    mma16816(xacc[mt][2*np],   al[mt], &bh[0]);
                    mma16816(xacc[mt][2*np+1], al[mt], &bh[2]);
                }
            }
        }
        __syncthreads();
    }

    int r4 = lane >> 2, c2 = (lane & 3) * 2;
    #pragma unroll
    for (int mt = 0; mt < 4; mt++) {
        #pragma unroll
        for (int half = 0; half < 2; half++) {
            int r = m0 + wm + mt*16 + r4 + half*8;
            #pragma unroll
            for (int nt = 0; nt < 8; nt++) {
                int col = n0 + wn + nt*8 + c2;
                float* cc = acc[mt][nt];
                float* xx = xacc[mt][nt];
                #pragma unroll
                for (int q = 0; q < 2; q++) {
                    float v = cc[half*2 + q] + xx[half*2 + q]*INVLOSCALE + bias[col + q];
                    v = v / (1.f + expf(-v));
                    size_t idx = (size_t)r * DMODEL + colofs + col + q;
                    Hout[idx] = v;
                    __half hi, lo;
                    split1(v, hi, lo);
                    ohi[idx] = hi;
                    olo[idx] = lo;
                }
            }
        }
    }
}

// ------------------------- helpers -------------------------
__device__ __forceinline__ float blockReduceSum(float v, float* red) {
    int tid = threadIdx.x;
    #pragma unroll
    for (int o = 16; o; o >>= 1) v += __shfl_xor_sync(0xffffffffu, v, o);
    if ((tid & 31) == 0) red[tid >> 5] = v;
    __syncthreads();
    if (tid < 32) {
        float w = (tid < 8) ? red[tid] : 0.f;
        #pragma unroll
        for (int o = 4; o; o >>= 1) w += __shfl_xor_sync(0xffffffffu, w, o);
        if (tid == 0) red[0] = w;
    }
    __syncthreads();
    float r0 = red[0];
    __syncthreads();
    return r0;
}

// ------------------------- front 1x1 conv SGEMM (writes hmid + fp16 split) -------------------------
__global__ __launch_bounds__(256) void gemm128_nt(
    const float* __restrict__ A, const float* __restrict__ B,
    float* __restrict__ C, int N, int K,
    const float* __restrict__ bias,
    __half* __restrict__ ohi, __half* __restrict__ olo)
{
    __shared__ float As[8][128];
    __shared__ float Bs[8][128];
    int m0 = blockIdx.y * 128, n0 = blockIdx.x * 128;
    int tid = threadIdx.x;
    int tx = tid & 15, ty = tid >> 4;
    float acc[8][8] = {};
    int lr = tid >> 1;
    int lk = (tid & 1) * 4;
    const float* Ag = A + (size_t)(m0 + lr) * K + lk;
    const float* Bg = B + (size_t)(n0 + lr) * K + lk;
    bool bvalid = (n0 + lr) < N;
    for (int k0 = 0; k0 < K; k0 += 8) {
        float4 av = *(const float4*)(Ag + k0);
        float4 bv = bvalid ? *(const float4*)(Bg + k0) : make_float4(0.f,0.f,0.f,0.f);
        __syncthreads();
        As[lk+0][lr] = av.x; As[lk+1][lr] = av.y; As[lk+2][lr] = av.z; As[lk+3][lr] = av.w;
        Bs[lk+0][lr] = bv.x; Bs[lk+1][lr] = bv.y; Bs[lk+2][lr] = bv.z; Bs[lk+3][lr] = bv.w;
        __syncthreads();
        #pragma unroll
        for (int kk = 0; kk < 8; kk++) {
            float4 a0 = *(const float4*)&As[kk][ty*8];
            float4 a1 = *(const float4*)&As[kk][ty*8+4];
            float4 b0 = *(const float4*)&Bs[kk][tx*8];
            float4 b1 = *(const float4*)&Bs[kk][tx*8+4];
            float a[8] = {a0.x,a0.y,a0.z,a0.w,a1.x,a1.y,a1.z,a1.w};
            float b[8] = {b0.x,b0.y,b0.z,b0.w,b1.x,b1.y,b1.z,b1.w};
            #pragma unroll
            for (int r = 0; r < 8; r++)
                #pragma unroll
                for (int s = 0; s < 8; s++) acc[r][s] += a[r]*b[s];
        }
    }
    #pragma unroll
    for (int r = 0; r < 8; r++) {
        int m = m0 + ty*8 + r;
        #pragma unroll
        for (int s = 0; s < 8; s++) {
            int n = n0 + tx*8 + s;
            if (n < N) {
                float v = acc[r][s] + bias[n];
                v = v / (1.f + expf(-v));
                size_t idx = (size_t)m * N + n;
                C[idx] = v;
                __half hi, lo;
                split1(v, hi, lo);
                ohi[idx] = hi;
                olo[idx] = lo;
            }
        }
    }
}

// ------------------------- conv weight NT transpose -------------------------
__global__ void transpose_wc(const float* __restrict__ w, float* __restrict__ wt, int KTAP)
{
    int idx = blockIdx.x * 256 + threadIdx.x;
    int K = KTAP * 128;
    int total = 256 * K;
    if (idx >= total) return;
    int o = idx / K;
    int kk = idx - o * K;
    int tap = kk >> 7;
    int i = kk & 127;
    wt[idx] = w[(size_t)o * 128 * KTAP + (size_t)i * KTAP + tap];
}

// ------------------------- dt softplus -------------------------
__global__ void dt_softplus(const float* __restrict__ zx, const float* __restrict__ dtb,
                            float* __restrict__ dt)
{
    int idx = blockIdx.x * 256 + threadIdx.x;
    if (idx >= NTOK * NHEADS) return;
    int t = idx / NHEADS, hh = idx - t * NHEADS;
    float x = zx[(size_t)t * DINPROJ + 3200 + hh] + dtb[hh];
    dt[idx] = (x > 20.f) ? x : log1pf(expf(x));
}

// ------------------------- depthwise causal conv + silu (4 tokens/thread) -------------------------
__global__ void dwconv4(const float* __restrict__ zx, const float* __restrict__ cw,
                        const float* __restrict__ cb, float* __restrict__ xBC)
{
    int c = blockIdx.x * 256 + threadIdx.x;
    if (c >= CONVDIM) return;
    int t0 = blockIdx.y * 4;
    int ti0 = t0 & (TLEN - 1);
    float4 w = *(const float4*)(cw + (size_t)c * 4);
    float bias = cb[c];
    float z[7];
    #pragma unroll
    for (int j = 0; j < 7; j++) {
        int ti = ti0 - 3 + j;
        z[j] = (ti >= 0) ? zx[(size_t)(t0 - 3 + j) * DINPROJ + DINNER + c] : 0.f;
    }
    #pragma unroll
    for (int j = 0; j < 4; j++) {
        float acc = bias + z[j]*w.x + z[j+1]*w.y + z[j+2]*w.z + z[j+3]*w.w;
        xBC[(size_t)(t0 + j) * CONVDIM + c] = acc / (1.f + expf(-acc));
    }
}

// ------------------------- SSD per-chunk kernel -------------------------
__global__ __launch_bounds__(256) void ssd_chunk(
    const float* __restrict__ xBC, const float* __restrict__ dt,
    const float* __restrict__ A_log, const float* __restrict__ Dv,
    float* __restrict__ ys, float* __restrict__ Sg,
    float* __restrict__ segout, float* __restrict__ cdout)
{
    extern __shared__ float sm[];
    float* Bs  = sm;
    float* Cs  = Bs + 64*SMP;
    float* Ds  = Cs + 64*SMP;
    float* seg = Ds + 64*SMP;
    float* dec = seg + 64;
    float* dts = dec + 64;

    int blk = blockIdx.x;
    int h = blk % NHEADS;
    int c = (blk / NHEADS) & (NCHUNK - 1);
    int b = blk / (NHEADS * NCHUNK);
    int t0 = b * TLEN + c * 64;
    int tid = threadIdx.x;
    float A = -expf(A_log[h]);

    if (tid < 64) dts[tid] = dt[(size_t)(t0 + tid) * NHEADS + h];
    __syncthreads();
    for (int e = tid; e < 4096; e += 256) {
        int j = e >> 6, n = e & 63;
        const float* row = xBC + (size_t)(t0 + j) * CONVDIM;
        Bs[j*SMP + n] = row[DINNER + n];
        Cs[j*SMP + n] = row[DINNER + DSTATE + n];
        Ds[j*SMP + n] = dts[j] * row[h*64 + n];
    }
    if (tid < 64) seg[tid] = dts[tid] * A;
    __syncthreads();
    for (int off = 1; off < 64; off <<= 1) {
        float v = 0.f;
        bool act = (tid < 64) && (tid >= off);
        if (act) v = seg[tid - off];
        __syncthreads();
        if (act) seg[tid] += v;
        __syncthreads();
    }
    if (tid < 64) {
        dec[tid] = expf(seg[63] - seg[tid]);
        segout[(size_t)blk * 64 + tid] = seg[tid];
    }
    if (tid == 0) cdout[blk] = expf(seg[63]);
    __syncthreads();

    int tx = tid & 15, ty = tid >> 4;
    float acc[4][4] = {};
    #pragma unroll 4
    for (int n = 0; n < 64; n++) {
        float a[4], bb[4];
        #pragma unroll
        for (int r = 0; r < 4; r++) a[r] = Cs[(ty*4 + r)*SMP + n];
        #pragma unroll
        for (int s = 0; s < 4; s++) bb[s] = Bs[(tx*4 + s)*SMP + n];
        #pragma unroll
        for (int r = 0; r < 4; r++)
            #pragma unroll
            for (int s = 0; s < 4; s++) acc[r][s] += a[r]*bb[s];
    }
    __syncthreads();
    #pragma unroll
    for (int r = 0; r < 4; r++)
        #pragma unroll
        for (int s = 0; s < 4; s++) {
            int i = ty*4 + r, j = tx*4 + s;
            float v = 0.f;
            if (i >= j) v = expf(seg[i] - seg[j]) * acc[r][s];
            Cs[i*SMP + j] = v;
        }
    __syncthreads();
    float acc2[4][4] = {};
    #pragma unroll 4
    for (int j = 0; j < 64; j++) {
        float a[4], bb[4];
        #pragma unroll
        for (int r = 0; r < 4; r++) a[r] = Cs[(ty*4 + r)*SMP + j];
        #pragma unroll
        for (int s = 0; s < 4; s++) bb[s] = Ds[j*SMP + tx*4 + s];
        #pragma unroll
        for (int r = 0; r < 4; r++)
            #pragma unroll
            for (int s = 0; s < 4; s++) acc2[r][s] += a[r]*bb[s];
    }
    float Dh = Dv[h];
    #pragma unroll
    for (int r = 0; r < 4; r++)
        #pragma unroll
        for (int s = 0; s < 4; s++) {
            int i = t0 + ty*4 + r;
            int p = tx*4 + s;
            ys[(size_t)i * DINNER + h*64 + p] =
                acc2[r][s] + Dh * xBC[(size_t)i * CONVDIM + h*64 + p];
        }
    float acc3[4][4] = {};
    #pragma unroll 4
    for (int j = 0; j < 64; j++) {
        float dj = dec[j];
        float a[4], bb[4];
        #pragma unroll
        for (int r = 0; r < 4; r++) a[r] = Ds[j*SMP + ty*4 + r] * dj;
        #pragma unroll
        for (int s = 0; s < 4; s++) bb[s] = Bs[j*SMP + tx*4 + s];
        #pragma unroll
        for (int r = 0; r < 4; r++)
            #pragma unroll
            for (int s = 0; s < 4; s++) acc3[r][s] += a[r]*bb[s];
    }
    #pragma unroll
    for (int r = 0; r < 4; r++)
        #pragma unroll
        for (int s = 0; s < 4; s++)
            Sg[(size_t)blk * 4096 + (ty*4 + r)*64 + tx*4 + s] = acc3[r][s];
}

// ------------------------- inter-chunk scan (8-way partitioned) -------------------------
__global__ __launch_bounds__(256) void ssd_scan8(float* __restrict__ Sg,
                                                 const float* __restrict__ cd)
{
    int blk = blockIdx.x;
    int part = blk & 7;
    int bh = blk >> 3;
    int h = bh % NHEADS, b = bh / NHEADS;
    int tid = threadIdx.x;
    int e0 = part * 512 + tid;
    float st0 = 0.f, st1 = 0.f;
    for (int c = 0; c < NCHUNK; c++) {
        int bidx = (b * NCHUNK + c) * NHEADS + h;
        size_t base = (size_t)bidx * 4096;
        float d = cd[bidx];
        float s0 = Sg[base + e0];
        float s1 = Sg[base + e0 + 256];
        Sg[base + e0]       = st0;
        Sg[base + e0 + 256] = st1;
        st0 = st0 * d + s0;
        st1 = st1 * d + s1;
    }
}

// ------------------------- y_inter accumulation -------------------------
__global__ __launch_bounds__(256) void ssd_inter(
    const float* __restrict__ xBC, const float* __restrict__ Sg,
    const float* __restrict__ segin, float* __restrict__ ys)
{
    __shared__ float Cs[64*SMP];
    __shared__ float Hs[64*SMP];
    __shared__ float seg[64];
    int blk = blockIdx.x;
    int h = blk % NHEADS;
    int c = (blk / NHEADS) & (NCHUNK - 1);
    int b = blk / (NHEADS * NCHUNK);
    int t0 = b * TLEN + c * 64;
    int tid = threadIdx.x;
    for (int e = tid; e < 4096; e += 256) {
        int j = e >> 6, n = e & 63;
        Cs[j*SMP + n] = xBC[(size_t)(t0 + j) * CONVDIM + DINNER + DSTATE + n];
        Hs[j*SMP + n] = Sg[(size_t)blk * 4096 + j*64 + n];
    }
    if (tid < 64) seg[tid] = segin[(size_t)blk * 64 + tid];
    __syncthreads();
    int tx = tid & 15, ty = tid >> 4;
    float acc[4][4] = {};
    #pragma unroll 4
    for (int n = 0; n < 64; n++) {
        float a[4], bb[4];
        #pragma unroll
        for (int r = 0; r < 4; r++) a[r] = Cs[(ty*4 + r)*SMP + n];
        #pragma unroll
        for (int s = 0; s < 4; s++) bb[s] = Hs[(tx*4 + s)*SMP + n];
        #pragma unroll
        for (int r = 0; r < 4; r++)
            #pragma unroll
            for (int s = 0; s < 4; s++) acc[r][s] += a[r]*bb[s];
    }
    #pragma unroll
    for (int r = 0; r < 4; r++) {
        float ei = expf(seg[ty*4 + r]);
        #pragma unroll
        for (int s = 0; s < 4; s++) {
            size_t idx = (size_t)(t0 + ty*4 + r) * DINNER + h*64 + tx*4 + s;
            ys[idx] += acc[r][s] * ei;
        }
    }
}

// ------------------------- gating + RMSNorm (writes fp16 split) -------------------------
__global__ __launch_bounds__(256) void gate_rms(
    const float* __restrict__ ys, const float* __restrict__ zx,
    const float* __restrict__ nw,
    __half* __restrict__ ohi, __half* __restrict__ olo)
{
    __shared__ float red[32];
    int t = blockIdx.x, tid = threadIdx.x;
    float v[6];
    float ss = 0.f;
    #pragma unroll
    for (int r = 0; r < 6; r++) {
        int i = tid + r*256;
        float z = zx[(size_t)t * DINPROJ + i];
        float val = ys[(size_t)t * DINNER + i] * (z / (1.f + expf(-z)));
        v[r] = val;
        ss += val*val;
    }
    ss = blockReduceSum(ss, red);
    float sc = rsqrtf(ss / (float)DINNER + 1e-5f);
    #pragma unroll
    for (int r = 0; r < 6; r++) {
        int i = tid + r*256;
        float val = v[r] * sc * nw[i];
        __half hi, lo;
        split1(val, hi, lo);
        size_t idx = (size_t)t * DINNER + i;
        ohi[idx] = hi;
        olo[idx] = lo;
    }
}

// ------------------------- residual + layernorm (writes h + fp16 split) -------------------------
__global__ __launch_bounds__(256) void resid_ln(
    const float* __restrict__ y2, float* __restrict__ hio,
    const float* __restrict__ w, const float* __restrict__ b,
    __half* __restrict__ ohi, __half* __restrict__ olo)
{
    __shared__ float red[32];
    int t = blockIdx.x, tid = threadIdx.x;
    float v[3];
    float s = 0.f;
    #pragma unroll
    for (int r = 0; r < 3; r++) {
        int i = tid + r*256;
        v[r] = y2[(size_t)t * DMODEL + i] + hio[(size_t)t * DMODEL + i];
        s += v[r];
    }
    s = blockReduceSum(s, red);
    float mean = s / (float)DMODEL;
    float q = 0.f;
    #pragma unroll
    for (int r = 0; r < 3; r++) { v[r] -= mean; q += v[r]*v[r]; }
    q = blockReduceSum(q, red);
    float inv = rsqrtf(q / (float)DMODEL + 1e-5f);
    #pragma unroll
    for (int r = 0; r < 3; r++) {
        int i = tid + r*256;
        float val = v[r] * inv * w[i] + b[i];
        size_t idx = (size_t)t * DMODEL + i;
        hio[idx] = val;
        __half hi, lo;
        split1(val, hi, lo);
        ohi[idx] = hi;
        olo[idx] = lo;
    }
}

// ------------------------- final layernorm + logits -------------------------
__global__ __launch_bounds__(256) void head_kernel(
    const float* __restrict__ hin,
    const float* __restrict__ fw, const float* __restrict__ fb,
    const float* __restrict__ lw, const float* __restrict__ lb,
    float* __restrict__ out)
{
    __shared__ float red[32];
    __shared__ float buf[DMODEL];
    int t = blockIdx.x, tid = threadIdx.x;
    float v[3];
    float s = 0.f;
    #pragma unroll
    for (int r = 0; r < 3; r++) {
        int i = tid + r*256;
        v[r] = hin[(size_t)t * DMODEL + i];
        s += v[r];
    }
    s = blockReduceSum(s, red);
    float mean = s / (float)DMODEL;
    float q = 0.f;
    #pragma unroll
    for (int r = 0; r < 3; r++) { v[r] -= mean; q += v[r]*v[r]; }
    q = blockReduceSum(q, red);
    float inv = rsqrtf(q / (float)DMODEL + 1e-5f);
    #pragma unroll
    for (int r = 0; r < 3; r++) {
        int i = tid + r*256;
        buf[i] = v[r] * inv * fw[i] + fb[i];
    }
    __syncthreads();
    for (int cls = 0; cls < 10; cls++) {
        float p = 0.f;
        #pragma unroll
        for (int r = 0; r < 3; r++) {
            int i = tid + r*256;
            p += buf[i] * lw[(size_t)cls * DMODEL + i];
        }
        p = blockReduceSum(p, red);
        if (tid == 0) out[(size_t)t * 10 + cls] = p + lb[cls];
    }
}

// ------------------------- launch -------------------------
extern "C" void kernel_launch(void* const* d_in, const int* in_sizes, int n_in,
                              void* d_out, int out_size)
{
    const float* x       = (const float*)d_in[0];
    const float* pc_w    = (const float*)d_in[1];
    const float* pc_b    = (const float*)d_in[2];
    const float* c1_w    = (const float*)d_in[3];
    const float* c1_b    = (const float*)d_in[4];
    const float* c2_w    = (const float*)d_in[5];
    const float* c2_b    = (const float*)d_in[6];
    const float* c3_w    = (const float*)d_in[7];
    const float* c3_b    = (const float*)d_in[8];
    const float* in_proj = (const float*)d_in[9];
    const float* conv_w  = (const float*)d_in[10];
    const float* conv_b  = (const float*)d_in[11];
    const float* dt_bias = (const float*)d_in[12];
    const float* A_log   = (const float*)d_in[13];
    const float* Dvec    = (const float*)d_in[14];
    const float* norm_w  = (const float*)d_in[15];
    const float* out_proj= (const float*)d_in[16];
    const float* ln_w    = (const float*)d_in[17];
    const float* ln_b    = (const float*)d_in[18];
    const float* fn_w    = (const float*)d_in[19];
    const float* fn_b    = (const float*)d_in[20];
    const float* lo_w    = (const float*)d_in[21];
    const float* lo_b    = (const float*)d_in[22];
    float* out = (float*)d_out;

    float *hmid, *h, *zx, *xBC, *dtb, *ys, *y2, *S, *segb, *cdb, *wt;
    __half *ahi, *alo, *hmh, *hml, *wch, *wcl, *wih, *wil, *woh, *wol;
    cudaGetSymbolAddress((void**)&hmid, g_hmid);
    cudaGetSymbolAddress((void**)&h,    g_h);
    cudaGetSymbolAddress((void**)&zx,   g_zx);
    cudaGetSymbolAddress((void**)&xBC,  g_xBC);
    cudaGetSymbolAddress((void**)&dtb,  g_dt);
    cudaGetSymbolAddress((void**)&ys,   g_ys);
    cudaGetSymbolAddress((void**)&y2,   g_y2);
    cudaGetSymbolAddress((void**)&S,    g_S);
    cudaGetSymbolAddress((void**)&segb, g_seg);
    cudaGetSymbolAddress((void**)&cdb,  g_cd);
    cudaGetSymbolAddress((void**)&wt,   g_wt);
    cudaGetSymbolAddress((void**)&ahi,  g_ahi);
    cudaGetSymbolAddress((void**)&alo,  g_alo);
    cudaGetSymbolAddress((void**)&hmh,  g_hmh);
    cudaGetSymbolAddress((void**)&hml,  g_hml);
    cudaGetSymbolAddress((void**)&wch,  g_wch);
    cudaGetSymbolAddress((void**)&wcl,  g_wcl);
    cudaGetSymbolAddress((void**)&wih,  g_wih);
    cudaGetSymbolAddress((void**)&wil,  g_wil);
    cudaGetSymbolAddress((void**)&woh,  g_woh);
    cudaGetSymbolAddress((void**)&wol,  g_wol);

    const int SSD_SMEM = (3 * 64 * SMP + 3 * 64) * (int)sizeof(float);
    cudaFuncSetAttribute(ssd_chunk, cudaFuncAttributeMaxDynamicSharedMemorySize, SSD_SMEM);
    const int MG_SMEM = 2 * MG_STAGE;   // 81920
    cudaFuncSetAttribute(mma_gemm2, cudaFuncAttributeMaxDynamicSharedMemorySize, MG_SMEM);
    cudaFuncSetAttribute(mma_conv<3>,  cudaFuncAttributeMaxDynamicSharedMemorySize, MG_SMEM);
    cudaFuncSetAttribute(mma_conv<9>,  cudaFuncAttributeMaxDynamicSharedMemorySize, MG_SMEM);
    cudaFuncSetAttribute(mma_conv<27>, cudaFuncAttributeMaxDynamicSharedMemorySize, MG_SMEM);

    // ---- front ----
    gemm128_nt<<<dim3(1, NTOK/128), 256>>>(x, pc_w, hmid, 128, 64, pc_b, hmh, hml);
    transpose_wc<<<(256*384  + 255)/256, 256>>>(c1_w, wt,           3);
    transpose_wc<<<(256*1152 + 255)/256, 256>>>(c2_w, wt + 98304,   9);
    transpose_wc<<<(256*3456 + 255)/256, 256>>>(c3_w, wt + 393216, 27);
    split_half<<<(1277952/4 + 255)/256, 256>>>((const float4*)wt, wch, wcl, 1277952/4);
    mma_conv<3> <<<dim3(2, NTOK/128), 128, MG_SMEM>>>(hmh, hml, wch,          wcl,          c1_b, h, ahi, alo, 0);
    mma_conv<9> <<<dim3(2, NTOK/128), 128, MG_SMEM>>>(hmh, hml, wch + 98304,  wcl + 98304,  c2_b, h, ahi, alo, 256);
    mma_conv<27><<<dim3(2, NTOK/128), 128, MG_SMEM>>>(hmh, hml, wch + 393216, wcl + 393216, c3_b, h, ahi, alo, 512);

    // ---- weight fp16 splits ----
    {
        int n4 = 4 * DINPROJ * DMODEL / 4;
        split_half<<<(n4 + 255)/256, 256>>>((const float4*)in_proj, wih, wil, n4);
        int m4 = 4 * DMODEL * DINNER / 4;
        split_half<<<(m4 + 255)/256, 256>>>((const float4*)out_proj, woh, wol, m4);
    }

    // ---- layers ----
    for (int l = 0; l < 4; l++) {
        mma_gemm2<<<dim3((DINPROJ + 127)/128, NTOK/128), 128, MG_SMEM>>>(
            ahi, alo,
            wih + (size_t)l * DINPROJ * DMODEL, wil + (size_t)l * DINPROJ * DMODEL,
            zx, DINPROJ, DMODEL);
        dt_softplus<<<(NTOK*NHEADS + 255)/256, 256>>>(zx, dt_bias + l*NHEADS, dtb);
        dwconv4<<<dim3((CONVDIM + 255)/256, NTOK/4), 256>>>(
            zx, conv_w + (size_t)l * CONVDIM * 4, conv_b + (size_t)l * CONVDIM, xBC);
        ssd_chunk<<<NBLK_SSD, 256, SSD_SMEM>>>(
            xBC, dtb, A_log + l*NHEADS, Dvec + l*NHEADS, ys, S, segb, cdb);
        ssd_scan8<<<8*NHEADS*8, 256>>>(S, cdb);
        ssd_inter<<<NBLK_SSD, 256>>>(xBC, S, segb, ys);
        gate_rms<<<NTOK, 256>>>(ys, zx, norm_w + (size_t)l * DINNER, ahi, alo);
        mma_gemm2<<<dim3(DMODEL/128, NTOK/128), 128, MG_SMEM>>>(
            ahi, alo,
            woh + (size_t)l * DMODEL * DINNER, wol + (size_t)l * DMODEL * DINNER,
            y2, DMODEL, DINNER);
        resid_ln<<<NTOK, 256>>>(y2, h, ln_w + (size_t)l * DMODEL, ln_b + (size_t)l * DMODEL,
                                ahi, alo);
    }

    // ---- head ----
    head_kernel<<<NTOK, 256>>>(h, fn_w, fn_b, lo_w, lo_b, out);
    (void)in_sizes; (void)n_in; (void)out_size;
}

// round 9
// speedup vs baseline: 1.6831x; 1.6831x over previous
#include <cuda_runtime.h>
#include <cuda_fp16.h>
#include <cstdint>
#include <math.h>

#define NTOK   16384
#define TLEN   2048
#define DMODEL 768
#define DINNER 1536
#define DSTATE 64
#define NHEADS 24
#define CONVDIM 1664
#define DINPROJ 3224
#define NCHUNK 32
#define NBLK_SSD (8*NCHUNK*NHEADS)   /* 6144 */
#define SMP 65

// ------------------------- scratch (device globals) -------------------------
__device__ float g_hmid[(size_t)NTOK*128];
__device__ float g_h   [(size_t)NTOK*DMODEL];
__device__ float g_zx  [(size_t)NTOK*DINPROJ];
__device__ float g_xBC [(size_t)NTOK*CONVDIM];
__device__ float g_dt  [(size_t)NTOK*NHEADS];
__device__ float g_ys  [(size_t)NTOK*DINNER];
__device__ float g_y2  [(size_t)NTOK*DMODEL];
__device__ float g_S   [(size_t)NBLK_SSD*4096];
__device__ float g_seg [(size_t)NBLK_SSD*64];
__device__ float g_cd  [NBLK_SSD];
__device__ float g_wt  [(size_t)(3+9+27)*128*256];   /* conv weights NT fp32 */
// fp16 buffers: activations split hi/lo, weights single fp16
__device__ __half g_ahi[(size_t)NTOK*DINNER];
__device__ __half g_alo[(size_t)NTOK*DINNER];
__device__ __half g_hmh[(size_t)NTOK*128];
__device__ __half g_hml[(size_t)NTOK*128];
__device__ __half g_wch[(size_t)(3+9+27)*128*256];
__device__ __half g_wih[(size_t)4*DINPROJ*DMODEL];
__device__ __half g_woh[(size_t)4*DMODEL*DINNER];

// ------------------------- PTX helpers -------------------------
__device__ __forceinline__ uint32_t smem_u32(const void* p) {
    uint32_t a;
    asm("{ .reg .u64 t; cvta.to.shared.u64 t, %1; cvt.u32.u64 %0, t; }" : "=r"(a) : "l"(p));
    return a;
}
__device__ __forceinline__ void cp16z(uint32_t dst, const void* src, int srcsz) {
    asm volatile("cp.async.cg.shared.global [%0], [%1], 16, %2;" :: "r"(dst), "l"(src), "r"(srcsz));
}
__device__ __forceinline__ void ldsm4(uint32_t* r, uint32_t addr) {
    asm volatile("ldmatrix.sync.aligned.m8n8.x4.shared.b16 {%0,%1,%2,%3}, [%4];"
        : "=r"(r[0]), "=r"(r[1]), "=r"(r[2]), "=r"(r[3]) : "r"(addr));
}
__device__ __forceinline__ void mma16816(float* c, const uint32_t* a, const uint32_t* b) {
    asm volatile("mma.sync.aligned.m16n8k16.row.col.f32.f16.f16.f32 "
        "{%0,%1,%2,%3}, {%4,%5,%6,%7}, {%8,%9}, {%0,%1,%2,%3};"
        : "+f"(c[0]), "+f"(c[1]), "+f"(c[2]), "+f"(c[3])
        : "r"(a[0]), "r"(a[1]), "r"(a[2]), "r"(a[3]), "r"(b[0]), "r"(b[1]));
}
__device__ __forceinline__ void split1(float v, __half& hi, __half& lo) {
    hi = __float2half_rn(v);
    lo = __float2half_rn(v - __half2float(hi));   // unscaled error-feedback term
}

// ------------------------- split fp32 -> fp16 hi/lo (activations) -------------------------
__global__ void split_half(const float4* __restrict__ src,
                           __half* __restrict__ hi,
                           __half* __restrict__ lo, int n4)
{
    int i = blockIdx.x * 256 + threadIdx.x;
    if (i >= n4) return;
    float4 v = src[i];
    float vv[4] = {v.x, v.y, v.z, v.w};
    __half h4[4], l4[4];
    #pragma unroll
    for (int j = 0; j < 4; j++) split1(vv[j], h4[j], l4[j]);
    uint2 hp, lp;
    hp.x = (uint32_t)__half_as_ushort(h4[0]) | ((uint32_t)__half_as_ushort(h4[1]) << 16);
    hp.y = (uint32_t)__half_as_ushort(h4[2]) | ((uint32_t)__half_as_ushort(h4[3]) << 16);
    lp.x = (uint32_t)__half_as_ushort(l4[0]) | ((uint32_t)__half_as_ushort(l4[1]) << 16);
    lp.y = (uint32_t)__half_as_ushort(l4[2]) | ((uint32_t)__half_as_ushort(l4[3]) << 16);
    *reinterpret_cast<uint2*>(hi + (size_t)i * 4) = hp;
    *reinterpret_cast<uint2*>(lo + (size_t)i * 4) = lp;
}

// ------------------------- convert fp32 -> fp16 (weights, single) -------------------------
__global__ void to_half(const float4* __restrict__ src, __half* __restrict__ dst, int n4)
{
    int i = blockIdx.x * 256 + threadIdx.x;
    if (i >= n4) return;
    float4 v = src[i];
    __half h4[4] = { __float2half_rn(v.x), __float2half_rn(v.y),
                     __float2half_rn(v.z), __float2half_rn(v.w) };
    uint2 hp;
    hp.x = (uint32_t)__half_as_ushort(h4[0]) | ((uint32_t)__half_as_ushort(h4[1]) << 16);
    hp.y = (uint32_t)__half_as_ushort(h4[2]) | ((uint32_t)__half_as_ushort(h4[3]) << 16);
    *reinterpret_cast<uint2*>(dst + (size_t)i * 4) = hp;
}

// ------------------------- 2-term split-fp16 NT GEMM, 64x128 tile, 128 thr -------------------------
// C = (Ah + Al) * B^T,  Ah/Al fp16 activation split, B fp16 weights.
#define MG_PITCH 80
#define MG_AMAT  5120             /* 64 rows * 80B */
#define MG_BBASE 10240
#define MG_STAGE 20480            /* Ah, Al, B */

__device__ __forceinline__ void mg_load(
    uint32_t sbase,
    const __half* __restrict__ Ah, const __half* __restrict__ Al,
    const __half* __restrict__ B,
    int m0, int n0, int Ntot, int K, int c, int tid)
{
    #pragma unroll
    for (int j = 0; j < 4; j++) {
        int e = tid + j * 128;
        int seg = e & 3, r = (e >> 2) & 63, mat = e >> 8;
        uint32_t soff = (uint32_t)(mat * MG_AMAT + r * MG_PITCH + seg * 16);
        const __half* src = (mat ? Al : Ah) + (size_t)(m0 + r) * K + (size_t)c * 32 + seg * 8;
        cp16z(sbase + soff, src, 16);
    }
    #pragma unroll
    for (int j = 0; j < 4; j++) {
        int e = tid + j * 128;
        int seg = e & 3, r = e >> 2;
        uint32_t soff = (uint32_t)(MG_BBASE + r * MG_PITCH + seg * 16);
        int nr = n0 + r;
        int sz = (nr < Ntot) ? 16 : 0;
        int nrc = (nr < Ntot) ? nr : 0;
        const __half* src = B + (size_t)nrc * K + (size_t)c * 32 + seg * 8;
        cp16z(sbase + soff, src, sz);
    }
    asm volatile("cp.async.commit_group;" ::: "memory");
}

__global__ __launch_bounds__(128, 3) void mma_gemm(
    const __half* __restrict__ Ah, const __half* __restrict__ Al,
    const __half* __restrict__ B,
    float* __restrict__ C, int Ntot, int K)
{
    extern __shared__ char smem[];
    uint32_t sb = smem_u32(smem);
    int tid = threadIdx.x, wid = tid >> 5, lane = tid & 31;
    int m0 = blockIdx.y * 64, n0 = blockIdx.x * 128;
    int wm = (wid >> 1) * 32;
    int wn = (wid & 1) * 64;

    float acc[2][8][4];
    #pragma unroll
    for (int a = 0; a < 2; a++)
        #pragma unroll
        for (int b = 0; b < 8; b++)
            #pragma unroll
            for (int q = 0; q < 4; q++) acc[a][b][q] = 0.f;

    int gr = lane >> 3, lr = lane & 7;
    int arow = (gr & 1) * 8 + lr;
    int acol = (gr >> 1) * 16;
    int brow = (gr >> 1) * 8 + lr;
    int bcol = (gr & 1) * 16;

    int nch = K >> 5;
    mg_load(sb, Ah, Al, B, m0, n0, Ntot, K, 0, tid);
    for (int c = 0; c < nch; c++) {
        if (c + 1 < nch) {
            mg_load(sb + ((c + 1) & 1) * MG_STAGE, Ah, Al, B, m0, n0, Ntot, K, c + 1, tid);
            asm volatile("cp.async.wait_group 1;" ::: "memory");
        } else {
            asm volatile("cp.async.wait_group 0;" ::: "memory");
        }
        __syncthreads();
        uint32_t base = sb + (uint32_t)(c & 1) * MG_STAGE;
        #pragma unroll
        for (int ks = 0; ks < 2; ks++) {
            uint32_t ah[2][4], al[2][4];
            #pragma unroll
            for (int mt = 0; mt < 2; mt++) {
                uint32_t off = (uint32_t)((wm + mt*16 + arow) * MG_PITCH + acol + ks*32);
                ldsm4(ah[mt], base + off);
                ldsm4(al[mt], base + MG_AMAT + off);
            }
            #pragma unroll
            for (int np = 0; np < 4; np++) {
                uint32_t bb[4];
                uint32_t off = (uint32_t)(MG_BBASE + (wn + np*16 + brow) * MG_PITCH + bcol + ks*32);
                ldsm4(bb, base + off);
                #pragma unroll
                for (int mt = 0; mt < 2; mt++) {
                    mma16816(acc[mt][2*np],   ah[mt], &bb[0]);
                    mma16816(acc[mt][2*np+1], ah[mt], &bb[2]);
                    mma16816(acc[mt][2*np],   al[mt], &bb[0]);
                    mma16816(acc[mt][2*np+1], al[mt], &bb[2]);
                }
            }
        }
        __syncthreads();
    }

    int r4 = lane >> 2, c2 = (lane & 3) * 2;
    #pragma unroll
    for (int mt = 0; mt < 2; mt++) {
        int r = m0 + wm + mt*16 + r4;
        #pragma unroll
        for (int nt = 0; nt < 8; nt++) {
            int col = n0 + wn + nt*8 + c2;
            if (col < Ntot) {
                float* cc = acc[mt][nt];
                *(float2*)&C[(size_t)r * Ntot + col]       = make_float2(cc[0], cc[1]);
                *(float2*)&C[(size_t)(r + 8) * Ntot + col] = make_float2(cc[2], cc[3]);
            }
        }
    }
}

// ------------------------- 2-term mma conv (implicit im2col), 64x128 tile, N=256 -------------------------
template<int KTAP>
__device__ __forceinline__ void mg_load_conv(
    uint32_t sbase,
    const __half* __restrict__ Ah, const __half* __restrict__ Al,
    const __half* __restrict__ B,
    int m0, int n0, int c, int tid)
{
    const int PAD = KTAP / 2;
    const int K = KTAP * 128;
    int tap = c >> 2;
    int ch0 = (c & 3) * 32;
    #pragma unroll
    for (int j = 0; j < 4; j++) {
        int e = tid + j * 128;
        int seg = e & 3, r = (e >> 2) & 63, mat = e >> 8;
        uint32_t soff = (uint32_t)(mat * MG_AMAT + r * MG_PITCH + seg * 16);
        int tg = m0 + r;
        int tsrc = (tg & (TLEN - 1)) + tap - PAD;
        int valid = (tsrc >= 0 && tsrc < TLEN);
        size_t gidx = valid ? ((size_t)(tg + tap - PAD) * 128 + ch0 + seg * 8) : 0;
        const __half* src = (mat ? Al : Ah) + gidx;
        cp16z(sbase + soff, src, valid ? 16 : 0);
    }
    #pragma unroll
    for (int j = 0; j < 4; j++) {
        int e = tid + j * 128;
        int seg = e & 3, r = e >> 2;
        uint32_t soff = (uint32_t)(MG_BBASE + r * MG_PITCH + seg * 16);
        const __half* src = B + (size_t)(n0 + r) * K + (size_t)c * 32 + seg * 8;
        cp16z(sbase + soff, src, 16);
    }
    asm volatile("cp.async.commit_group;" ::: "memory");
}

template<int KTAP>
__global__ __launch_bounds__(128, 3) void mma_conv(
    const __half* __restrict__ Ah, const __half* __restrict__ Al,
    const __half* __restrict__ B,
    const float* __restrict__ bias, float* __restrict__ Hout,
    __half* __restrict__ ohi, __half* __restrict__ olo, int colofs)
{
    extern __shared__ char smem[];
    uint32_t sb = smem_u32(smem);
    int tid = threadIdx.x, wid = tid >> 5, lane = tid & 31;
    int m0 = blockIdx.y * 64, n0 = blockIdx.x * 128;
    int wm = (wid >> 1) * 32;
    int wn = (wid & 1) * 64;

    float acc[2][8][4];
    #pragma unroll
    for (int a = 0; a < 2; a++)
        #pragma unroll
        for (int b = 0; b < 8; b++)
            #pragma unroll
            for (int q = 0; q < 4; q++) acc[a][b][q] = 0.f;

    int gr = lane >> 3, lr = lane & 7;
    int arow = (gr & 1) * 8 + lr;
    int acol = (gr >> 1) * 16;
    int brow = (gr >> 1) * 8 + lr;
    int bcol = (gr & 1) * 16;

    const int nch = KTAP * 4;
    mg_load_conv<KTAP>(sb, Ah, Al, B, m0, n0, 0, tid);
    for (int c = 0; c < nch; c++) {
        if (c + 1 < nch) {
            mg_load_conv<KTAP>(sb + ((c + 1) & 1) * MG_STAGE, Ah, Al, B, m0, n0, c + 1, tid);
            asm volatile("cp.async.wait_group 1;" ::: "memory");
        } else {
            asm volatile("cp.async.wait_group 0;" ::: "memory");
        }
        __syncthreads();
        uint32_t base = sb + (uint32_t)(c & 1) * MG_STAGE;
        #pragma unroll
        for (int ks = 0; ks < 2; ks++) {
            uint32_t ah[2][4], al[2][4];
            #pragma unroll
            for (int mt = 0; mt < 2; mt++) {
                uint32_t off = (uint32_t)((wm + mt*16 + arow) * MG_PITCH + acol + ks*32);
                ldsm4(ah[mt], base + off);
                ldsm4(al[mt], base + MG_AMAT + off);
            }
            #pragma unroll
            for (int np = 0; np < 4; np++) {
                uint32_t bb[4];
                uint32_t off = (uint32_t)(MG_BBASE + (wn + np*16 + brow) * MG_PITCH + bcol + ks*32);
                ldsm4(bb, base + off);
                #pragma unroll
                for (int mt = 0; mt < 2; mt++) {
                    mma16816(acc[mt][2*np],   ah[mt], &bb[0]);
                    mma16816(acc[mt][2*np+1], ah[mt], &bb[2]);
                    mma16816(acc[mt][2*np],   al[mt], &bb[0]);
                    mma16816(acc[mt][2*np+1], al[mt], &bb[2]);
                }
            }
        }
        __syncthreads();
    }

    int r4 = lane >> 2, c2 = (lane & 3) * 2;
    #pragma unroll
    for (int mt = 0; mt < 2; mt++) {
        #pragma unroll
        for (int half = 0; half < 2; half++) {
            int r = m0 + wm + mt*16 + r4 + half*8;
            #pragma unroll
            for (int nt = 0; nt < 8; nt++) {
                int col = n0 + wn + nt*8 + c2;
                float* cc = acc[mt][nt];
                #pragma unroll
                for (int q = 0; q < 2; q++) {
                    float v = cc[half*2 + q] + bias[col + q];
                    v = v / (1.f + expf(-v));
                    size_t idx = (size_t)r * DMODEL + colofs + col + q;
                    Hout[idx] = v;
                    __half hi, lo;
                    split1(v, hi, lo);
                    ohi[idx] = hi;
                    olo[idx] = lo;
                }
            }
        }
    }
}

// ------------------------- helpers -------------------------
__device__ __forceinline__ float blockReduceSum(float v, float* red) {
    int tid = threadIdx.x;
    #pragma unroll
    for (int o = 16; o; o >>= 1) v += __shfl_xor_sync(0xffffffffu, v, o);
    if ((tid & 31) == 0) red[tid >> 5] = v;
    __syncthreads();
    if (tid < 32) {
        float w = (tid < 8) ? red[tid] : 0.f;
        #pragma unroll
        for (int o = 4; o; o >>= 1) w += __shfl_xor_sync(0xffffffffu, w, o);
        if (tid == 0) red[0] = w;
    }
    __syncthreads();
    float r0 = red[0];
    __syncthreads();
    return r0;
}

// ------------------------- front 1x1 conv SGEMM (writes hmid + fp16 split) -------------------------
__global__ __launch_bounds__(256) void gemm128_nt(
    const float* __restrict__ A, const float* __restrict__ B,
    float* __restrict__ C, int N, int K,
    const float* __restrict__ bias,
    __half* __restrict__ ohi, __half* __restrict__ olo)
{
    __shared__ float As[8][128];
    __shared__ float Bs[8][128];
    int m0 = blockIdx.y * 128, n0 = blockIdx.x * 128;
    int tid = threadIdx.x;
    int tx = tid & 15, ty = tid >> 4;
    float acc[8][8] = {};
    int lr = tid >> 1;
    int lk = (tid & 1) * 4;
    const float* Ag = A + (size_t)(m0 + lr) * K + lk;
    const float* Bg = B + (size_t)(n0 + lr) * K + lk;
    bool bvalid = (n0 + lr) < N;
    for (int k0 = 0; k0 < K; k0 += 8) {
        float4 av = *(const float4*)(Ag + k0);
        float4 bv = bvalid ? *(const float4*)(Bg + k0) : make_float4(0.f,0.f,0.f,0.f);
        __syncthreads();
        As[lk+0][lr] = av.x; As[lk+1][lr] = av.y; As[lk+2][lr] = av.z; As[lk+3][lr] = av.w;
        Bs[lk+0][lr] = bv.x; Bs[lk+1][lr] = bv.y; Bs[lk+2][lr] = bv.z; Bs[lk+3][lr] = bv.w;
        __syncthreads();
        #pragma unroll
        for (int kk = 0; kk < 8; kk++) {
            float4 a0 = *(const float4*)&As[kk][ty*8];
            float4 a1 = *(const float4*)&As[kk][ty*8+4];
            float4 b0 = *(const float4*)&Bs[kk][tx*8];
            float4 b1 = *(const float4*)&Bs[kk][tx*8+4];
            float a[8] = {a0.x,a0.y,a0.z,a0.w,a1.x,a1.y,a1.z,a1.w};
            float b[8] = {b0.x,b0.y,b0.z,b0.w,b1.x,b1.y,b1.z,b1.w};
            #pragma unroll
            for (int r = 0; r < 8; r++)
                #pragma unroll
                for (int s = 0; s < 8; s++) acc[r][s] += a[r]*b[s];
        }
    }
    #pragma unroll
    for (int r = 0; r < 8; r++) {
        int m = m0 + ty*8 + r;
        #pragma unroll
        for (int s = 0; s < 8; s++) {
            int n = n0 + tx*8 + s;
            if (n < N) {
                float v = acc[r][s] + bias[n];
                v = v / (1.f + expf(-v));
                size_t idx = (size_t)m * N + n;
                C[idx] = v;
                __half hi, lo;
                split1(v, hi, lo);
                ohi[idx] = hi;
                olo[idx] = lo;
            }
        }
    }
}

// ------------------------- conv weight NT transpose -------------------------
__global__ void transpose_wc(const float* __restrict__ w, float* __restrict__ wt, int KTAP)
{
    int idx = blockIdx.x * 256 + threadIdx.x;
    int K = KTAP * 128;
    int total = 256 * K;
    if (idx >= total) return;
    int o = idx / K;
    int kk = idx - o * K;
    int tap = kk >> 7;
    int i = kk & 127;
    wt[idx] = w[(size_t)o * 128 * KTAP + (size_t)i * KTAP + tap];
}

// ------------------------- dt softplus -------------------------
__global__ void dt_softplus(const float* __restrict__ zx, const float* __restrict__ dtb,
                            float* __restrict__ dt)
{
    int idx = blockIdx.x * 256 + threadIdx.x;
    if (idx >= NTOK * NHEADS) return;
    int t = idx / NHEADS, hh = idx - t * NHEADS;
    float x = zx[(size_t)t * DINPROJ + 3200 + hh] + dtb[hh];
    dt[idx] = (x > 20.f) ? x : log1pf(expf(x));
}

// ------------------------- depthwise causal conv + silu (4 tokens/thread) -------------------------
__global__ void dwconv4(const float* __restrict__ zx, const float* __restrict__ cw,
                        const float* __restrict__ cb, float* __restrict__ xBC)
{
    int c = blockIdx.x * 256 + threadIdx.x;
    if (c >= CONVDIM) return;
    int t0 = blockIdx.y * 4;
    int ti0 = t0 & (TLEN - 1);
    float4 w = *(const float4*)(cw + (size_t)c * 4);
    float bias = cb[c];
    float z[7];
    #pragma unroll
    for (int j = 0; j < 7; j++) {
        int ti = ti0 - 3 + j;
        z[j] = (ti >= 0) ? zx[(size_t)(t0 - 3 + j) * DINPROJ + DINNER + c] : 0.f;
    }
    #pragma unroll
    for (int j = 0; j < 4; j++) {
        float acc = bias + z[j]*w.x + z[j+1]*w.y + z[j+2]*w.z + z[j+3]*w.w;
        xBC[(size_t)(t0 + j) * CONVDIM + c] = acc / (1.f + expf(-acc));
    }
}

// ------------------------- SSD per-chunk kernel -------------------------
__global__ __launch_bounds__(256) void ssd_chunk(
    const float* __restrict__ xBC, const float* __restrict__ dt,
    const float* __restrict__ A_log, const float* __restrict__ Dv,
    float* __restrict__ ys, float* __restrict__ Sg,
    float* __restrict__ segout, float* __restrict__ cdout)
{
    extern __shared__ float sm[];
    float* Bs  = sm;
    float* Cs  = Bs + 64*SMP;
    float* Ds  = Cs + 64*SMP;
    float* seg = Ds + 64*SMP;
    float* dec = seg + 64;
    float* dts = dec + 64;

    int blk = blockIdx.x;
    int h = blk % NHEADS;
    int c = (blk / NHEADS) & (NCHUNK - 1);
    int b = blk / (NHEADS * NCHUNK);
    int t0 = b * TLEN + c * 64;
    int tid = threadIdx.x;
    float A = -expf(A_log[h]);

    if (tid < 64) dts[tid] = dt[(size_t)(t0 + tid) * NHEADS + h];
    __syncthreads();
    for (int e = tid; e < 4096; e += 256) {
        int j = e >> 6, n = e & 63;
        const float* row = xBC + (size_t)(t0 + j) * CONVDIM;
        Bs[j*SMP + n] = row[DINNER + n];
        Cs[j*SMP + n] = row[DINNER + DSTATE + n];
        Ds[j*SMP + n] = dts[j] * row[h*64 + n];
    }
    if (tid < 64) seg[tid] = dts[tid] * A;
    __syncthreads();
    for (int off = 1; off < 64; off <<= 1) {
        float v = 0.f;
        bool act = (tid < 64) && (tid >= off);
        if (act) v = seg[tid - off];
        __syncthreads();
        if (act) seg[tid] += v;
        __syncthreads();
    }
    if (tid < 64) {
        dec[tid] = expf(seg[63] - seg[tid]);
        segout[(size_t)blk * 64 + tid] = seg[tid];
    }
    if (tid == 0) cdout[blk] = expf(seg[63]);
    __syncthreads();

    int tx = tid & 15, ty = tid >> 4;
    float acc[4][4] = {};
    #pragma unroll 4
    for (int n = 0; n < 64; n++) {
        float a[4], bb[4];
        #pragma unroll
        for (int r = 0; r < 4; r++) a[r] = Cs[(ty*4 + r)*SMP + n];
        #pragma unroll
        for (int s = 0; s < 4; s++) bb[s] = Bs[(tx*4 + s)*SMP + n];
        #pragma unroll
        for (int r = 0; r < 4; r++)
            #pragma unroll
            for (int s = 0; s < 4; s++) acc[r][s] += a[r]*bb[s];
    }
    __syncthreads();
    #pragma unroll
    for (int r = 0; r < 4; r++)
        #pragma unroll
        for (int s = 0; s < 4; s++) {
            int i = ty*4 + r, j = tx*4 + s;
            float v = 0.f;
            if (i >= j) v = expf(seg[i] - seg[j]) * acc[r][s];
            Cs[i*SMP + j] = v;
        }
    __syncthreads();
    float acc2[4][4] = {};
    #pragma unroll 4
    for (int j = 0; j < 64; j++) {
        float a[4], bb[4];
        #pragma unroll
        for (int r = 0; r < 4; r++) a[r] = Cs[(ty*4 + r)*SMP + j];
        #pragma unroll
        for (int s = 0; s < 4; s++) bb[s] = Ds[j*SMP + tx*4 + s];
        #pragma unroll
        for (int r = 0; r < 4; r++)
            #pragma unroll
            for (int s = 0; s < 4; s++) acc2[r][s] += a[r]*bb[s];
    }
    float Dh = Dv[h];
    #pragma unroll
    for (int r = 0; r < 4; r++)
        #pragma unroll
        for (int s = 0; s < 4; s++) {
            int i = t0 + ty*4 + r;
            int p = tx*4 + s;
            ys[(size_t)i * DINNER + h*64 + p] =
                acc2[r][s] + Dh * xBC[(size_t)i * CONVDIM + h*64 + p];
        }
    float acc3[4][4] = {};
    #pragma unroll 4
    for (int j = 0; j < 64; j++) {
        float dj = dec[j];
        float a[4], bb[4];
        #pragma unroll
        for (int r = 0; r < 4; r++) a[r] = Ds[j*SMP + ty*4 + r] * dj;
        #pragma unroll
        for (int s = 0; s < 4; s++) bb[s] = Bs[j*SMP + tx*4 + s];
        #pragma unroll
        for (int r = 0; r < 4; r++)
            #pragma unroll
            for (int s = 0; s < 4; s++) acc3[r][s] += a[r]*bb[s];
    }
    #pragma unroll
    for (int r = 0; r < 4; r++)
        #pragma unroll
        for (int s = 0; s < 4; s++)
            Sg[(size_t)blk * 4096 + (ty*4 + r)*64 + tx*4 + s] = acc3[r][s];
}

// ------------------------- inter-chunk scan (8-way partitioned) -------------------------
__global__ __launch_bounds__(256) void ssd_scan8(float* __restrict__ Sg,
                                                 const float* __restrict__ cd)
{
    int blk = blockIdx.x;
    int part = blk & 7;
    int bh = blk >> 3;
    int h = bh % NHEADS, b = bh / NHEADS;
    int tid = threadIdx.x;
    int e0 = part * 512 + tid;
    float st0 = 0.f, st1 = 0.f;
    for (int c = 0; c < NCHUNK; c++) {
        int bidx = (b * NCHUNK + c) * NHEADS + h;
        size_t base = (size_t)bidx * 4096;
        float d = cd[bidx];
        float s0 = Sg[base + e0];
        float s1 = Sg[base + e0 + 256];
        Sg[base + e0]       = st0;
        Sg[base + e0 + 256] = st1;
        st0 = st0 * d + s0;
        st1 = st1 * d + s1;
    }
}

// ------------------------- y_inter accumulation -------------------------
__global__ __launch_bounds__(256) void ssd_inter(
    const float* __restrict__ xBC, const float* __restrict__ Sg,
    const float* __restrict__ segin, float* __restrict__ ys)
{
    __shared__ float Cs[64*SMP];
    __shared__ float Hs[64*SMP];
    __shared__ float seg[64];
    int blk = blockIdx.x;
    int h = blk % NHEADS;
    int c = (blk / NHEADS) & (NCHUNK - 1);
    int b = blk / (NHEADS * NCHUNK);
    int t0 = b * TLEN + c * 64;
    int tid = threadIdx.x;
    for (int e = tid; e < 4096; e += 256) {
        int j = e >> 6, n = e & 63;
        Cs[j*SMP + n] = xBC[(size_t)(t0 + j) * CONVDIM + DINNER + DSTATE + n];
        Hs[j*SMP + n] = Sg[(size_t)blk * 4096 + j*64 + n];
    }
    if (tid < 64) seg[tid] = segin[(size_t)blk * 64 + tid];
    __syncthreads();
    int tx = tid & 15, ty = tid >> 4;
    float acc[4][4] = {};
    #pragma unroll 4
    for (int n = 0; n < 64; n++) {
        float a[4], bb[4];
        #pragma unroll
        for (int r = 0; r < 4; r++) a[r] = Cs[(ty*4 + r)*SMP + n];
        #pragma unroll
        for (int s = 0; s < 4; s++) bb[s] = Hs[(tx*4 + s)*SMP + n];
        #pragma unroll
        for (int r = 0; r < 4; r++)
            #pragma unroll
            for (int s = 0; s < 4; s++) acc[r][s] += a[r]*bb[s];
    }
    #pragma unroll
    for (int r = 0; r < 4; r++) {
        float ei = expf(seg[ty*4 + r]);
        #pragma unroll
        for (int s = 0; s < 4; s++) {
            size_t idx = (size_t)(t0 + ty*4 + r) * DINNER + h*64 + tx*4 + s;
            ys[idx] += acc[r][s] * ei;
        }
    }
}

// ------------------------- gating + RMSNorm (writes fp16 split) -------------------------
__global__ __launch_bounds__(256) void gate_rms(
    const float* __restrict__ ys, const float* __restrict__ zx,
    const float* __restrict__ nw,
    __half* __restrict__ ohi, __half* __restrict__ olo)
{
    __shared__ float red[32];
    int t = blockIdx.x, tid = threadIdx.x;
    float v[6];
    float ss = 0.f;
    #pragma unroll
    for (int r = 0; r < 6; r++) {
        int i = tid + r*256;
        float z = zx[(size_t)t * DINPROJ + i];
        float val = ys[(size_t)t * DINNER + i] * (z / (1.f + expf(-z)));
        v[r] = val;
        ss += val*val;
    }
    ss = blockReduceSum(ss, red);
    float sc = rsqrtf(ss / (float)DINNER + 1e-5f);
    #pragma unroll
    for (int r = 0; r < 6; r++) {
        int i = tid + r*256;
        float val = v[r] * sc * nw[i];
        __half hi, lo;
        split1(val, hi, lo);
        size_t idx = (size_t)t * DINNER + i;
        ohi[idx] = hi;
        olo[idx] = lo;
    }
}

// ------------------------- residual + layernorm (writes h + fp16 split) -------------------------
__global__ __launch_bounds__(256) void resid_ln(
    const float* __restrict__ y2, float* __restrict__ hio,
    const float* __restrict__ w, const float* __restrict__ b,
    __half* __restrict__ ohi, __half* __restrict__ olo)
{
    __shared__ float red[32];
    int t = blockIdx.x, tid = threadIdx.x;
    float v[3];
    float s = 0.f;
    #pragma unroll
    for (int r = 0; r < 3; r++) {
        int i = tid + r*256;
        v[r] = y2[(size_t)t * DMODEL + i] + hio[(size_t)t * DMODEL + i];
        s += v[r];
    }
    s = blockReduceSum(s, red);
    float mean = s / (float)DMODEL;
    float q = 0.f;
    #pragma unroll
    for (int r = 0; r < 3; r++) { v[r] -= mean; q += v[r]*v[r]; }
    q = blockReduceSum(q, red);
    float inv = rsqrtf(q / (float)DMODEL + 1e-5f);
    #pragma unroll
    for (int r = 0; r < 3; r++) {
        int i = tid + r*256;
        float val = v[r] * inv * w[i] + b[i];
        size_t idx = (size_t)t * DMODEL + i;
        hio[idx] = val;
        __half hi, lo;
        split1(val, hi, lo);
        ohi[idx] = hi;
        olo[idx] = lo;
    }
}

// ------------------------- final layernorm + logits -------------------------
__global__ __launch_bounds__(256) void head_kernel(
    const float* __restrict__ hin,
    const float* __restrict__ fw, const float* __restrict__ fb,
    const float* __restrict__ lw, const float* __restrict__ lb,
    float* __restrict__ out)
{
    __shared__ float red[32];
    __shared__ float buf[DMODEL];
    int t = blockIdx.x, tid = threadIdx.x;
    float v[3];
    float s = 0.f;
    #pragma unroll
    for (int r = 0; r < 3; r++) {
        int i = tid + r*256;
        v[r] = hin[(size_t)t * DMODEL + i];
        s += v[r];
    }
    s = blockReduceSum(s, red);
    float mean = s / (float)DMODEL;
    float q = 0.f;
    #pragma unroll
    for (int r = 0; r < 3; r++) { v[r] -= mean; q += v[r]*v[r]; }
    q = blockReduceSum(q, red);
    float inv = rsqrtf(q / (float)DMODEL + 1e-5f);
    #pragma unroll
    for (int r = 0; r < 3; r++) {
        int i = tid + r*256;
        buf[i] = v[r] * inv * fw[i] + fb[i];
    }
    __syncthreads();
    for (int cls = 0; cls < 10; cls++) {
        float p = 0.f;
        #pragma unroll
        for (int r = 0; r < 3; r++) {
            int i = tid + r*256;
            p += buf[i] * lw[(size_t)cls * DMODEL + i];
        }
        p = blockReduceSum(p, red);
        if (tid == 0) out[(size_t)t * 10 + cls] = p + lb[cls];
    }
}

// ------------------------- launch -------------------------
extern "C" void kernel_launch(void* const* d_in, const int* in_sizes, int n_in,
                              void* d_out, int out_size)
{
    const float* x       = (const float*)d_in[0];
    const float* pc_w    = (const float*)d_in[1];
    const float* pc_b    = (const float*)d_in[2];
    const float* c1_w    = (const float*)d_in[3];
    const float* c1_b    = (const float*)d_in[4];
    const float* c2_w    = (const float*)d_in[5];
    const float* c2_b    = (const float*)d_in[6];
    const float* c3_w    = (const float*)d_in[7];
    const float* c3_b    = (const float*)d_in[8];
    const float* in_proj = (const float*)d_in[9];
    const float* conv_w  = (const float*)d_in[10];
    const float* conv_b  = (const float*)d_in[11];
    const float* dt_bias = (const float*)d_in[12];
    const float* A_log   = (const float*)d_in[13];
    const float* Dvec    = (const float*)d_in[14];
    const float* norm_w  = (const float*)d_in[15];
    const float* out_proj= (const float*)d_in[16];
    const float* ln_w    = (const float*)d_in[17];
    const float* ln_b    = (const float*)d_in[18];
    const float* fn_w    = (const float*)d_in[19];
    const float* fn_b    = (const float*)d_in[20];
    const float* lo_w    = (const float*)d_in[21];
    const float* lo_b    = (const float*)d_in[22];
    float* out = (float*)d_out;

    float *hmid, *h, *zx, *xBC, *dtb, *ys, *y2, *S, *segb, *cdb, *wt;
    __half *ahi, *alo, *hmh, *hml, *wch, *wih, *woh;
    cudaGetSymbolAddress((void**)&hmid, g_hmid);
    cudaGetSymbolAddress((void**)&h,    g_h);
    cudaGetSymbolAddress((void**)&zx,   g_zx);
    cudaGetSymbolAddress((void**)&xBC,  g_xBC);
    cudaGetSymbolAddress((void**)&dtb,  g_dt);
    cudaGetSymbolAddress((void**)&ys,   g_ys);
    cudaGetSymbolAddress((void**)&y2,   g_y2);
    cudaGetSymbolAddress((void**)&S,    g_S);
    cudaGetSymbolAddress((void**)&segb, g_seg);
    cudaGetSymbolAddress((void**)&cdb,  g_cd);
    cudaGetSymbolAddress((void**)&wt,   g_wt);
    cudaGetSymbolAddress((void**)&ahi,  g_ahi);
    cudaGetSymbolAddress((void**)&alo,  g_alo);
    cudaGetSymbolAddress((void**)&hmh,  g_hmh);
    cudaGetSymbolAddress((void**)&hml,  g_hml);
    cudaGetSymbolAddress((void**)&wch,  g_wch);
    cudaGetSymbolAddress((void**)&wih,  g_wih);
    cudaGetSymbolAddress((void**)&woh,  g_woh);

    const int SSD_SMEM = (3 * 64 * SMP + 3 * 64) * (int)sizeof(float);
    cudaFuncSetAttribute(ssd_chunk, cudaFuncAttributeMaxDynamicSharedMemorySize, SSD_SMEM);
    const int MG_SMEM = 2 * MG_STAGE;   // 40960
    cudaFuncSetAttribute(mma_gemm, cudaFuncAttributeMaxDynamicSharedMemorySize, MG_SMEM);
    cudaFuncSetAttribute(mma_conv<3>,  cudaFuncAttributeMaxDynamicSharedMemorySize, MG_SMEM);
    cudaFuncSetAttribute(mma_conv<9>,  cudaFuncAttributeMaxDynamicSharedMemorySize, MG_SMEM);
    cudaFuncSetAttribute(mma_conv<27>, cudaFuncAttributeMaxDynamicSharedMemorySize, MG_SMEM);

    // ---- front ----
    gemm128_nt<<<dim3(1, NTOK/128), 256>>>(x, pc_w, hmid, 128, 64, pc_b, hmh, hml);
    transpose_wc<<<(256*384  + 255)/256, 256>>>(c1_w, wt,           3);
    transpose_wc<<<(256*1152 + 255)/256, 256>>>(c2_w, wt + 98304,   9);
    transpose_wc<<<(256*3456 + 255)/256, 256>>>(c3_w, wt + 393216, 27);
    to_half<<<(1277952/4 + 255)/256, 256>>>((const float4*)wt, wch, 1277952/4);
    mma_conv<3> <<<dim3(2, NTOK/64), 128, MG_SMEM>>>(hmh, hml, wch,          c1_b, h, ahi, alo, 0);
    mma_conv<9> <<<dim3(2, NTOK/64), 128, MG_SMEM>>>(hmh, hml, wch + 98304,  c2_b, h, ahi, alo, 256);
    mma_conv<27><<<dim3(2, NTOK/64), 128, MG_SMEM>>>(hmh, hml, wch + 393216, c3_b, h, ahi, alo, 512);

    // ---- weight fp16 conversion ----
    {
        int n4 = 4 * DINPROJ * DMODEL / 4;
        to_half<<<(n4 + 255)/256, 256>>>((const float4*)in_proj, wih, n4);
        int m4 = 4 * DMODEL * DINNER / 4;
        to_half<<<(m4 + 255)/256, 256>>>((const float4*)out_proj, woh, m4);
    }

    // ---- layers ----
    for (int l = 0; l < 4; l++) {
        mma_gemm<<<dim3((DINPROJ + 127)/128, NTOK/64), 128, MG_SMEM>>>(
            ahi, alo, wih + (size_t)l * DINPROJ * DMODEL,
            zx, DINPROJ, DMODEL);
        dt_softplus<<<(NTOK*NHEADS + 255)/256, 256>>>(zx, dt_bias + l*NHEADS, dtb);
        dwconv4<<<dim3((CONVDIM + 255)/256, NTOK/4), 256>>>(
            zx, conv_w + (size_t)l * CONVDIM * 4, conv_b + (size_t)l * CONVDIM, xBC);
        ssd_chunk<<<NBLK_SSD, 256, SSD_SMEM>>>(
            xBC, dtb, A_log + l*NHEADS, Dvec + l*NHEADS, ys, S, segb, cdb);
        ssd_scan8<<<8*NHEADS*8, 256>>>(S, cdb);
        ssd_inter<<<NBLK_SSD, 256>>>(xBC, S, segb, ys);
        gate_rms<<<NTOK, 256>>>(ys, zx, norm_w + (size_t)l * DINNER, ahi, alo);
        mma_gemm<<<dim3(DMODEL/128, NTOK/64), 128, MG_SMEM>>>(
            ahi, alo, woh + (size_t)l * DMODEL * DINNER,
            y2, DMODEL, DINNER);
        resid_ln<<<NTOK, 256>>>(y2, h, ln_w + (size_t)l * DMODEL, ln_b + (size_t)l * DMODEL,
                                ahi, alo);
    }

    // ---- head ----
    head_kernel<<<NTOK, 256>>>(h, fn_w, fn_b, lo_w, lo_b, out);
    (void)in_sizes; (void)n_in; (void)out_size;
}

// round 10
// speedup vs baseline: 1.8236x; 1.0834x over previous
#include <cuda_runtime.h>
#include <cuda_fp16.h>
#include <cstdint>
#include <math.h>

#define NTOK   16384
#define TLEN   2048
#define DMODEL 768
#define DINNER 1536
#define DSTATE 64
#define NHEADS 24
#define CONVDIM 1664
#define DINPROJ 3224
#define NCHUNK 32
#define NBC    256                   /* 8 batches * 32 chunks */
#define NBLK_SSD (NBC*NHEADS)        /* 6144 */
#define SMT 68                       /* smem pitch (floats), 16B-aligned rows */

// ------------------------- scratch (device globals) -------------------------
__device__ float g_hmid[(size_t)NTOK*128];
__device__ float g_h   [(size_t)NTOK*DMODEL];
__device__ float g_zx  [(size_t)NTOK*DINPROJ];
__device__ float g_xBC [(size_t)NTOK*CONVDIM];
__device__ float g_dt  [(size_t)NTOK*NHEADS];
__device__ float g_ys  [(size_t)NTOK*DINNER];
__device__ float g_y2  [(size_t)NTOK*DMODEL];
__device__ float g_S   [(size_t)NBLK_SSD*4096];
__device__ float g_seg [(size_t)NBLK_SSD*64];
__device__ float g_cd  [NBLK_SSD];
__device__ float g_sc  [(size_t)NBC*4096];           /* scoresT per (b,c) */
__device__ float g_wt  [(size_t)(3+9+27)*128*256];
// fp16 buffers: activations split hi/lo, weights single fp16
__device__ __half g_ahi[(size_t)NTOK*DINNER];
__device__ __half g_alo[(size_t)NTOK*DINNER];
__device__ __half g_hmh[(size_t)NTOK*128];
__device__ __half g_hml[(size_t)NTOK*128];
__device__ __half g_wch[(size_t)(3+9+27)*128*256];
__device__ __half g_wih[(size_t)4*DINPROJ*DMODEL];
__device__ __half g_woh[(size_t)4*DMODEL*DINNER];

// ------------------------- PTX helpers -------------------------
__device__ __forceinline__ uint32_t smem_u32(const void* p) {
    uint32_t a;
    asm("{ .reg .u64 t; cvta.to.shared.u64 t, %1; cvt.u32.u64 %0, t; }" : "=r"(a) : "l"(p));
    return a;
}
__device__ __forceinline__ void cp16z(uint32_t dst, const void* src, int srcsz) {
    asm volatile("cp.async.cg.shared.global [%0], [%1], 16, %2;" :: "r"(dst), "l"(src), "r"(srcsz));
}
__device__ __forceinline__ void ldsm4(uint32_t* r, uint32_t addr) {
    asm volatile("ldmatrix.sync.aligned.m8n8.x4.shared.b16 {%0,%1,%2,%3}, [%4];"
        : "=r"(r[0]), "=r"(r[1]), "=r"(r[2]), "=r"(r[3]) : "r"(addr));
}
__device__ __forceinline__ void mma16816(float* c, const uint32_t* a, const uint32_t* b) {
    asm volatile("mma.sync.aligned.m16n8k16.row.col.f32.f16.f16.f32 "
        "{%0,%1,%2,%3}, {%4,%5,%6,%7}, {%8,%9}, {%0,%1,%2,%3};"
        : "+f"(c[0]), "+f"(c[1]), "+f"(c[2]), "+f"(c[3])
        : "r"(a[0]), "r"(a[1]), "r"(a[2]), "r"(a[3]), "r"(b[0]), "r"(b[1]));
}
__device__ __forceinline__ void split1(float v, __half& hi, __half& lo) {
    hi = __float2half_rn(v);
    lo = __float2half_rn(v - __half2float(hi));
}

// ------------------------- split fp32 -> fp16 hi/lo -------------------------
__global__ void split_half(const float4* __restrict__ src,
                           __half* __restrict__ hi,
                           __half* __restrict__ lo, int n4)
{
    int i = blockIdx.x * 256 + threadIdx.x;
    if (i >= n4) return;
    float4 v = src[i];
    float vv[4] = {v.x, v.y, v.z, v.w};
    __half h4[4], l4[4];
    #pragma unroll
    for (int j = 0; j < 4; j++) split1(vv[j], h4[j], l4[j]);
    uint2 hp, lp;
    hp.x = (uint32_t)__half_as_ushort(h4[0]) | ((uint32_t)__half_as_ushort(h4[1]) << 16);
    hp.y = (uint32_t)__half_as_ushort(h4[2]) | ((uint32_t)__half_as_ushort(h4[3]) << 16);
    lp.x = (uint32_t)__half_as_ushort(l4[0]) | ((uint32_t)__half_as_ushort(l4[1]) << 16);
    lp.y = (uint32_t)__half_as_ushort(l4[2]) | ((uint32_t)__half_as_ushort(l4[3]) << 16);
    *reinterpret_cast<uint2*>(hi + (size_t)i * 4) = hp;
    *reinterpret_cast<uint2*>(lo + (size_t)i * 4) = lp;
}

// ------------------------- convert fp32 -> fp16 (weights) -------------------------
__global__ void to_half(const float4* __restrict__ src, __half* __restrict__ dst, int n4)
{
    int i = blockIdx.x * 256 + threadIdx.x;
    if (i >= n4) return;
    float4 v = src[i];
    __half h4[4] = { __float2half_rn(v.x), __float2half_rn(v.y),
                     __float2half_rn(v.z), __float2half_rn(v.w) };
    uint2 hp;
    hp.x = (uint32_t)__half_as_ushort(h4[0]) | ((uint32_t)__half_as_ushort(h4[1]) << 16);
    hp.y = (uint32_t)__half_as_ushort(h4[2]) | ((uint32_t)__half_as_ushort(h4[3]) << 16);
    *reinterpret_cast<uint2*>(dst + (size_t)i * 4) = hp;
}

// ------------------------- 2-term split-fp16 NT GEMM, 64x128 tile, 128 thr -------------------------
#define MG_PITCH 80
#define MG_AMAT  5120
#define MG_BBASE 10240
#define MG_STAGE 20480

__device__ __forceinline__ void mg_load(
    uint32_t sbase,
    const __half* __restrict__ Ah, const __half* __restrict__ Al,
    const __half* __restrict__ B,
    int m0, int n0, int Ntot, int K, int c, int tid)
{
    #pragma unroll
    for (int j = 0; j < 4; j++) {
        int e = tid + j * 128;
        int seg = e & 3, r = (e >> 2) & 63, mat = e >> 8;
        uint32_t soff = (uint32_t)(mat * MG_AMAT + r * MG_PITCH + seg * 16);
        const __half* src = (mat ? Al : Ah) + (size_t)(m0 + r) * K + (size_t)c * 32 + seg * 8;
        cp16z(sbase + soff, src, 16);
    }
    #pragma unroll
    for (int j = 0; j < 4; j++) {
        int e = tid + j * 128;
        int seg = e & 3, r = e >> 2;
        uint32_t soff = (uint32_t)(MG_BBASE + r * MG_PITCH + seg * 16);
        int nr = n0 + r;
        int sz = (nr < Ntot) ? 16 : 0;
        int nrc = (nr < Ntot) ? nr : 0;
        const __half* src = B + (size_t)nrc * K + (size_t)c * 32 + seg * 8;
        cp16z(sbase + soff, src, sz);
    }
    asm volatile("cp.async.commit_group;" ::: "memory");
}

__global__ __launch_bounds__(128, 3) void mma_gemm(
    const __half* __restrict__ Ah, const __half* __restrict__ Al,
    const __half* __restrict__ B,
    float* __restrict__ C, int Ntot, int K)
{
    extern __shared__ char smem[];
    uint32_t sb = smem_u32(smem);
    int tid = threadIdx.x, wid = tid >> 5, lane = tid & 31;
    int m0 = blockIdx.y * 64, n0 = blockIdx.x * 128;
    int wm = (wid >> 1) * 32;
    int wn = (wid & 1) * 64;

    float acc[2][8][4];
    #pragma unroll
    for (int a = 0; a < 2; a++)
        #pragma unroll
        for (int b = 0; b < 8; b++)
            #pragma unroll
            for (int q = 0; q < 4; q++) acc[a][b][q] = 0.f;

    int gr = lane >> 3, lr = lane & 7;
    int arow = (gr & 1) * 8 + lr;
    int acol = (gr >> 1) * 16;
    int brow = (gr >> 1) * 8 + lr;
    int bcol = (gr & 1) * 16;

    int nch = K >> 5;
    mg_load(sb, Ah, Al, B, m0, n0, Ntot, K, 0, tid);
    for (int c = 0; c < nch; c++) {
        if (c + 1 < nch) {
            mg_load(sb + ((c + 1) & 1) * MG_STAGE, Ah, Al, B, m0, n0, Ntot, K, c + 1, tid);
            asm volatile("cp.async.wait_group 1;" ::: "memory");
        } else {
            asm volatile("cp.async.wait_group 0;" ::: "memory");
        }
        __syncthreads();
        uint32_t base = sb + (uint32_t)(c & 1) * MG_STAGE;
        #pragma unroll
        for (int ks = 0; ks < 2; ks++) {
            uint32_t ah[2][4], al[2][4];
            #pragma unroll
            for (int mt = 0; mt < 2; mt++) {
                uint32_t off = (uint32_t)((wm + mt*16 + arow) * MG_PITCH + acol + ks*32);
                ldsm4(ah[mt], base + off);
                ldsm4(al[mt], base + MG_AMAT + off);
            }
            #pragma unroll
            for (int np = 0; np < 4; np++) {
                uint32_t bb[4];
                uint32_t off = (uint32_t)(MG_BBASE + (wn + np*16 + brow) * MG_PITCH + bcol + ks*32);
                ldsm4(bb, base + off);
                #pragma unroll
                for (int mt = 0; mt < 2; mt++) {
                    mma16816(acc[mt][2*np],   ah[mt], &bb[0]);
                    mma16816(acc[mt][2*np+1], ah[mt], &bb[2]);
                    mma16816(acc[mt][2*np],   al[mt], &bb[0]);
                    mma16816(acc[mt][2*np+1], al[mt], &bb[2]);
                }
            }
        }
        __syncthreads();
    }

    int r4 = lane >> 2, c2 = (lane & 3) * 2;
    #pragma unroll
    for (int mt = 0; mt < 2; mt++) {
        int r = m0 + wm + mt*16 + r4;
        #pragma unroll
        for (int nt = 0; nt < 8; nt++) {
            int col = n0 + wn + nt*8 + c2;
            if (col < Ntot) {
                float* cc = acc[mt][nt];
                *(float2*)&C[(size_t)r * Ntot + col]       = make_float2(cc[0], cc[1]);
                *(float2*)&C[(size_t)(r + 8) * Ntot + col] = make_float2(cc[2], cc[3]);
            }
        }
    }
}

// ------------------------- 2-term mma conv (implicit im2col), 64x128 tile, N=256 -------------------------
template<int KTAP>
__device__ __forceinline__ void mg_load_conv(
    uint32_t sbase,
    const __half* __restrict__ Ah, const __half* __restrict__ Al,
    const __half* __restrict__ B,
    int m0, int n0, int c, int tid)
{
    const int PAD = KTAP / 2;
    const int K = KTAP * 128;
    int tap = c >> 2;
    int ch0 = (c & 3) * 32;
    #pragma unroll
    for (int j = 0; j < 4; j++) {
        int e = tid + j * 128;
        int seg = e & 3, r = (e >> 2) & 63, mat = e >> 8;
        uint32_t soff = (uint32_t)(mat * MG_AMAT + r * MG_PITCH + seg * 16);
        int tg = m0 + r;
        int tsrc = (tg & (TLEN - 1)) + tap - PAD;
        int valid = (tsrc >= 0 && tsrc < TLEN);
        size_t gidx = valid ? ((size_t)(tg + tap - PAD) * 128 + ch0 + seg * 8) : 0;
        const __half* src = (mat ? Al : Ah) + gidx;
        cp16z(sbase + soff, src, valid ? 16 : 0);
    }
    #pragma unroll
    for (int j = 0; j < 4; j++) {
        int e = tid + j * 128;
        int seg = e & 3, r = e >> 2;
        uint32_t soff = (uint32_t)(MG_BBASE + r * MG_PITCH + seg * 16);
        const __half* src = B + (size_t)(n0 + r) * K + (size_t)c * 32 + seg * 8;
        cp16z(sbase + soff, src, 16);
    }
    asm volatile("cp.async.commit_group;" ::: "memory");
}

template<int KTAP>
__global__ __launch_bounds__(128, 3) void mma_conv(
    const __half* __restrict__ Ah, const __half* __restrict__ Al,
    const __half* __restrict__ B,
    const float* __restrict__ bias, float* __restrict__ Hout,
    __half* __restrict__ ohi, __half* __restrict__ olo, int colofs)
{
    extern __shared__ char smem[];
    uint32_t sb = smem_u32(smem);
    int tid = threadIdx.x, wid = tid >> 5, lane = tid & 31;
    int m0 = blockIdx.y * 64, n0 = blockIdx.x * 128;
    int wm = (wid >> 1) * 32;
    int wn = (wid & 1) * 64;

    float acc[2][8][4];
    #pragma unroll
    for (int a = 0; a < 2; a++)
        #pragma unroll
        for (int b = 0; b < 8; b++)
            #pragma unroll
            for (int q = 0; q < 4; q++) acc[a][b][q] = 0.f;

    int gr = lane >> 3, lr = lane & 7;
    int arow = (gr & 1) * 8 + lr;
    int acol = (gr >> 1) * 16;
    int brow = (gr >> 1) * 8 + lr;
    int bcol = (gr & 1) * 16;

    const int nch = KTAP * 4;
    mg_load_conv<KTAP>(sb, Ah, Al, B, m0, n0, 0, tid);
    for (int c = 0; c < nch; c++) {
        if (c + 1 < nch) {
            mg_load_conv<KTAP>(sb + ((c + 1) & 1) * MG_STAGE, Ah, Al, B, m0, n0, c + 1, tid);
            asm volatile("cp.async.wait_group 1;" ::: "memory");
        } else {
            asm volatile("cp.async.wait_group 0;" ::: "memory");
        }
        __syncthreads();
        uint32_t base = sb + (uint32_t)(c & 1) * MG_STAGE;
        #pragma unroll
        for (int ks = 0; ks < 2; ks++) {
            uint32_t ah[2][4], al[2][4];
            #pragma unroll
            for (int mt = 0; mt < 2; mt++) {
                uint32_t off = (uint32_t)((wm + mt*16 + arow) * MG_PITCH + acol + ks*32);
                ldsm4(ah[mt], base + off);
                ldsm4(al[mt], base + MG_AMAT + off);
            }
            #pragma unroll
            for (int np = 0; np < 4; np++) {
                uint32_t bb[4];
                uint32_t off = (uint32_t)(MG_BBASE + (wn + np*16 + brow) * MG_PITCH + bcol + ks*32);
                ldsm4(bb, base + off);
                #pragma unroll
                for (int mt = 0; mt < 2; mt++) {
                    mma16816(acc[mt][2*np],   ah[mt], &bb[0]);
                    mma16816(acc[mt][2*np+1], ah[mt], &bb[2]);
                    mma16816(acc[mt][2*np],   al[mt], &bb[0]);
                    mma16816(acc[mt][2*np+1], al[mt], &bb[2]);
                }
            }
        }
        __syncthreads();
    }

    int r4 = lane >> 2, c2 = (lane & 3) * 2;
    #pragma unroll
    for (int mt = 0; mt < 2; mt++) {
        #pragma unroll
        for (int half = 0; half < 2; half++) {
            int r = m0 + wm + mt*16 + r4 + half*8;
            #pragma unroll
            for (int nt = 0; nt < 8; nt++) {
                int col = n0 + wn + nt*8 + c2;
                float* cc = acc[mt][nt];
                #pragma unroll
                for (int q = 0; q < 2; q++) {
                    float v = cc[half*2 + q] + bias[col + q];
                    v = v / (1.f + expf(-v));
                    size_t idx = (size_t)r * DMODEL + colofs + col + q;
                    Hout[idx] = v;
                    __half hi, lo;
                    split1(v, hi, lo);
                    ohi[idx] = hi;
                    olo[idx] = lo;
                }
            }
        }
    }
}

// ------------------------- helpers -------------------------
__device__ __forceinline__ float blockReduceSum(float v, float* red) {
    int tid = threadIdx.x;
    #pragma unroll
    for (int o = 16; o; o >>= 1) v += __shfl_xor_sync(0xffffffffu, v, o);
    if ((tid & 31) == 0) red[tid >> 5] = v;
    __syncthreads();
    if (tid < 32) {
        float w = (tid < 8) ? red[tid] : 0.f;
        #pragma unroll
        for (int o = 4; o; o >>= 1) w += __shfl_xor_sync(0xffffffffu, w, o);
        if (tid == 0) red[0] = w;
    }
    __syncthreads();
    float r0 = red[0];
    __syncthreads();
    return r0;
}

// ------------------------- front 1x1 conv SGEMM (writes hmid + fp16 split) -------------------------
__global__ __launch_bounds__(256) void gemm128_nt(
    const float* __restrict__ A, const float* __restrict__ B,
    float* __restrict__ C, int N, int K,
    const float* __restrict__ bias,
    __half* __restrict__ ohi, __half* __restrict__ olo)
{
    __shared__ float As[8][128];
    __shared__ float Bs[8][128];
    int m0 = blockIdx.y * 128, n0 = blockIdx.x * 128;
    int tid = threadIdx.x;
    int tx = tid & 15, ty = tid >> 4;
    float acc[8][8] = {};
    int lr = tid >> 1;
    int lk = (tid & 1) * 4;
    const float* Ag = A + (size_t)(m0 + lr) * K + lk;
    const float* Bg = B + (size_t)(n0 + lr) * K + lk;
    bool bvalid = (n0 + lr) < N;
    for (int k0 = 0; k0 < K; k0 += 8) {
        float4 av = *(const float4*)(Ag + k0);
        float4 bv = bvalid ? *(const float4*)(Bg + k0) : make_float4(0.f,0.f,0.f,0.f);
        __syncthreads();
        As[lk+0][lr] = av.x; As[lk+1][lr] = av.y; As[lk+2][lr] = av.z; As[lk+3][lr] = av.w;
        Bs[lk+0][lr] = bv.x; Bs[lk+1][lr] = bv.y; Bs[lk+2][lr] = bv.z; Bs[lk+3][lr] = bv.w;
        __syncthreads();
        #pragma unroll
        for (int kk = 0; kk < 8; kk++) {
            float4 a0 = *(const float4*)&As[kk][ty*8];
            float4 a1 = *(const float4*)&As[kk][ty*8+4];
            float4 b0 = *(const float4*)&Bs[kk][tx*8];
            float4 b1 = *(const float4*)&Bs[kk][tx*8+4];
            float a[8] = {a0.x,a0.y,a0.z,a0.w,a1.x,a1.y,a1.z,a1.w};
            float b[8] = {b0.x,b0.y,b0.z,b0.w,b1.x,b1.y,b1.z,b1.w};
            #pragma unroll
            for (int r = 0; r < 8; r++)
                #pragma unroll
                for (int s = 0; s < 8; s++) acc[r][s] += a[r]*b[s];
        }
    }
    #pragma unroll
    for (int r = 0; r < 8; r++) {
        int m = m0 + ty*8 + r;
        #pragma unroll
        for (int s = 0; s < 8; s++) {
            int n = n0 + tx*8 + s;
            if (n < N) {
                float v = acc[r][s] + bias[n];
                v = v / (1.f + expf(-v));
                size_t idx = (size_t)m * N + n;
                C[idx] = v;
                __half hi, lo;
                split1(v, hi, lo);
                ohi[idx] = hi;
                olo[idx] = lo;
            }
        }
    }
}

// ------------------------- conv weight NT transpose -------------------------
__global__ void transpose_wc(const float* __restrict__ w, float* __restrict__ wt, int KTAP)
{
    int idx = blockIdx.x * 256 + threadIdx.x;
    int K = KTAP * 128;
    int total = 256 * K;
    if (idx >= total) return;
    int o = idx / K;
    int kk = idx - o * K;
    int tap = kk >> 7;
    int i = kk & 127;
    wt[idx] = w[(size_t)o * 128 * KTAP + (size_t)i * KTAP + tap];
}

// ------------------------- dt softplus -------------------------
__global__ void dt_softplus(const float* __restrict__ zx, const float* __restrict__ dtb,
                            float* __restrict__ dt)
{
    int idx = blockIdx.x * 256 + threadIdx.x;
    if (idx >= NTOK * NHEADS) return;
    int t = idx / NHEADS, hh = idx - t * NHEADS;
    float x = zx[(size_t)t * DINPROJ + 3200 + hh] + dtb[hh];
    dt[idx] = (x > 20.f) ? x : log1pf(expf(x));
}

// ------------------------- depthwise causal conv + silu (4 tokens/thread) -------------------------
__global__ void dwconv4(const float* __restrict__ zx, const float* __restrict__ cw,
                        const float* __restrict__ cb, float* __restrict__ xBC)
{
    int c = blockIdx.x * 256 + threadIdx.x;
    if (c >= CONVDIM) return;
    int t0 = blockIdx.y * 4;
    int ti0 = t0 & (TLEN - 1);
    float4 w = *(const float4*)(cw + (size_t)c * 4);
    float bias = cb[c];
    float z[7];
    #pragma unroll
    for (int j = 0; j < 7; j++) {
        int ti = ti0 - 3 + j;
        z[j] = (ti >= 0) ? zx[(size_t)(t0 - 3 + j) * DINPROJ + DINNER + c] : 0.f;
    }
    #pragma unroll
    for (int j = 0; j < 4; j++) {
        float acc = bias + z[j]*w.x + z[j+1]*w.y + z[j+2]*w.z + z[j+3]*w.w;
        xBC[(size_t)(t0 + j) * CONVDIM + c] = acc / (1.f + expf(-acc));
    }
}

// ------------------------- SSD scores (shared across heads): per (b,c) -------------------------
// scoresT[j][i] = sum_n B[j,n] * C[i,n]
__global__ __launch_bounds__(256) void ssd_scores(
    const float* __restrict__ xBC, float* __restrict__ sc)
{
    __shared__ float BsT[64*SMT];
    __shared__ float CsT[64*SMT];
    int bc = blockIdx.x;
    int t0 = bc * 64;
    int tid = threadIdx.x;
    for (int e = tid; e < 4096; e += 256) {
        int j = e >> 6, n = e & 63;
        const float* row = xBC + (size_t)(t0 + j) * CONVDIM + DINNER;
        BsT[n*SMT + j] = row[n];
        CsT[n*SMT + j] = row[DSTATE + n];
    }
    __syncthreads();
    int tx = tid & 15, ty = tid >> 4;
    float acc[4][4] = {};
    #pragma unroll 4
    for (int n = 0; n < 64; n++) {
        float4 a4 = *(const float4*)&BsT[n*SMT + ty*4];
        float4 b4 = *(const float4*)&CsT[n*SMT + tx*4];
        float a[4] = {a4.x,a4.y,a4.z,a4.w};
        float b[4] = {b4.x,b4.y,b4.z,b4.w};
        #pragma unroll
        for (int r = 0; r < 4; r++)
            #pragma unroll
            for (int s = 0; s < 4; s++) acc[r][s] += a[r]*b[s];
    }
    #pragma unroll
    for (int r = 0; r < 4; r++)
        *(float4*)&sc[(size_t)bc*4096 + (ty*4 + r)*64 + tx*4] =
            make_float4(acc[r][0], acc[r][1], acc[r][2], acc[r][3]);
}

// ------------------------- SSD per-(b,c,h): seg scan + 2 GEMMs (float4 operands) ----------------
__global__ __launch_bounds__(256) void ssd_heads(
    const float* __restrict__ xBC, const float* __restrict__ dt,
    const float* __restrict__ sc,
    const float* __restrict__ A_log, const float* __restrict__ Dv,
    float* __restrict__ ys, float* __restrict__ Sg,
    float* __restrict__ segout, float* __restrict__ cdout)
{
    extern __shared__ float sm[];
    float* Bs  = sm;              // [64][SMT]  B rows
    float* Ds  = Bs + 64*SMT;     // [64][SMT]  dtx rows
    float* aT  = Ds + 64*SMT;     // [64][SMT]  attT[j][i]
    float* seg = aT + 64*SMT;
    float* dec = seg + 64;
    float* dts = dec + 64;

    int blk = blockIdx.x;
    int h = blk % NHEADS;
    int bc = blk / NHEADS;
    int t0 = bc * 64;
    int tid = threadIdx.x;
    float A = -expf(A_log[h]);

    if (tid < 64) dts[tid] = dt[(size_t)(t0 + tid) * NHEADS + h];
    __syncthreads();
    for (int e = tid; e < 4096; e += 256) {
        int j = e >> 6, n = e & 63;
        const float* row = xBC + (size_t)(t0 + j) * CONVDIM;
        Bs[j*SMT + n] = row[DINNER + n];
        Ds[j*SMT + n] = dts[j] * row[h*64 + n];
    }
    if (tid < 64) seg[tid] = dts[tid] * A;
    __syncthreads();
    for (int off = 1; off < 64; off <<= 1) {
        float v = 0.f;
        bool act = (tid < 64) && (tid >= off);
        if (act) v = seg[tid - off];
        __syncthreads();
        if (act) seg[tid] += v;
        __syncthreads();
    }
    if (tid < 64) {
        dec[tid] = expf(seg[63] - seg[tid]);
        segout[(size_t)blk * 64 + tid] = seg[tid];
    }
    if (tid == 0) cdout[blk] = expf(seg[63]);
    __syncthreads();

    // attT[j][i] = (i>=j) ? exp(seg[i]-seg[j]) * scoresT[j][i] : 0
    for (int e = tid; e < 4096; e += 256) {
        int j = e >> 6, i = e & 63;
        float v = 0.f;
        if (i >= j) v = expf(seg[i] - seg[j]) * sc[(size_t)bc*4096 + e];
        aT[j*SMT + i] = v;
    }
    __syncthreads();

    int tx = tid & 15, ty = tid >> 4;
    // ---- y[i][p] = sum_j att[i][j] * dtx[j][p]
    float acc2[4][4] = {};
    #pragma unroll 4
    for (int j = 0; j < 64; j++) {
        float4 a4 = *(const float4*)&aT[j*SMT + ty*4];
        float4 b4 = *(const float4*)&Ds[j*SMT + tx*4];
        float a[4] = {a4.x,a4.y,a4.z,a4.w};
        float b[4] = {b4.x,b4.y,b4.z,b4.w};
        #pragma unroll
        for (int r = 0; r < 4; r++)
            #pragma unroll
            for (int s = 0; s < 4; s++) acc2[r][s] += a[r]*b[s];
    }
    float Dh = Dv[h];
    #pragma unroll
    for (int r = 0; r < 4; r++) {
        int i = t0 + ty*4 + r;
        float4 xs = *(const float4*)&xBC[(size_t)i * CONVDIM + h*64 + tx*4];
        float4 o = make_float4(acc2[r][0] + Dh*xs.x, acc2[r][1] + Dh*xs.y,
                               acc2[r][2] + Dh*xs.z, acc2[r][3] + Dh*xs.w);
        *(float4*)&ys[(size_t)i * DINNER + h*64 + tx*4] = o;
    }
    // ---- S[p][n] = sum_j dec[j]*dtx[j][p]*B[j][n]
    float acc3[4][4] = {};
    #pragma unroll 4
    for (int j = 0; j < 64; j++) {
        float dj = dec[j];
        float4 a4 = *(const float4*)&Ds[j*SMT + ty*4];
        float4 b4 = *(const float4*)&Bs[j*SMT + tx*4];
        float a[4] = {a4.x*dj, a4.y*dj, a4.z*dj, a4.w*dj};
        float b[4] = {b4.x,b4.y,b4.z,b4.w};
        #pragma unroll
        for (int r = 0; r < 4; r++)
            #pragma unroll
            for (int s = 0; s < 4; s++) acc3[r][s] += a[r]*b[s];
    }
    #pragma unroll
    for (int r = 0; r < 4; r++)
        *(float4*)&Sg[(size_t)blk * 4096 + (ty*4 + r)*64 + tx*4] =
            make_float4(acc3[r][0], acc3[r][1], acc3[r][2], acc3[r][3]);
}

// ------------------------- inter-chunk scan (8-way partitioned) -------------------------
__global__ __launch_bounds__(256) void ssd_scan8(float* __restrict__ Sg,
                                                 const float* __restrict__ cd)
{
    int blk = blockIdx.x;
    int part = blk & 7;
    int bh = blk >> 3;
    int h = bh % NHEADS, b = bh / NHEADS;
    int tid = threadIdx.x;
    int e0 = part * 512 + tid;
    float st0 = 0.f, st1 = 0.f;
    for (int c = 0; c < NCHUNK; c++) {
        int bidx = (b * NCHUNK + c) * NHEADS + h;
        size_t base = (size_t)bidx * 4096;
        float d = cd[bidx];
        float s0 = Sg[base + e0];
        float s1 = Sg[base + e0 + 256];
        Sg[base + e0]       = st0;
        Sg[base + e0 + 256] = st1;
        st0 = st0 * d + s0;
        st1 = st1 * d + s1;
    }
}

// ------------------------- y_inter accumulation (float4 operands) -------------------------
__global__ __launch_bounds__(256) void ssd_inter(
    const float* __restrict__ xBC, const float* __restrict__ Sg,
    const float* __restrict__ segin, float* __restrict__ ys)
{
    __shared__ float CsT[64*SMT];   // [n][i]
    __shared__ float HsT[64*SMT];   // [n][p]
    __shared__ float seg[64];
    int blk = blockIdx.x;
    int h = blk % NHEADS;
    int bc = blk / NHEADS;
    int t0 = bc * 64;
    int tid = threadIdx.x;
    for (int e = tid; e < 4096; e += 256) {
        int j = e >> 6, n = e & 63;
        CsT[n*SMT + j] = xBC[(size_t)(t0 + j) * CONVDIM + DINNER + DSTATE + n];
        HsT[n*SMT + j] = Sg[(size_t)blk * 4096 + j*64 + n];
    }
    if (tid < 64) seg[tid] = segin[(size_t)blk * 64 + tid];
    __syncthreads();
    int tx = tid & 15, ty = tid >> 4;
    float acc[4][4] = {};
    #pragma unroll 4
    for (int n = 0; n < 64; n++) {
        float4 a4 = *(const float4*)&CsT[n*SMT + ty*4];
        float4 b4 = *(const float4*)&HsT[n*SMT + tx*4];
        float a[4] = {a4.x,a4.y,a4.z,a4.w};
        float b[4] = {b4.x,b4.y,b4.z,b4.w};
        #pragma unroll
        for (int r = 0; r < 4; r++)
            #pragma unroll
            for (int s = 0; s < 4; s++) acc[r][s] += a[r]*b[s];
    }
    #pragma unroll
    for (int r = 0; r < 4; r++) {
        float ei = expf(seg[ty*4 + r]);
        size_t idx = (size_t)(t0 + ty*4 + r) * DINNER + h*64 + tx*4;
        float4 cur = *(const float4*)&ys[idx];
        cur.x += acc[r][0] * ei;
        cur.y += acc[r][1] * ei;
        cur.z += acc[r][2] * ei;
        cur.w += acc[r][3] * ei;
        *(float4*)&ys[idx] = cur;
    }
}

// ------------------------- gating + RMSNorm (writes fp16 split) -------------------------
__global__ __launch_bounds__(256) void gate_rms(
    const float* __restrict__ ys, const float* __restrict__ zx,
    const float* __restrict__ nw,
    __half* __restrict__ ohi, __half* __restrict__ olo)
{
    __shared__ float red[32];
    int t = blockIdx.x, tid = threadIdx.x;
    float v[6];
    float ss = 0.f;
    #pragma unroll
    for (int r = 0; r < 6; r++) {
        int i = tid + r*256;
        float z = zx[(size_t)t * DINPROJ + i];
        float val = ys[(size_t)t * DINNER + i] * (z / (1.f + expf(-z)));
        v[r] = val;
        ss += val*val;
    }
    ss = blockReduceSum(ss, red);
    float sc = rsqrtf(ss / (float)DINNER + 1e-5f);
    #pragma unroll
    for (int r = 0; r < 6; r++) {
        int i = tid + r*256;
        float val = v[r] * sc * nw[i];
        __half hi, lo;
        split1(val, hi, lo);
        size_t idx = (size_t)t * DINNER + i;
        ohi[idx] = hi;
        olo[idx] = lo;
    }
}

// ------------------------- residual + layernorm (writes h + fp16 split) -------------------------
__global__ __launch_bounds__(256) void resid_ln(
    const float* __restrict__ y2, float* __restrict__ hio,
    const float* __restrict__ w, const float* __restrict__ b,
    __half* __restrict__ ohi, __half* __restrict__ olo)
{
    __shared__ float red[32];
    int t = blockIdx.x, tid = threadIdx.x;
    float v[3];
    float s = 0.f;
    #pragma unroll
    for (int r = 0; r < 3; r++) {
        int i = tid + r*256;
        v[r] = y2[(size_t)t * DMODEL + i] + hio[(size_t)t * DMODEL + i];
        s += v[r];
    }
    s = blockReduceSum(s, red);
    float mean = s / (float)DMODEL;
    float q = 0.f;
    #pragma unroll
    for (int r = 0; r < 3; r++) { v[r] -= mean; q += v[r]*v[r]; }
    q = blockReduceSum(q, red);
    float inv = rsqrtf(q / (float)DMODEL + 1e-5f);
    #pragma unroll
    for (int r = 0; r < 3; r++) {
        int i = tid + r*256;
        float val = v[r] * inv * w[i] + b[i];
        size_t idx = (size_t)t * DMODEL + i;
        hio[idx] = val;
        __half hi, lo;
        split1(val, hi, lo);
        ohi[idx] = hi;
        olo[idx] = lo;
    }
}

// ------------------------- final layernorm + logits -------------------------
__global__ __launch_bounds__(256) void head_kernel(
    const float* __restrict__ hin,
    const float* __restrict__ fw, const float* __restrict__ fb,
    const float* __restrict__ lw, const float* __restrict__ lb,
    float* __restrict__ out)
{
    __shared__ float red[32];
    __shared__ float buf[DMODEL];
    int t = blockIdx.x, tid = threadIdx.x;
    float v[3];
    float s = 0.f;
    #pragma unroll
    for (int r = 0; r < 3; r++) {
        int i = tid + r*256;
        v[r] = hin[(size_t)t * DMODEL + i];
        s += v[r];
    }
    s = blockReduceSum(s, red);
    float mean = s / (float)DMODEL;
    float q = 0.f;
    #pragma unroll
    for (int r = 0; r < 3; r++) { v[r] -= mean; q += v[r]*v[r]; }
    q = blockReduceSum(q, red);
    float inv = rsqrtf(q / (float)DMODEL + 1e-5f);
    #pragma unroll
    for (int r = 0; r < 3; r++) {
        int i = tid + r*256;
        buf[i] = v[r] * inv * fw[i] + fb[i];
    }
    __syncthreads();
    for (int cls = 0; cls < 10; cls++) {
        float p = 0.f;
        #pragma unroll
        for (int r = 0; r < 3; r++) {
            int i = tid + r*256;
            p += buf[i] * lw[(size_t)cls * DMODEL + i];
        }
        p = blockReduceSum(p, red);
        if (tid == 0) out[(size_t)t * 10 + cls] = p + lb[cls];
    }
}

// ------------------------- launch -------------------------
extern "C" void kernel_launch(void* const* d_in, const int* in_sizes, int n_in,
                              void* d_out, int out_size)
{
    const float* x       = (const float*)d_in[0];
    const float* pc_w    = (const float*)d_in[1];
    const float* pc_b    = (const float*)d_in[2];
    const float* c1_w    = (const float*)d_in[3];
    const float* c1_b    = (const float*)d_in[4];
    const float* c2_w    = (const float*)d_in[5];
    const float* c2_b    = (const float*)d_in[6];
    const float* c3_w    = (const float*)d_in[7];
    const float* c3_b    = (const float*)d_in[8];
    const float* in_proj = (const float*)d_in[9];
    const float* conv_w  = (const float*)d_in[10];
    const float* conv_b  = (const float*)d_in[11];
    const float* dt_bias = (const float*)d_in[12];
    const float* A_log   = (const float*)d_in[13];
    const float* Dvec    = (const float*)d_in[14];
    const float* norm_w  = (const float*)d_in[15];
    const float* out_proj= (const float*)d_in[16];
    const float* ln_w    = (const float*)d_in[17];
    const float* ln_b    = (const float*)d_in[18];
    const float* fn_w    = (const float*)d_in[19];
    const float* fn_b    = (const float*)d_in[20];
    const float* lo_w    = (const float*)d_in[21];
    const float* lo_b    = (const float*)d_in[22];
    float* out = (float*)d_out;

    float *hmid, *h, *zx, *xBC, *dtb, *ys, *y2, *S, *segb, *cdb, *scb, *wt;
    __half *ahi, *alo, *hmh, *hml, *wch, *wih, *woh;
    cudaGetSymbolAddress((void**)&hmid, g_hmid);
    cudaGetSymbolAddress((void**)&h,    g_h);
    cudaGetSymbolAddress((void**)&zx,   g_zx);
    cudaGetSymbolAddress((void**)&xBC,  g_xBC);
    cudaGetSymbolAddress((void**)&dtb,  g_dt);
    cudaGetSymbolAddress((void**)&ys,   g_ys);
    cudaGetSymbolAddress((void**)&y2,   g_y2);
    cudaGetSymbolAddress((void**)&S,    g_S);
    cudaGetSymbolAddress((void**)&segb, g_seg);
    cudaGetSymbolAddress((void**)&cdb,  g_cd);
    cudaGetSymbolAddress((void**)&scb,  g_sc);
    cudaGetSymbolAddress((void**)&wt,   g_wt);
    cudaGetSymbolAddress((void**)&ahi,  g_ahi);
    cudaGetSymbolAddress((void**)&alo,  g_alo);
    cudaGetSymbolAddress((void**)&hmh,  g_hmh);
    cudaGetSymbolAddress((void**)&hml,  g_hml);
    cudaGetSymbolAddress((void**)&wch,  g_wch);
    cudaGetSymbolAddress((void**)&wih,  g_wih);
    cudaGetSymbolAddress((void**)&woh,  g_woh);

    const int SSD_SMEM = (3 * 64 * SMT + 3 * 64) * (int)sizeof(float);  // 52992
    cudaFuncSetAttribute(ssd_heads, cudaFuncAttributeMaxDynamicSharedMemorySize, SSD_SMEM);
    const int MG_SMEM = 2 * MG_STAGE;   // 40960
    cudaFuncSetAttribute(mma_gemm, cudaFuncAttributeMaxDynamicSharedMemorySize, MG_SMEM);
    cudaFuncSetAttribute(mma_conv<3>,  cudaFuncAttributeMaxDynamicSharedMemorySize, MG_SMEM);
    cudaFuncSetAttribute(mma_conv<9>,  cudaFuncAttributeMaxDynamicSharedMemorySize, MG_SMEM);
    cudaFuncSetAttribute(mma_conv<27>, cudaFuncAttributeMaxDynamicSharedMemorySize, MG_SMEM);

    // ---- front ----
    gemm128_nt<<<dim3(1, NTOK/128), 256>>>(x, pc_w, hmid, 128, 64, pc_b, hmh, hml);
    transpose_wc<<<(256*384  + 255)/256, 256>>>(c1_w, wt,           3);
    transpose_wc<<<(256*1152 + 255)/256, 256>>>(c2_w, wt + 98304,   9);
    transpose_wc<<<(256*3456 + 255)/256, 256>>>(c3_w, wt + 393216, 27);
    to_half<<<(1277952/4 + 255)/256, 256>>>((const float4*)wt, wch, 1277952/4);
    mma_conv<3> <<<dim3(2, NTOK/64), 128, MG_SMEM>>>(hmh, hml, wch,          c1_b, h, ahi, alo, 0);
    mma_conv<9> <<<dim3(2, NTOK/64), 128, MG_SMEM>>>(hmh, hml, wch + 98304,  c2_b, h, ahi, alo, 256);
    mma_conv<27><<<dim3(2, NTOK/64), 128, MG_SMEM>>>(hmh, hml, wch + 393216, c3_b, h, ahi, alo, 512);

    // ---- weight fp16 conversion ----
    {
        int n4 = 4 * DINPROJ * DMODEL / 4;
        to_half<<<(n4 + 255)/256, 256>>>((const float4*)in_proj, wih, n4);
        int m4 = 4 * DMODEL * DINNER / 4;
        to_half<<<(m4 + 255)/256, 256>>>((const float4*)out_proj, woh, m4);
    }

    // ---- layers ----
    for (int l = 0; l < 4; l++) {
        mma_gemm<<<dim3((DINPROJ + 127)/128, NTOK/64), 128, MG_SMEM>>>(
            ahi, alo, wih + (size_t)l * DINPROJ * DMODEL,
            zx, DINPROJ, DMODEL);
        dt_softplus<<<(NTOK*NHEADS + 255)/256, 256>>>(zx, dt_bias + l*NHEADS, dtb);
        dwconv4<<<dim3((CONVDIM + 255)/256, NTOK/4), 256>>>(
            zx, conv_w + (size_t)l * CONVDIM * 4, conv_b + (size_t)l * CONVDIM, xBC);
        ssd_scores<<<NBC, 256>>>(xBC, scb);
        ssd_heads<<<NBLK_SSD, 256, SSD_SMEM>>>(
            xBC, dtb, scb, A_log + l*NHEADS, Dvec + l*NHEADS, ys, S, segb, cdb);
        ssd_scan8<<<8*NHEADS*8, 256>>>(S, cdb);
        ssd_inter<<<NBLK_SSD, 256>>>(xBC, S, segb, ys);
        gate_rms<<<NTOK, 256>>>(ys, zx, norm_w + (size_t)l * DINNER, ahi, alo);
        mma_gemm<<<dim3(DMODEL/128, NTOK/64), 128, MG_SMEM>>>(
            ahi, alo, woh + (size_t)l * DMODEL * DINNER,
            y2, DMODEL, DINNER);
        resid_ln<<<NTOK, 256>>>(y2, h, ln_w + (size_t)l * DMODEL, ln_b + (size_t)l * DMODEL,
                                ahi, alo);
    }

    // ---- head ----
    head_kernel<<<NTOK, 256>>>(h, fn_w, fn_b, lo_w, lo_b, out);
    (void)in_sizes; (void)n_in; (void)out_size;
}

// round 11
// speedup vs baseline: 1.8329x; 1.0051x over previous
#include <cuda_runtime.h>
#include <cuda_fp16.h>
#include <cstdint>
#include <math.h>

#define NTOK   16384
#define TLEN   2048
#define DMODEL 768
#define DINNER 1536
#define DSTATE 64
#define NHEADS 24
#define CONVDIM 1664
#define DINPROJ 3224
#define NCHUNK 32
#define NBC    256
#define NBLK_SSD (NBC*NHEADS)
#define SMT 68

// ------------------------- scratch (device globals) -------------------------
__device__ float g_hmid[(size_t)NTOK*128];
__device__ float g_h   [(size_t)NTOK*DMODEL];
__device__ float g_zx  [(size_t)NTOK*DINPROJ];
__device__ float g_xBC [(size_t)NTOK*CONVDIM];
__device__ float g_dt  [(size_t)NTOK*NHEADS];
__device__ float g_ys  [(size_t)NTOK*DINNER];
__device__ float g_y2  [(size_t)NTOK*DMODEL];
__device__ float g_S   [(size_t)NBLK_SSD*4096];
__device__ float g_seg [(size_t)NBLK_SSD*64];
__device__ float g_cd  [NBLK_SSD];
__device__ float g_sc  [(size_t)NBC*4096];
__device__ float g_wt  [(size_t)(3+9+27)*128*256];
__device__ __half g_ahi[(size_t)NTOK*DINNER];
__device__ __half g_alo[(size_t)NTOK*DINNER];
__device__ __half g_hmh[(size_t)NTOK*128];
__device__ __half g_hml[(size_t)NTOK*128];
__device__ __half g_wch[(size_t)(3+9+27)*128*256];
__device__ __half g_wih[(size_t)4*DINPROJ*DMODEL];
__device__ __half g_woh[(size_t)4*DMODEL*DINNER];

// ------------------------- PTX helpers -------------------------
__device__ __forceinline__ uint32_t smem_u32(const void* p) {
    uint32_t a;
    asm("{ .reg .u64 t; cvta.to.shared.u64 t, %1; cvt.u32.u64 %0, t; }" : "=r"(a) : "l"(p));
    return a;
}
__device__ __forceinline__ void cp16z(uint32_t dst, const void* src, int srcsz) {
    asm volatile("cp.async.cg.shared.global [%0], [%1], 16, %2;" :: "r"(dst), "l"(src), "r"(srcsz));
}
__device__ __forceinline__ void ldsm4(uint32_t* r, uint32_t addr) {
    asm volatile("ldmatrix.sync.aligned.m8n8.x4.shared.b16 {%0,%1,%2,%3}, [%4];"
        : "=r"(r[0]), "=r"(r[1]), "=r"(r[2]), "=r"(r[3]) : "r"(addr));
}
__device__ __forceinline__ void mma16816(float* c, const uint32_t* a, const uint32_t* b) {
    asm volatile("mma.sync.aligned.m16n8k16.row.col.f32.f16.f16.f32 "
        "{%0,%1,%2,%3}, {%4,%5,%6,%7}, {%8,%9}, {%0,%1,%2,%3};"
        : "+f"(c[0]), "+f"(c[1]), "+f"(c[2]), "+f"(c[3])
        : "r"(a[0]), "r"(a[1]), "r"(a[2]), "r"(a[3]), "r"(b[0]), "r"(b[1]));
}
__device__ __forceinline__ void split1(float v, __half& hi, __half& lo) {
    hi = __float2half_rn(v);
    lo = __float2half_rn(v - __half2float(hi));
}
__device__ __forceinline__ uint32_t pack2(__half a, __half b) {
    return (uint32_t)__half_as_ushort(a) | ((uint32_t)__half_as_ushort(b) << 16);
}

// block reduce, NW warps (NW <= 32)
template<int NW>
__device__ __forceinline__ float blockReduceSumT(float v, float* red) {
    int tid = threadIdx.x;
    #pragma unroll
    for (int o = 16; o; o >>= 1) v += __shfl_xor_sync(0xffffffffu, v, o);
    if ((tid & 31) == 0) red[tid >> 5] = v;
    __syncthreads();
    if (tid < 32) {
        float w = (tid < NW) ? red[tid] : 0.f;
        #pragma unroll
        for (int o = 16; o; o >>= 1) w += __shfl_xor_sync(0xffffffffu, w, o);
        if (tid == 0) red[0] = w;
    }
    __syncthreads();
    float r0 = red[0];
    __syncthreads();
    return r0;
}

// ------------------------- split fp32 -> fp16 hi/lo -------------------------
__global__ void split_half(const float4* __restrict__ src,
                           __half* __restrict__ hi,
                           __half* __restrict__ lo, int n4)
{
    int i = blockIdx.x * 256 + threadIdx.x;
    if (i >= n4) return;
    float4 v = src[i];
    float vv[4] = {v.x, v.y, v.z, v.w};
    __half h4[4], l4[4];
    #pragma unroll
    for (int j = 0; j < 4; j++) split1(vv[j], h4[j], l4[j]);
    uint2 hp = make_uint2(pack2(h4[0], h4[1]), pack2(h4[2], h4[3]));
    uint2 lp = make_uint2(pack2(l4[0], l4[1]), pack2(l4[2], l4[3]));
    *reinterpret_cast<uint2*>(hi + (size_t)i * 4) = hp;
    *reinterpret_cast<uint2*>(lo + (size_t)i * 4) = lp;
}

// ------------------------- convert fp32 -> fp16 (weights) -------------------------
__global__ void to_half(const float4* __restrict__ src, __half* __restrict__ dst, int n4)
{
    int i = blockIdx.x * 256 + threadIdx.x;
    if (i >= n4) return;
    float4 v = src[i];
    uint2 hp = make_uint2(pack2(__float2half_rn(v.x), __float2half_rn(v.y)),
                          pack2(__float2half_rn(v.z), __float2half_rn(v.w)));
    *reinterpret_cast<uint2*>(dst + (size_t)i * 4) = hp;
}

// ------------------------- 2-term split-fp16 NT GEMM, 64x128 tile, 3-stage -------------------------
#define MG_PITCH 80
#define MG_AMAT  5120
#define MG_BBASE 10240
#define MG_STAGE 20480

__device__ __forceinline__ void mg_load(
    uint32_t sbase,
    const __half* __restrict__ Ah, const __half* __restrict__ Al,
    const __half* __restrict__ B,
    int m0, int n0, int Ntot, int K, int c, int tid)
{
    #pragma unroll
    for (int j = 0; j < 4; j++) {
        int e = tid + j * 128;
        int seg = e & 3, r = (e >> 2) & 63, mat = e >> 8;
        uint32_t soff = (uint32_t)(mat * MG_AMAT + r * MG_PITCH + seg * 16);
        const __half* src = (mat ? Al : Ah) + (size_t)(m0 + r) * K + (size_t)c * 32 + seg * 8;
        cp16z(sbase + soff, src, 16);
    }
    #pragma unroll
    for (int j = 0; j < 4; j++) {
        int e = tid + j * 128;
        int seg = e & 3, r = e >> 2;
        uint32_t soff = (uint32_t)(MG_BBASE + r * MG_PITCH + seg * 16);
        int nr = n0 + r;
        int sz = (nr < Ntot) ? 16 : 0;
        int nrc = (nr < Ntot) ? nr : 0;
        const __half* src = B + (size_t)nrc * K + (size_t)c * 32 + seg * 8;
        cp16z(sbase + soff, src, sz);
    }
    asm volatile("cp.async.commit_group;" ::: "memory");
}

__global__ __launch_bounds__(128, 3) void mma_gemm(
    const __half* __restrict__ Ah, const __half* __restrict__ Al,
    const __half* __restrict__ B,
    float* __restrict__ C, int Ntot, int K)
{
    extern __shared__ char smem[];
    uint32_t sb = smem_u32(smem);
    int tid = threadIdx.x, wid = tid >> 5, lane = tid & 31;
    int m0 = blockIdx.y * 64, n0 = blockIdx.x * 128;
    int wm = (wid >> 1) * 32;
    int wn = (wid & 1) * 64;

    float acc[2][8][4];
    #pragma unroll
    for (int a = 0; a < 2; a++)
        #pragma unroll
        for (int b = 0; b < 8; b++)
            #pragma unroll
            for (int q = 0; q < 4; q++) acc[a][b][q] = 0.f;

    int gr = lane >> 3, lr = lane & 7;
    int arow = (gr & 1) * 8 + lr;
    int acol = (gr >> 1) * 16;
    int brow = (gr >> 1) * 8 + lr;
    int bcol = (gr & 1) * 16;

    int nch = K >> 5;
    mg_load(sb, Ah, Al, B, m0, n0, Ntot, K, 0, tid);
    mg_load(sb + MG_STAGE, Ah, Al, B, m0, n0, Ntot, K, 1, tid);
    int sidx = 0;
    for (int c = 0; c < nch; c++) {
        if (c + 2 < nch) {
            asm volatile("cp.async.wait_group 1;" ::: "memory");
        } else {
            asm volatile("cp.async.wait_group 0;" ::: "memory");
        }
        __syncthreads();
        if (c + 2 < nch) {
            int s2 = sidx + 2; if (s2 >= 3) s2 -= 3;
            mg_load(sb + (uint32_t)s2 * MG_STAGE, Ah, Al, B, m0, n0, Ntot, K, c + 2, tid);
        }
        uint32_t base = sb + (uint32_t)sidx * MG_STAGE;
        #pragma unroll
        for (int ks = 0; ks < 2; ks++) {
            uint32_t ah[2][4], al[2][4];
            #pragma unroll
            for (int mt = 0; mt < 2; mt++) {
                uint32_t off = (uint32_t)((wm + mt*16 + arow) * MG_PITCH + acol + ks*32);
                ldsm4(ah[mt], base + off);
                ldsm4(al[mt], base + MG_AMAT + off);
            }
            #pragma unroll
            for (int np = 0; np < 4; np++) {
                uint32_t bb[4];
                uint32_t off = (uint32_t)(MG_BBASE + (wn + np*16 + brow) * MG_PITCH + bcol + ks*32);
                ldsm4(bb, base + off);
                #pragma unroll
                for (int mt = 0; mt < 2; mt++) {
                    mma16816(acc[mt][2*np],   ah[mt], &bb[0]);
                    mma16816(acc[mt][2*np+1], ah[mt], &bb[2]);
                    mma16816(acc[mt][2*np],   al[mt], &bb[0]);
                    mma16816(acc[mt][2*np+1], al[mt], &bb[2]);
                }
            }
        }
        if (++sidx == 3) sidx = 0;
    }

    int r4 = lane >> 2, c2 = (lane & 3) * 2;
    #pragma unroll
    for (int mt = 0; mt < 2; mt++) {
        int r = m0 + wm + mt*16 + r4;
        #pragma unroll
        for (int nt = 0; nt < 8; nt++) {
            int col = n0 + wn + nt*8 + c2;
            if (col < Ntot) {
                float* cc = acc[mt][nt];
                *(float2*)&C[(size_t)r * Ntot + col]       = make_float2(cc[0], cc[1]);
                *(float2*)&C[(size_t)(r + 8) * Ntot + col] = make_float2(cc[2], cc[3]);
            }
        }
    }
}

// ------------------------- 2-term mma conv (implicit im2col), 64x128 tile, 3-stage ----------------
template<int KTAP>
__device__ __forceinline__ void mg_load_conv(
    uint32_t sbase,
    const __half* __restrict__ Ah, const __half* __restrict__ Al,
    const __half* __restrict__ B,
    int m0, int n0, int c, int tid)
{
    const int PAD = KTAP / 2;
    const int K = KTAP * 128;
    int tap = c >> 2;
    int ch0 = (c & 3) * 32;
    #pragma unroll
    for (int j = 0; j < 4; j++) {
        int e = tid + j * 128;
        int seg = e & 3, r = (e >> 2) & 63, mat = e >> 8;
        uint32_t soff = (uint32_t)(mat * MG_AMAT + r * MG_PITCH + seg * 16);
        int tg = m0 + r;
        int tsrc = (tg & (TLEN - 1)) + tap - PAD;
        int valid = (tsrc >= 0 && tsrc < TLEN);
        size_t gidx = valid ? ((size_t)(tg + tap - PAD) * 128 + ch0 + seg * 8) : 0;
        const __half* src = (mat ? Al : Ah) + gidx;
        cp16z(sbase + soff, src, valid ? 16 : 0);
    }
    #pragma unroll
    for (int j = 0; j < 4; j++) {
        int e = tid + j * 128;
        int seg = e & 3, r = e >> 2;
        uint32_t soff = (uint32_t)(MG_BBASE + r * MG_PITCH + seg * 16);
        const __half* src = B + (size_t)(n0 + r) * K + (size_t)c * 32 + seg * 8;
        cp16z(sbase + soff, src, 16);
    }
    asm volatile("cp.async.commit_group;" ::: "memory");
}

template<int KTAP>
__global__ __launch_bounds__(128, 3) void mma_conv(
    const __half* __restrict__ Ah, const __half* __restrict__ Al,
    const __half* __restrict__ B,
    const float* __restrict__ bias, float* __restrict__ Hout,
    __half* __restrict__ ohi, __half* __restrict__ olo, int colofs)
{
    extern __shared__ char smem[];
    uint32_t sb = smem_u32(smem);
    int tid = threadIdx.x, wid = tid >> 5, lane = tid & 31;
    int m0 = blockIdx.y * 64, n0 = blockIdx.x * 128;
    int wm = (wid >> 1) * 32;
    int wn = (wid & 1) * 64;

    float acc[2][8][4];
    #pragma unroll
    for (int a = 0; a < 2; a++)
        #pragma unroll
        for (int b = 0; b < 8; b++)
            #pragma unroll
            for (int q = 0; q < 4; q++) acc[a][b][q] = 0.f;

    int gr = lane >> 3, lr = lane & 7;
    int arow = (gr & 1) * 8 + lr;
    int acol = (gr >> 1) * 16;
    int brow = (gr >> 1) * 8 + lr;
    int bcol = (gr & 1) * 16;

    const int nch = KTAP * 4;
    mg_load_conv<KTAP>(sb, Ah, Al, B, m0, n0, 0, tid);
    mg_load_conv<KTAP>(sb + MG_STAGE, Ah, Al, B, m0, n0, 1, tid);
    int sidx = 0;
    for (int c = 0; c < nch; c++) {
        if (c + 2 < nch) {
            asm volatile("cp.async.wait_group 1;" ::: "memory");
        } else {
            asm volatile("cp.async.wait_group 0;" ::: "memory");
        }
        __syncthreads();
        if (c + 2 < nch) {
            int s2 = sidx + 2; if (s2 >= 3) s2 -= 3;
            mg_load_conv<KTAP>(sb + (uint32_t)s2 * MG_STAGE, Ah, Al, B, m0, n0, c + 2, tid);
        }
        uint32_t base = sb + (uint32_t)sidx * MG_STAGE;
        #pragma unroll
        for (int ks = 0; ks < 2; ks++) {
            uint32_t ah[2][4], al[2][4];
            #pragma unroll
            for (int mt = 0; mt < 2; mt++) {
                uint32_t off = (uint32_t)((wm + mt*16 + arow) * MG_PITCH + acol + ks*32);
                ldsm4(ah[mt], base + off);
                ldsm4(al[mt], base + MG_AMAT + off);
            }
            #pragma unroll
            for (int np = 0; np < 4; np++) {
                uint32_t bb[4];
                uint32_t off = (uint32_t)(MG_BBASE + (wn + np*16 + brow) * MG_PITCH + bcol + ks*32);
                ldsm4(bb, base + off);
                #pragma unroll
                for (int mt = 0; mt < 2; mt++) {
                    mma16816(acc[mt][2*np],   ah[mt], &bb[0]);
                    mma16816(acc[mt][2*np+1], ah[mt], &bb[2]);
                    mma16816(acc[mt][2*np],   al[mt], &bb[0]);
                    mma16816(acc[mt][2*np+1], al[mt], &bb[2]);
                }
            }
        }
        if (++sidx == 3) sidx = 0;
    }

    int r4 = lane >> 2, c2 = (lane & 3) * 2;
    #pragma unroll
    for (int mt = 0; mt < 2; mt++) {
        #pragma unroll
        for (int half = 0; half < 2; half++) {
            int r = m0 + wm + mt*16 + r4 + half*8;
            #pragma unroll
            for (int nt = 0; nt < 8; nt++) {
                int col = n0 + wn + nt*8 + c2;
                float* cc = acc[mt][nt];
                #pragma unroll
                for (int q = 0; q < 2; q++) {
                    float v = cc[half*2 + q] + bias[col + q];
                    v = v / (1.f + expf(-v));
                    size_t idx = (size_t)r * DMODEL + colofs + col + q;
                    Hout[idx] = v;
                    __half hi, lo;
                    split1(v, hi, lo);
                    ohi[idx] = hi;
                    olo[idx] = lo;
                }
            }
        }
    }
}

// ------------------------- front 1x1 conv SGEMM (writes hmid + fp16 split) -------------------------
__global__ __launch_bounds__(256) void gemm128_nt(
    const float* __restrict__ A, const float* __restrict__ B,
    float* __restrict__ C, int N, int K,
    const float* __restrict__ bias,
    __half* __restrict__ ohi, __half* __restrict__ olo)
{
    __shared__ float As[8][128];
    __shared__ float Bs[8][128];
    int m0 = blockIdx.y * 128, n0 = blockIdx.x * 128;
    int tid = threadIdx.x;
    int tx = tid & 15, ty = tid >> 4;
    float acc[8][8] = {};
    int lr = tid >> 1;
    int lk = (tid & 1) * 4;
    const float* Ag = A + (size_t)(m0 + lr) * K + lk;
    const float* Bg = B + (size_t)(n0 + lr) * K + lk;
    bool bvalid = (n0 + lr) < N;
    for (int k0 = 0; k0 < K; k0 += 8) {
        float4 av = *(const float4*)(Ag + k0);
        float4 bv = bvalid ? *(const float4*)(Bg + k0) : make_float4(0.f,0.f,0.f,0.f);
        __syncthreads();
        As[lk+0][lr] = av.x; As[lk+1][lr] = av.y; As[lk+2][lr] = av.z; As[lk+3][lr] = av.w;
        Bs[lk+0][lr] = bv.x; Bs[lk+1][lr] = bv.y; Bs[lk+2][lr] = bv.z; Bs[lk+3][lr] = bv.w;
        __syncthreads();
        #pragma unroll
        for (int kk = 0; kk < 8; kk++) {
            float4 a0 = *(const float4*)&As[kk][ty*8];
            float4 a1 = *(const float4*)&As[kk][ty*8+4];
            float4 b0 = *(const float4*)&Bs[kk][tx*8];
            float4 b1 = *(const float4*)&Bs[kk][tx*8+4];
            float a[8] = {a0.x,a0.y,a0.z,a0.w,a1.x,a1.y,a1.z,a1.w};
            float b[8] = {b0.x,b0.y,b0.z,b0.w,b1.x,b1.y,b1.z,b1.w};
            #pragma unroll
            for (int r = 0; r < 8; r++)
                #pragma unroll
                for (int s = 0; s < 8; s++) acc[r][s] += a[r]*b[s];
        }
    }
    #pragma unroll
    for (int r = 0; r < 8; r++) {
        int m = m0 + ty*8 + r;
        #pragma unroll
        for (int s = 0; s < 8; s++) {
            int n = n0 + tx*8 + s;
            if (n < N) {
                float v = acc[r][s] + bias[n];
                v = v / (1.f + expf(-v));
                size_t idx = (size_t)m * N + n;
                C[idx] = v;
                __half hi, lo;
                split1(v, hi, lo);
                ohi[idx] = hi;
                olo[idx] = lo;
            }
        }
    }
}

// ------------------------- conv weight NT transpose -------------------------
__global__ void transpose_wc(const float* __restrict__ w, float* __restrict__ wt, int KTAP)
{
    int idx = blockIdx.x * 256 + threadIdx.x;
    int K = KTAP * 128;
    int total = 256 * K;
    if (idx >= total) return;
    int o = idx / K;
    int kk = idx - o * K;
    int tap = kk >> 7;
    int i = kk & 127;
    wt[idx] = w[(size_t)o * 128 * KTAP + (size_t)i * KTAP + tap];
}

// ------------------------- dt softplus -------------------------
__global__ void dt_softplus(const float* __restrict__ zx, const float* __restrict__ dtb,
                            float* __restrict__ dt)
{
    int idx = blockIdx.x * 256 + threadIdx.x;
    if (idx >= NTOK * NHEADS) return;
    int t = idx / NHEADS, hh = idx - t * NHEADS;
    float x = zx[(size_t)t * DINPROJ + 3200 + hh] + dtb[hh];
    dt[idx] = (x > 20.f) ? x : log1pf(expf(x));
}

// ------------------------- depthwise causal conv + silu (4 tokens/thread) -------------------------
__global__ void dwconv4(const float* __restrict__ zx, const float* __restrict__ cw,
                        const float* __restrict__ cb, float* __restrict__ xBC)
{
    int c = blockIdx.x * 256 + threadIdx.x;
    if (c >= CONVDIM) return;
    int t0 = blockIdx.y * 4;
    int ti0 = t0 & (TLEN - 1);
    float4 w = *(const float4*)(cw + (size_t)c * 4);
    float bias = cb[c];
    float z[7];
    #pragma unroll
    for (int j = 0; j < 7; j++) {
        int ti = ti0 - 3 + j;
        z[j] = (ti >= 0) ? zx[(size_t)(t0 - 3 + j) * DINPROJ + DINNER + c] : 0.f;
    }
    #pragma unroll
    for (int j = 0; j < 4; j++) {
        float acc = bias + z[j]*w.x + z[j+1]*w.y + z[j+2]*w.z + z[j+3]*w.w;
        xBC[(size_t)(t0 + j) * CONVDIM + c] = acc / (1.f + expf(-acc));
    }
}

// ------------------------- SSD scores (shared across heads) -------------------------
__global__ __launch_bounds__(256) void ssd_scores(
    const float* __restrict__ xBC, float* __restrict__ sc)
{
    __shared__ float BsT[64*SMT];
    __shared__ float CsT[64*SMT];
    int bc = blockIdx.x;
    int t0 = bc * 64;
    int tid = threadIdx.x;
    for (int e = tid; e < 4096; e += 256) {
        int j = e >> 6, n = e & 63;
        const float* row = xBC + (size_t)(t0 + j) * CONVDIM + DINNER;
        BsT[n*SMT + j] = row[n];
        CsT[n*SMT + j] = row[DSTATE + n];
    }
    __syncthreads();
    int tx = tid & 15, ty = tid >> 4;
    float acc[4][4] = {};
    #pragma unroll 4
    for (int n = 0; n < 64; n++) {
        float4 a4 = *(const float4*)&BsT[n*SMT + ty*4];
        float4 b4 = *(const float4*)&CsT[n*SMT + tx*4];
        float a[4] = {a4.x,a4.y,a4.z,a4.w};
        float b[4] = {b4.x,b4.y,b4.z,b4.w};
        #pragma unroll
        for (int r = 0; r < 4; r++)
            #pragma unroll
            for (int s = 0; s < 4; s++) acc[r][s] += a[r]*b[s];
    }
    #pragma unroll
    for (int r = 0; r < 4; r++)
        *(float4*)&sc[(size_t)bc*4096 + (ty*4 + r)*64 + tx*4] =
            make_float4(acc[r][0], acc[r][1], acc[r][2], acc[r][3]);
}

// ------------------------- SSD per-(b,c,h) -------------------------
__global__ __launch_bounds__(256) void ssd_heads(
    const float* __restrict__ xBC, const float* __restrict__ dt,
    const float* __restrict__ sc,
    const float* __restrict__ A_log, const float* __restrict__ Dv,
    float* __restrict__ ys, float* __restrict__ Sg,
    float* __restrict__ segout, float* __restrict__ cdout)
{
    extern __shared__ float sm[];
    float* Bs  = sm;
    float* Ds  = Bs + 64*SMT;
    float* aT  = Ds + 64*SMT;
    float* seg = aT + 64*SMT;
    float* dec = seg + 64;
    float* dts = dec + 64;

    int blk = blockIdx.x;
    int h = blk % NHEADS;
    int bc = blk / NHEADS;
    int t0 = bc * 64;
    int tid = threadIdx.x;
    float A = -expf(A_log[h]);

    if (tid < 64) dts[tid] = dt[(size_t)(t0 + tid) * NHEADS + h];
    __syncthreads();
    for (int e = tid; e < 4096; e += 256) {
        int j = e >> 6, n = e & 63;
        const float* row = xBC + (size_t)(t0 + j) * CONVDIM;
        Bs[j*SMT + n] = row[DINNER + n];
        Ds[j*SMT + n] = dts[j] * row[h*64 + n];
    }
    if (tid < 64) seg[tid] = dts[tid] * A;
    __syncthreads();
    for (int off = 1; off < 64; off <<= 1) {
        float v = 0.f;
        bool act = (tid < 64) && (tid >= off);
        if (act) v = seg[tid - off];
        __syncthreads();
        if (act) seg[tid] += v;
        __syncthreads();
    }
    if (tid < 64) {
        dec[tid] = expf(seg[63] - seg[tid]);
        segout[(size_t)blk * 64 + tid] = seg[tid];
    }
    if (tid == 0) cdout[blk] = expf(seg[63]);
    __syncthreads();

    for (int e = tid; e < 4096; e += 256) {
        int j = e >> 6, i = e & 63;
        float v = 0.f;
        if (i >= j) v = expf(seg[i] - seg[j]) * sc[(size_t)bc*4096 + e];
        aT[j*SMT + i] = v;
    }
    __syncthreads();

    int tx = tid & 15, ty = tid >> 4;
    float acc2[4][4] = {};
    #pragma unroll 4
    for (int j = 0; j < 64; j++) {
        float4 a4 = *(const float4*)&aT[j*SMT + ty*4];
        float4 b4 = *(const float4*)&Ds[j*SMT + tx*4];
        float a[4] = {a4.x,a4.y,a4.z,a4.w};
        float b[4] = {b4.x,b4.y,b4.z,b4.w};
        #pragma unroll
        for (int r = 0; r < 4; r++)
            #pragma unroll
            for (int s = 0; s < 4; s++) acc2[r][s] += a[r]*b[s];
    }
    float Dh = Dv[h];
    #pragma unroll
    for (int r = 0; r < 4; r++) {
        int i = t0 + ty*4 + r;
        float4 xs = *(const float4*)&xBC[(size_t)i * CONVDIM + h*64 + tx*4];
        float4 o = make_float4(acc2[r][0] + Dh*xs.x, acc2[r][1] + Dh*xs.y,
                               acc2[r][2] + Dh*xs.z, acc2[r][3] + Dh*xs.w);
        *(float4*)&ys[(size_t)i * DINNER + h*64 + tx*4] = o;
    }
    float acc3[4][4] = {};
    #pragma unroll 4
    for (int j = 0; j < 64; j++) {
        float dj = dec[j];
        float4 a4 = *(const float4*)&Ds[j*SMT + ty*4];
        float4 b4 = *(const float4*)&Bs[j*SMT + tx*4];
        float a[4] = {a4.x*dj, a4.y*dj, a4.z*dj, a4.w*dj};
        float b[4] = {b4.x,b4.y,b4.z,b4.w};
        #pragma unroll
        for (int r = 0; r < 4; r++)
            #pragma unroll
            for (int s = 0; s < 4; s++) acc3[r][s] += a[r]*b[s];
    }
    #pragma unroll
    for (int r = 0; r < 4; r++)
        *(float4*)&Sg[(size_t)blk * 4096 + (ty*4 + r)*64 + tx*4] =
            make_float4(acc3[r][0], acc3[r][1], acc3[r][2], acc3[r][3]);
}

// ------------------------- inter-chunk scan (8-way partitioned) -------------------------
__global__ __launch_bounds__(256) void ssd_scan8(float* __restrict__ Sg,
                                                 const float* __restrict__ cd)
{
    int blk = blockIdx.x;
    int part = blk & 7;
    int bh = blk >> 3;
    int h = bh % NHEADS, b = bh / NHEADS;
    int tid = threadIdx.x;
    int e0 = part * 512 + tid;
    float st0 = 0.f, st1 = 0.f;
    for (int c = 0; c < NCHUNK; c++) {
        int bidx = (b * NCHUNK + c) * NHEADS + h;
        size_t base = (size_t)bidx * 4096;
        float d = cd[bidx];
        float s0 = Sg[base + e0];
        float s1 = Sg[base + e0 + 256];
        Sg[base + e0]       = st0;
        Sg[base + e0 + 256] = st1;
        st0 = st0 * d + s0;
        st1 = st1 * d + s1;
    }
}

// ------------------------- y_inter accumulation -------------------------
__global__ __launch_bounds__(256) void ssd_inter(
    const float* __restrict__ xBC, const float* __restrict__ Sg,
    const float* __restrict__ segin, float* __restrict__ ys)
{
    __shared__ float CsT[64*SMT];
    __shared__ float HsT[64*SMT];
    __shared__ float seg[64];
    int blk = blockIdx.x;
    int h = blk % NHEADS;
    int bc = blk / NHEADS;
    int t0 = bc * 64;
    int tid = threadIdx.x;
    for (int e = tid; e < 4096; e += 256) {
        int j = e >> 6, n = e & 63;
        CsT[n*SMT + j] = xBC[(size_t)(t0 + j) * CONVDIM + DINNER + DSTATE + n];
        HsT[n*SMT + j] = Sg[(size_t)blk * 4096 + j*64 + n];
    }
    if (tid < 64) seg[tid] = segin[(size_t)blk * 64 + tid];
    __syncthreads();
    int tx = tid & 15, ty = tid >> 4;
    float acc[4][4] = {};
    #pragma unroll 4
    for (int n = 0; n < 64; n++) {
        float4 a4 = *(const float4*)&CsT[n*SMT + ty*4];
        float4 b4 = *(const float4*)&HsT[n*SMT + tx*4];
        float a[4] = {a4.x,a4.y,a4.z,a4.w};
        float b[4] = {b4.x,b4.y,b4.z,b4.w};
        #pragma unroll
        for (int r = 0; r < 4; r++)
            #pragma unroll
            for (int s = 0; s < 4; s++) acc[r][s] += a[r]*b[s];
    }
    #pragma unroll
    for (int r = 0; r < 4; r++) {
        float ei = expf(seg[ty*4 + r]);
        size_t idx = (size_t)(t0 + ty*4 + r) * DINNER + h*64 + tx*4;
        float4 cur = *(const float4*)&ys[idx];
        cur.x += acc[r][0] * ei;
        cur.y += acc[r][1] * ei;
        cur.z += acc[r][2] * ei;
        cur.w += acc[r][3] * ei;
        *(float4*)&ys[idx] = cur;
    }
}

// ------------------------- gating + RMSNorm (float4, 128 thr, writes fp16 split) ------------------
__global__ __launch_bounds__(128) void gate_rms(
    const float* __restrict__ ys, const float* __restrict__ zx,
    const float* __restrict__ nw,
    __half* __restrict__ ohi, __half* __restrict__ olo)
{
    __shared__ float red[32];
    int t = blockIdx.x, tid = threadIdx.x;
    float4 v[3];
    float ss = 0.f;
    #pragma unroll
    for (int r = 0; r < 3; r++) {
        int i = (tid + r*128) * 4;
        float4 yv = *(const float4*)&ys[(size_t)t * DINNER + i];
        float4 zv = *(const float4*)&zx[(size_t)t * DINPROJ + i];
        float4 val;
        val.x = yv.x * (zv.x / (1.f + expf(-zv.x)));
        val.y = yv.y * (zv.y / (1.f + expf(-zv.y)));
        val.z = yv.z * (zv.z / (1.f + expf(-zv.z)));
        val.w = yv.w * (zv.w / (1.f + expf(-zv.w)));
        v[r] = val;
        ss += val.x*val.x + val.y*val.y + val.z*val.z + val.w*val.w;
    }
    ss = blockReduceSumT<4>(ss, red);
    float sc = rsqrtf(ss / (float)DINNER + 1e-5f);
    #pragma unroll
    for (int r = 0; r < 3; r++) {
        int i = (tid + r*128) * 4;
        float4 wv = *(const float4*)&nw[i];
        __half h4[4], l4[4];
        split1(v[r].x * sc * wv.x, h4[0], l4[0]);
        split1(v[r].y * sc * wv.y, h4[1], l4[1]);
        split1(v[r].z * sc * wv.z, h4[2], l4[2]);
        split1(v[r].w * sc * wv.w, h4[3], l4[3]);
        size_t idx = (size_t)t * DINNER + i;
        *reinterpret_cast<uint2*>(ohi + idx) = make_uint2(pack2(h4[0], h4[1]), pack2(h4[2], h4[3]));
        *reinterpret_cast<uint2*>(olo + idx) = make_uint2(pack2(l4[0], l4[1]), pack2(l4[2], l4[3]));
    }
}

// ------------------------- residual + layernorm (float4, 192 thr, writes h + split) ---------------
__global__ __launch_bounds__(192) void resid_ln(
    const float* __restrict__ y2, float* __restrict__ hio,
    const float* __restrict__ w, const float* __restrict__ b,
    __half* __restrict__ ohi, __half* __restrict__ olo)
{
    __shared__ float red[32];
    int t = blockIdx.x, tid = threadIdx.x;
    int i = tid * 4;
    float4 a = *(const float4*)&y2[(size_t)t * DMODEL + i];
    float4 hh = *(const float4*)&hio[(size_t)t * DMODEL + i];
    float4 v = make_float4(a.x + hh.x, a.y + hh.y, a.z + hh.z, a.w + hh.w);
    float s = v.x + v.y + v.z + v.w;
    s = blockReduceSumT<6>(s, red);
    float mean = s / (float)DMODEL;
    v.x -= mean; v.y -= mean; v.z -= mean; v.w -= mean;
    float q = v.x*v.x + v.y*v.y + v.z*v.z + v.w*v.w;
    q = blockReduceSumT<6>(q, red);
    float inv = rsqrtf(q / (float)DMODEL + 1e-5f);
    float4 wv = *(const float4*)&w[i];
    float4 bv = *(const float4*)&b[i];
    float4 val = make_float4(v.x*inv*wv.x + bv.x, v.y*inv*wv.y + bv.y,
                             v.z*inv*wv.z + bv.z, v.w*inv*wv.w + bv.w);
    size_t idx = (size_t)t * DMODEL + i;
    *(float4*)&hio[idx] = val;
    __half h4[4], l4[4];
    split1(val.x, h4[0], l4[0]);
    split1(val.y, h4[1], l4[1]);
    split1(val.z, h4[2], l4[2]);
    split1(val.w, h4[3], l4[3]);
    *reinterpret_cast<uint2*>(ohi + idx) = make_uint2(pack2(h4[0], h4[1]), pack2(h4[2], h4[3]));
    *reinterpret_cast<uint2*>(olo + idx) = make_uint2(pack2(l4[0], l4[1]), pack2(l4[2], l4[3]));
}

// ------------------------- final layernorm + logits -------------------------
__global__ __launch_bounds__(256) void head_kernel(
    const float* __restrict__ hin,
    const float* __restrict__ fw, const float* __restrict__ fb,
    const float* __restrict__ lw, const float* __restrict__ lb,
    float* __restrict__ out)
{
    __shared__ float red[32];
    __shared__ float buf[DMODEL];
    int t = blockIdx.x, tid = threadIdx.x;
    float v[3];
    float s = 0.f;
    #pragma unroll
    for (int r = 0; r < 3; r++) {
        int i = tid + r*256;
        v[r] = hin[(size_t)t * DMODEL + i];
        s += v[r];
    }
    s = blockReduceSumT<8>(s, red);
    float mean = s / (float)DMODEL;
    float q = 0.f;
    #pragma unroll
    for (int r = 0; r < 3; r++) { v[r] -= mean; q += v[r]*v[r]; }
    q = blockReduceSumT<8>(q, red);
    float inv = rsqrtf(q / (float)DMODEL + 1e-5f);
    #pragma unroll
    for (int r = 0; r < 3; r++) {
        int i = tid + r*256;
        buf[i] = v[r] * inv * fw[i] + fb[i];
    }
    __syncthreads();
    for (int cls = 0; cls < 10; cls++) {
        float p = 0.f;
        #pragma unroll
        for (int r = 0; r < 3; r++) {
            int i = tid + r*256;
            p += buf[i] * lw[(size_t)cls * DMODEL + i];
        }
        p = blockReduceSumT<8>(p, red);
        if (tid == 0) out[(size_t)t * 10 + cls] = p + lb[cls];
    }
}

// ------------------------- launch -------------------------
extern "C" void kernel_launch(void* const* d_in, const int* in_sizes, int n_in,
                              void* d_out, int out_size)
{
    const float* x       = (const float*)d_in[0];
    const float* pc_w    = (const float*)d_in[1];
    const float* pc_b    = (const float*)d_in[2];
    const float* c1_w    = (const float*)d_in[3];
    const float* c1_b    = (const float*)d_in[4];
    const float* c2_w    = (const float*)d_in[5];
    const float* c2_b    = (const float*)d_in[6];
    const float* c3_w    = (const float*)d_in[7];
    const float* c3_b    = (const float*)d_in[8];
    const float* in_proj = (const float*)d_in[9];
    const float* conv_w  = (const float*)d_in[10];
    const float* conv_b  = (const float*)d_in[11];
    const float* dt_bias = (const float*)d_in[12];
    const float* A_log   = (const float*)d_in[13];
    const float* Dvec    = (const float*)d_in[14];
    const float* norm_w  = (const float*)d_in[15];
    const float* out_proj= (const float*)d_in[16];
    const float* ln_w    = (const float*)d_in[17];
    const float* ln_b    = (const float*)d_in[18];
    const float* fn_w    = (const float*)d_in[19];
    const float* fn_b    = (const float*)d_in[20];
    const float* lo_w    = (const float*)d_in[21];
    const float* lo_b    = (const float*)d_in[22];
    float* out = (float*)d_out;

    float *hmid, *h, *zx, *xBC, *dtb, *ys, *y2, *S, *segb, *cdb, *scb, *wt;
    __half *ahi, *alo, *hmh, *hml, *wch, *wih, *woh;
    cudaGetSymbolAddress((void**)&hmid, g_hmid);
    cudaGetSymbolAddress((void**)&h,    g_h);
    cudaGetSymbolAddress((void**)&zx,   g_zx);
    cudaGetSymbolAddress((void**)&xBC,  g_xBC);
    cudaGetSymbolAddress((void**)&dtb,  g_dt);
    cudaGetSymbolAddress((void**)&ys,   g_ys);
    cudaGetSymbolAddress((void**)&y2,   g_y2);
    cudaGetSymbolAddress((void**)&S,    g_S);
    cudaGetSymbolAddress((void**)&segb, g_seg);
    cudaGetSymbolAddress((void**)&cdb,  g_cd);
    cudaGetSymbolAddress((void**)&scb,  g_sc);
    cudaGetSymbolAddress((void**)&wt,   g_wt);
    cudaGetSymbolAddress((void**)&ahi,  g_ahi);
    cudaGetSymbolAddress((void**)&alo,  g_alo);
    cudaGetSymbolAddress((void**)&hmh,  g_hmh);
    cudaGetSymbolAddress((void**)&hml,  g_hml);
    cudaGetSymbolAddress((void**)&wch,  g_wch);
    cudaGetSymbolAddress((void**)&wih,  g_wih);
    cudaGetSymbolAddress((void**)&woh,  g_woh);

    const int SSD_SMEM = (3 * 64 * SMT + 3 * 64) * (int)sizeof(float);
    cudaFuncSetAttribute(ssd_heads, cudaFuncAttributeMaxDynamicSharedMemorySize, SSD_SMEM);
    const int MG_SMEM = 3 * MG_STAGE;   // 61440
    cudaFuncSetAttribute(mma_gemm, cudaFuncAttributeMaxDynamicSharedMemorySize, MG_SMEM);
    cudaFuncSetAttribute(mma_conv<3>,  cudaFuncAttributeMaxDynamicSharedMemorySize, MG_SMEM);
    cudaFuncSetAttribute(mma_conv<9>,  cudaFuncAttributeMaxDynamicSharedMemorySize, MG_SMEM);
    cudaFuncSetAttribute(mma_conv<27>, cudaFuncAttributeMaxDynamicSharedMemorySize, MG_SMEM);

    // ---- front ----
    gemm128_nt<<<dim3(1, NTOK/128), 256>>>(x, pc_w, hmid, 128, 64, pc_b, hmh, hml);
    transpose_wc<<<(256*384  + 255)/256, 256>>>(c1_w, wt,           3);
    transpose_wc<<<(256*1152 + 255)/256, 256>>>(c2_w, wt + 98304,   9);
    transpose_wc<<<(256*3456 + 255)/256, 256>>>(c3_w, wt + 393216, 27);
    to_half<<<(1277952/4 + 255)/256, 256>>>((const float4*)wt, wch, 1277952/4);
    mma_conv<3> <<<dim3(2, NTOK/64), 128, MG_SMEM>>>(hmh, hml, wch,          c1_b, h, ahi, alo, 0);
    mma_conv<9> <<<dim3(2, NTOK/64), 128, MG_SMEM>>>(hmh, hml, wch + 98304,  c2_b, h, ahi, alo, 256);
    mma_conv<27><<<dim3(2, NTOK/64), 128, MG_SMEM>>>(hmh, hml, wch + 393216, c3_b, h, ahi, alo, 512);

    // ---- weight fp16 conversion ----
    {
        int n4 = 4 * DINPROJ * DMODEL / 4;
        to_half<<<(n4 + 255)/256, 256>>>((const float4*)in_proj, wih, n4);
        int m4 = 4 * DMODEL * DINNER / 4;
        to_half<<<(m4 + 255)/256, 256>>>((const float4*)out_proj, woh, m4);
    }

    // ---- layers ----
    for (int l = 0; l < 4; l++) {
        mma_gemm<<<dim3((DINPROJ + 127)/128, NTOK/64), 128, MG_SMEM>>>(
            ahi, alo, wih + (size_t)l * DINPROJ * DMODEL,
            zx, DINPROJ, DMODEL);
        dt_softplus<<<(NTOK*NHEADS + 255)/256, 256>>>(zx, dt_bias + l*NHEADS, dtb);
        dwconv4<<<dim3((CONVDIM + 255)/256, NTOK/4), 256>>>(
            zx, conv_w + (size_t)l * CONVDIM * 4, conv_b + (size_t)l * CONVDIM, xBC);
        ssd_scores<<<NBC, 256>>>(xBC, scb);
        ssd_heads<<<NBLK_SSD, 256, SSD_SMEM>>>(
            xBC, dtb, scb, A_log + l*NHEADS, Dvec + l*NHEADS, ys, S, segb, cdb);
        ssd_scan8<<<8*NHEADS*8, 256>>>(S, cdb);
        ssd_inter<<<NBLK_SSD, 256>>>(xBC, S, segb, ys);
        gate_rms<<<NTOK, 128>>>(ys, zx, norm_w + (size_t)l * DINNER, ahi, alo);
        mma_gemm<<<dim3(DMODEL/128, NTOK/64), 128, MG_SMEM>>>(
            ahi, alo, woh + (size_t)l * DMODEL * DINNER,
            y2, DMODEL, DINNER);
        resid_ln<<<NTOK, 192>>>(y2, h, ln_w + (size_t)l * DMODEL, ln_b + (size_t)l * DMODEL,
                                ahi, alo);
    }

    // ---- head ----
    head_kernel<<<NTOK, 256>>>(h, fn_w, fn_b, lo_w, lo_b, out);
    (void)in_sizes; (void)n_in; (void)out_size;
}

// round 12
// speedup vs baseline: 1.8438x; 1.0059x over previous
#include <cuda_runtime.h>
#include <cuda_fp16.h>
#include <cstdint>
#include <math.h>

#define NTOK   16384
#define TLEN   2048
#define DMODEL 768
#define DINNER 1536
#define DSTATE 64
#define NHEADS 24
#define CONVDIM 1664
#define DINPROJ 3224
#define NCHUNK 32
#define NBC    256
#define NBLK_SSD (NBC*NHEADS)
#define SMT 68

// ------------------------- scratch (device globals) -------------------------
__device__ float g_h   [(size_t)NTOK*DMODEL];
__device__ float g_zx  [(size_t)NTOK*DINPROJ];
__device__ float g_xBC [(size_t)NTOK*CONVDIM];
__device__ float g_dt  [(size_t)NTOK*NHEADS];
__device__ float g_ys  [(size_t)NTOK*DINNER];
__device__ float g_y2  [(size_t)NTOK*DMODEL];
__device__ float g_S   [(size_t)NBLK_SSD*4096];
__device__ float g_seg [(size_t)NBLK_SSD*64];
__device__ float g_cd  [NBLK_SSD];
__device__ float g_sc  [(size_t)NBC*4096];
__device__ float g_wt  [(size_t)(3+9+27)*128*256];
__device__ __half g_ahi[(size_t)NTOK*DINNER];
__device__ __half g_alo[(size_t)NTOK*DINNER];
__device__ __half g_hmh[(size_t)NTOK*128];
__device__ __half g_hml[(size_t)NTOK*128];
__device__ __half g_wch[(size_t)(3+9+27)*128*256];
__device__ __half g_wih[(size_t)4*DINPROJ*DMODEL];
__device__ __half g_woh[(size_t)4*DMODEL*DINNER];

// ------------------------- PTX helpers -------------------------
__device__ __forceinline__ uint32_t smem_u32(const void* p) {
    uint32_t a;
    asm("{ .reg .u64 t; cvta.to.shared.u64 t, %1; cvt.u32.u64 %0, t; }" : "=r"(a) : "l"(p));
    return a;
}
__device__ __forceinline__ void cp16z(uint32_t dst, const void* src, int srcsz) {
    asm volatile("cp.async.cg.shared.global [%0], [%1], 16, %2;" :: "r"(dst), "l"(src), "r"(srcsz));
}
__device__ __forceinline__ void ldsm4(uint32_t* r, uint32_t addr) {
    asm volatile("ldmatrix.sync.aligned.m8n8.x4.shared.b16 {%0,%1,%2,%3}, [%4];"
        : "=r"(r[0]), "=r"(r[1]), "=r"(r[2]), "=r"(r[3]) : "r"(addr));
}
__device__ __forceinline__ void mma16816(float* c, const uint32_t* a, const uint32_t* b) {
    asm volatile("mma.sync.aligned.m16n8k16.row.col.f32.f16.f16.f32 "
        "{%0,%1,%2,%3}, {%4,%5,%6,%7}, {%8,%9}, {%0,%1,%2,%3};"
        : "+f"(c[0]), "+f"(c[1]), "+f"(c[2]), "+f"(c[3])
        : "r"(a[0]), "r"(a[1]), "r"(a[2]), "r"(a[3]), "r"(b[0]), "r"(b[1]));
}
__device__ __forceinline__ void split1(float v, __half& hi, __half& lo) {
    hi = __float2half_rn(v);
    lo = __float2half_rn(v - __half2float(hi));
}
__device__ __forceinline__ uint32_t pack2(__half a, __half b) {
    return (uint32_t)__half_as_ushort(a) | ((uint32_t)__half_as_ushort(b) << 16);
}

template<int NW>
__device__ __forceinline__ float blockReduceSumT(float v, float* red) {
    int tid = threadIdx.x;
    #pragma unroll
    for (int o = 16; o; o >>= 1) v += __shfl_xor_sync(0xffffffffu, v, o);
    if ((tid & 31) == 0) red[tid >> 5] = v;
    __syncthreads();
    if (tid < 32) {
        float w = (tid < NW) ? red[tid] : 0.f;
        #pragma unroll
        for (int o = 16; o; o >>= 1) w += __shfl_xor_sync(0xffffffffu, w, o);
        if (tid == 0) red[0] = w;
    }
    __syncthreads();
    float r0 = red[0];
    __syncthreads();
    return r0;
}

// ------------------------- convert fp32 -> fp16 (weights) -------------------------
__global__ void to_half(const float4* __restrict__ src, __half* __restrict__ dst, int n4)
{
    int i = blockIdx.x * 256 + threadIdx.x;
    if (i >= n4) return;
    float4 v = src[i];
    uint2 hp = make_uint2(pack2(__float2half_rn(v.x), __float2half_rn(v.y)),
                          pack2(__float2half_rn(v.z), __float2half_rn(v.w)));
    *reinterpret_cast<uint2*>(dst + (size_t)i * 4) = hp;
}

// ------------------------- 2-term split-fp16 NT GEMM, 64x128 tile, 3-stage -------------------------
#define MG_PITCH 80
#define MG_AMAT  5120
#define MG_BBASE 10240
#define MG_STAGE 20480

__device__ __forceinline__ void mg_load(
    uint32_t sbase,
    const __half* __restrict__ Ah, const __half* __restrict__ Al,
    const __half* __restrict__ B,
    int m0, int n0, int Ntot, int K, int c, int tid)
{
    #pragma unroll
    for (int j = 0; j < 4; j++) {
        int e = tid + j * 128;
        int seg = e & 3, r = (e >> 2) & 63, mat = e >> 8;
        uint32_t soff = (uint32_t)(mat * MG_AMAT + r * MG_PITCH + seg * 16);
        const __half* src = (mat ? Al : Ah) + (size_t)(m0 + r) * K + (size_t)c * 32 + seg * 8;
        cp16z(sbase + soff, src, 16);
    }
    #pragma unroll
    for (int j = 0; j < 4; j++) {
        int e = tid + j * 128;
        int seg = e & 3, r = e >> 2;
        uint32_t soff = (uint32_t)(MG_BBASE + r * MG_PITCH + seg * 16);
        int nr = n0 + r;
        int sz = (nr < Ntot) ? 16 : 0;
        int nrc = (nr < Ntot) ? nr : 0;
        const __half* src = B + (size_t)nrc * K + (size_t)c * 32 + seg * 8;
        cp16z(sbase + soff, src, sz);
    }
    asm volatile("cp.async.commit_group;" ::: "memory");
}

__global__ __launch_bounds__(128, 3) void mma_gemm(
    const __half* __restrict__ Ah, const __half* __restrict__ Al,
    const __half* __restrict__ B,
    float* __restrict__ C, int Ntot, int K)
{
    extern __shared__ char smem[];
    uint32_t sb = smem_u32(smem);
    int tid = threadIdx.x, wid = tid >> 5, lane = tid & 31;
    int m0 = blockIdx.y * 64, n0 = blockIdx.x * 128;
    int wm = (wid >> 1) * 32;
    int wn = (wid & 1) * 64;

    float acc[2][8][4];
    #pragma unroll
    for (int a = 0; a < 2; a++)
        #pragma unroll
        for (int b = 0; b < 8; b++)
            #pragma unroll
            for (int q = 0; q < 4; q++) acc[a][b][q] = 0.f;

    int gr = lane >> 3, lr = lane & 7;
    int arow = (gr & 1) * 8 + lr;
    int acol = (gr >> 1) * 16;
    int brow = (gr >> 1) * 8 + lr;
    int bcol = (gr & 1) * 16;

    int nch = K >> 5;
    mg_load(sb, Ah, Al, B, m0, n0, Ntot, K, 0, tid);
    mg_load(sb + MG_STAGE, Ah, Al, B, m0, n0, Ntot, K, 1, tid);
    int sidx = 0;
    for (int c = 0; c < nch; c++) {
        if (c + 2 < nch) {
            asm volatile("cp.async.wait_group 1;" ::: "memory");
        } else {
            asm volatile("cp.async.wait_group 0;" ::: "memory");
        }
        __syncthreads();
        if (c + 2 < nch) {
            int s2 = sidx + 2; if (s2 >= 3) s2 -= 3;
            mg_load(sb + (uint32_t)s2 * MG_STAGE, Ah, Al, B, m0, n0, Ntot, K, c + 2, tid);
        }
        uint32_t base = sb + (uint32_t)sidx * MG_STAGE;
        #pragma unroll
        for (int ks = 0; ks < 2; ks++) {
            uint32_t ah[2][4], al[2][4];
            #pragma unroll
            for (int mt = 0; mt < 2; mt++) {
                uint32_t off = (uint32_t)((wm + mt*16 + arow) * MG_PITCH + acol + ks*32);
                ldsm4(ah[mt], base + off);
                ldsm4(al[mt], base + MG_AMAT + off);
            }
            #pragma unroll
            for (int np = 0; np < 4; np++) {
                uint32_t bb[4];
                uint32_t off = (uint32_t)(MG_BBASE + (wn + np*16 + brow) * MG_PITCH + bcol + ks*32);
                ldsm4(bb, base + off);
                #pragma unroll
                for (int mt = 0; mt < 2; mt++) {
                    mma16816(acc[mt][2*np],   ah[mt], &bb[0]);
                    mma16816(acc[mt][2*np+1], ah[mt], &bb[2]);
                    mma16816(acc[mt][2*np],   al[mt], &bb[0]);
                    mma16816(acc[mt][2*np+1], al[mt], &bb[2]);
                }
            }
        }
        if (++sidx == 3) sidx = 0;
    }

    int r4 = lane >> 2, c2 = (lane & 3) * 2;
    #pragma unroll
    for (int mt = 0; mt < 2; mt++) {
        int r = m0 + wm + mt*16 + r4;
        #pragma unroll
        for (int nt = 0; nt < 8; nt++) {
            int col = n0 + wn + nt*8 + c2;
            if (col < Ntot) {
                float* cc = acc[mt][nt];
                *(float2*)&C[(size_t)r * Ntot + col]       = make_float2(cc[0], cc[1]);
                *(float2*)&C[(size_t)(r + 8) * Ntot + col] = make_float2(cc[2], cc[3]);
            }
        }
    }
}

// ------------------------- 2-term mma conv (implicit im2col), 64x128 tile, 3-stage ----------------
template<int KTAP>
__device__ __forceinline__ void mg_load_conv(
    uint32_t sbase,
    const __half* __restrict__ Ah, const __half* __restrict__ Al,
    const __half* __restrict__ B,
    int m0, int n0, int c, int tid)
{
    const int PAD = KTAP / 2;
    const int K = KTAP * 128;
    int tap = c >> 2;
    int ch0 = (c & 3) * 32;
    #pragma unroll
    for (int j = 0; j < 4; j++) {
        int e = tid + j * 128;
        int seg = e & 3, r = (e >> 2) & 63, mat = e >> 8;
        uint32_t soff = (uint32_t)(mat * MG_AMAT + r * MG_PITCH + seg * 16);
        int tg = m0 + r;
        int tsrc = (tg & (TLEN - 1)) + tap - PAD;
        int valid = (tsrc >= 0 && tsrc < TLEN);
        size_t gidx = valid ? ((size_t)(tg + tap - PAD) * 128 + ch0 + seg * 8) : 0;
        const __half* src = (mat ? Al : Ah) + gidx;
        cp16z(sbase + soff, src, valid ? 16 : 0);
    }
    #pragma unroll
    for (int j = 0; j < 4; j++) {
        int e = tid + j * 128;
        int seg = e & 3, r = e >> 2;
        uint32_t soff = (uint32_t)(MG_BBASE + r * MG_PITCH + seg * 16);
        const __half* src = B + (size_t)(n0 + r) * K + (size_t)c * 32 + seg * 8;
        cp16z(sbase + soff, src, 16);
    }
    asm volatile("cp.async.commit_group;" ::: "memory");
}

template<int KTAP>
__global__ __launch_bounds__(128, 3) void mma_conv(
    const __half* __restrict__ Ah, const __half* __restrict__ Al,
    const __half* __restrict__ B,
    const float* __restrict__ bias, float* __restrict__ Hout,
    __half* __restrict__ ohi, __half* __restrict__ olo, int colofs)
{
    extern __shared__ char smem[];
    uint32_t sb = smem_u32(smem);
    int tid = threadIdx.x, wid = tid >> 5, lane = tid & 31;
    int m0 = blockIdx.y * 64, n0 = blockIdx.x * 128;
    int wm = (wid >> 1) * 32;
    int wn = (wid & 1) * 64;

    float acc[2][8][4];
    #pragma unroll
    for (int a = 0; a < 2; a++)
        #pragma unroll
        for (int b = 0; b < 8; b++)
            #pragma unroll
            for (int q = 0; q < 4; q++) acc[a][b][q] = 0.f;

    int gr = lane >> 3, lr = lane & 7;
    int arow = (gr & 1) * 8 + lr;
    int acol = (gr >> 1) * 16;
    int brow = (gr >> 1) * 8 + lr;
    int bcol = (gr & 1) * 16;

    const int nch = KTAP * 4;
    mg_load_conv<KTAP>(sb, Ah, Al, B, m0, n0, 0, tid);
    mg_load_conv<KTAP>(sb + MG_STAGE, Ah, Al, B, m0, n0, 1, tid);
    int sidx = 0;
    for (int c = 0; c < nch; c++) {
        if (c + 2 < nch) {
            asm volatile("cp.async.wait_group 1;" ::: "memory");
        } else {
            asm volatile("cp.async.wait_group 0;" ::: "memory");
        }
        __syncthreads();
        if (c + 2 < nch) {
            int s2 = sidx + 2; if (s2 >= 3) s2 -= 3;
            mg_load_conv<KTAP>(sb + (uint32_t)s2 * MG_STAGE, Ah, Al, B, m0, n0, c + 2, tid);
        }
        uint32_t base = sb + (uint32_t)sidx * MG_STAGE;
        #pragma unroll
        for (int ks = 0; ks < 2; ks++) {
            uint32_t ah[2][4], al[2][4];
            #pragma unroll
            for (int mt = 0; mt < 2; mt++) {
                uint32_t off = (uint32_t)((wm + mt*16 + arow) * MG_PITCH + acol + ks*32);
                ldsm4(ah[mt], base + off);
                ldsm4(al[mt], base + MG_AMAT + off);
            }
            #pragma unroll
            for (int np = 0; np < 4; np++) {
                uint32_t bb[4];
                uint32_t off = (uint32_t)(MG_BBASE + (wn + np*16 + brow) * MG_PITCH + bcol + ks*32);
                ldsm4(bb, base + off);
                #pragma unroll
                for (int mt = 0; mt < 2; mt++) {
                    mma16816(acc[mt][2*np],   ah[mt], &bb[0]);
                    mma16816(acc[mt][2*np+1], ah[mt], &bb[2]);
                    mma16816(acc[mt][2*np],   al[mt], &bb[0]);
                    mma16816(acc[mt][2*np+1], al[mt], &bb[2]);
                }
            }
        }
        if (++sidx == 3) sidx = 0;
    }

    int r4 = lane >> 2, c2 = (lane & 3) * 2;
    #pragma unroll
    for (int mt = 0; mt < 2; mt++) {
        #pragma unroll
        for (int half = 0; half < 2; half++) {
            int r = m0 + wm + mt*16 + r4 + half*8;
            #pragma unroll
            for (int nt = 0; nt < 8; nt++) {
                int col = n0 + wn + nt*8 + c2;
                float* cc = acc[mt][nt];
                #pragma unroll
                for (int q = 0; q < 2; q++) {
                    float v = cc[half*2 + q] + bias[col + q];
                    v = v / (1.f + expf(-v));
                    size_t idx = (size_t)r * DMODEL + colofs + col + q;
                    Hout[idx] = v;
                    __half hi, lo;
                    split1(v, hi, lo);
                    ohi[idx] = hi;
                    olo[idx] = lo;
                }
            }
        }
    }
}

// ------------------------- front 1x1 conv SGEMM (writes fp16 split only) -------------------------
__global__ __launch_bounds__(256) void gemm128_nt(
    const float* __restrict__ A, const float* __restrict__ B,
    int N, int K,
    const float* __restrict__ bias,
    __half* __restrict__ ohi, __half* __restrict__ olo)
{
    __shared__ float As[8][128];
    __shared__ float Bs[8][128];
    int m0 = blockIdx.y * 128, n0 = blockIdx.x * 128;
    int tid = threadIdx.x;
    int tx = tid & 15, ty = tid >> 4;
    float acc[8][8] = {};
    int lr = tid >> 1;
    int lk = (tid & 1) * 4;
    const float* Ag = A + (size_t)(m0 + lr) * K + lk;
    const float* Bg = B + (size_t)(n0 + lr) * K + lk;
    bool bvalid = (n0 + lr) < N;
    for (int k0 = 0; k0 < K; k0 += 8) {
        float4 av = *(const float4*)(Ag + k0);
        float4 bv = bvalid ? *(const float4*)(Bg + k0) : make_float4(0.f,0.f,0.f,0.f);
        __syncthreads();
        As[lk+0][lr] = av.x; As[lk+1][lr] = av.y; As[lk+2][lr] = av.z; As[lk+3][lr] = av.w;
        Bs[lk+0][lr] = bv.x; Bs[lk+1][lr] = bv.y; Bs[lk+2][lr] = bv.z; Bs[lk+3][lr] = bv.w;
        __syncthreads();
        #pragma unroll
        for (int kk = 0; kk < 8; kk++) {
            float4 a0 = *(const float4*)&As[kk][ty*8];
            float4 a1 = *(const float4*)&As[kk][ty*8+4];
            float4 b0 = *(const float4*)&Bs[kk][tx*8];
            float4 b1 = *(const float4*)&Bs[kk][tx*8+4];
            float a[8] = {a0.x,a0.y,a0.z,a0.w,a1.x,a1.y,a1.z,a1.w};
            float b[8] = {b0.x,b0.y,b0.z,b0.w,b1.x,b1.y,b1.z,b1.w};
            #pragma unroll
            for (int r = 0; r < 8; r++)
                #pragma unroll
                for (int s = 0; s < 8; s++) acc[r][s] += a[r]*b[s];
        }
    }
    #pragma unroll
    for (int r = 0; r < 8; r++) {
        int m = m0 + ty*8 + r;
        #pragma unroll
        for (int s = 0; s < 8; s++) {
            int n = n0 + tx*8 + s;
            if (n < N) {
                float v = acc[r][s] + bias[n];
                v = v / (1.f + expf(-v));
                size_t idx = (size_t)m * N + n;
                __half hi, lo;
                split1(v, hi, lo);
                ohi[idx] = hi;
                olo[idx] = lo;
            }
        }
    }
}

// ------------------------- conv weight NT transpose -------------------------
__global__ void transpose_wc(const float* __restrict__ w, float* __restrict__ wt, int KTAP)
{
    int idx = blockIdx.x * 256 + threadIdx.x;
    int K = KTAP * 128;
    int total = 256 * K;
    if (idx >= total) return;
    int o = idx / K;
    int kk = idx - o * K;
    int tap = kk >> 7;
    int i = kk & 127;
    wt[idx] = w[(size_t)o * 128 * KTAP + (size_t)i * KTAP + tap];
}

// ------------------------- depthwise causal conv + silu + fused dt softplus -------------------------
__global__ void dwconv4(const float* __restrict__ zx, const float* __restrict__ cw,
                        const float* __restrict__ cb, float* __restrict__ xBC,
                        const float* __restrict__ dtb, float* __restrict__ dtout)
{
    int c = blockIdx.x * 256 + threadIdx.x;
    int t0 = blockIdx.y * 4;
    if (c < CONVDIM) {
        int ti0 = t0 & (TLEN - 1);
        float4 w = *(const float4*)(cw + (size_t)c * 4);
        float bias = cb[c];
        float z[7];
        #pragma unroll
        for (int j = 0; j < 7; j++) {
            int ti = ti0 - 3 + j;
            z[j] = (ti >= 0) ? zx[(size_t)(t0 - 3 + j) * DINPROJ + DINNER + c] : 0.f;
        }
        #pragma unroll
        for (int j = 0; j < 4; j++) {
            float acc = bias + z[j]*w.x + z[j+1]*w.y + z[j+2]*w.z + z[j+3]*w.w;
            xBC[(size_t)(t0 + j) * CONVDIM + c] = acc / (1.f + expf(-acc));
        }
    } else if (c < CONVDIM + 4*NHEADS) {
        int q = c - CONVDIM;
        int j = q / NHEADS, hh = q - j * NHEADS;
        int t = t0 + j;
        float xv = zx[(size_t)t * DINPROJ + 3200 + hh] + dtb[hh];
        dtout[(size_t)t * NHEADS + hh] = (xv > 20.f) ? xv : log1pf(expf(xv));
    }
}

// ------------------------- SSD scores (shared across heads) -------------------------
__global__ __launch_bounds__(256) void ssd_scores(
    const float* __restrict__ xBC, float* __restrict__ sc)
{
    __shared__ float BsT[64*SMT];
    __shared__ float CsT[64*SMT];
    int bc = blockIdx.x;
    int t0 = bc * 64;
    int tid = threadIdx.x;
    for (int e = tid; e < 4096; e += 256) {
        int j = e >> 6, n = e & 63;
        const float* row = xBC + (size_t)(t0 + j) * CONVDIM + DINNER;
        BsT[n*SMT + j] = row[n];
        CsT[n*SMT + j] = row[DSTATE + n];
    }
    __syncthreads();
    int tx = tid & 15, ty = tid >> 4;
    float acc[4][4] = {};
    #pragma unroll 4
    for (int n = 0; n < 64; n++) {
        float4 a4 = *(const float4*)&BsT[n*SMT + ty*4];
        float4 b4 = *(const float4*)&CsT[n*SMT + tx*4];
        float a[4] = {a4.x,a4.y,a4.z,a4.w};
        float b[4] = {b4.x,b4.y,b4.z,b4.w};
        #pragma unroll
        for (int r = 0; r < 4; r++)
            #pragma unroll
            for (int s = 0; s < 4; s++) acc[r][s] += a[r]*b[s];
    }
    #pragma unroll
    for (int r = 0; r < 4; r++)
        *(float4*)&sc[(size_t)bc*4096 + (ty*4 + r)*64 + tx*4] =
            make_float4(acc[r][0], acc[r][1], acc[r][2], acc[r][3]);
}

// ------------------------- SSD state: seg scan + S GEMM per (b,c,h) -------------------------
__global__ __launch_bounds__(256) void ssd_state(
    const float* __restrict__ xBC, const float* __restrict__ dt,
    const float* __restrict__ A_log,
    float* __restrict__ Sg, float* __restrict__ segout, float* __restrict__ cdout)
{
    extern __shared__ float sm[];
    float* Bs  = sm;
    float* Ds  = Bs + 64*SMT;
    float* seg = Ds + 64*SMT;
    float* dec = seg + 64;
    float* dts = dec + 64;

    int blk = blockIdx.x;
    int h = blk % NHEADS;
    int bc = blk / NHEADS;
    int t0 = bc * 64;
    int tid = threadIdx.x;
    float A = -expf(A_log[h]);

    if (tid < 64) dts[tid] = dt[(size_t)(t0 + tid) * NHEADS + h];
    __syncthreads();
    for (int e = tid; e < 4096; e += 256) {
        int j = e >> 6, n = e & 63;
        const float* row = xBC + (size_t)(t0 + j) * CONVDIM;
        Bs[j*SMT + n] = row[DINNER + n];
        Ds[j*SMT + n] = dts[j] * row[h*64 + n];
    }
    if (tid < 64) seg[tid] = dts[tid] * A;
    __syncthreads();
    for (int off = 1; off < 64; off <<= 1) {
        float v = 0.f;
        bool act = (tid < 64) && (tid >= off);
        if (act) v = seg[tid - off];
        __syncthreads();
        if (act) seg[tid] += v;
        __syncthreads();
    }
    if (tid < 64) {
        dec[tid] = expf(seg[63] - seg[tid]);
        segout[(size_t)blk * 64 + tid] = seg[tid];
    }
    if (tid == 0) cdout[blk] = expf(seg[63]);
    __syncthreads();

    int tx = tid & 15, ty = tid >> 4;
    float acc3[4][4] = {};
    #pragma unroll 4
    for (int j = 0; j < 64; j++) {
        float dj = dec[j];
        float4 a4 = *(const float4*)&Ds[j*SMT + ty*4];
        float4 b4 = *(const float4*)&Bs[j*SMT + tx*4];
        float a[4] = {a4.x*dj, a4.y*dj, a4.z*dj, a4.w*dj};
        float b[4] = {b4.x,b4.y,b4.z,b4.w};
        #pragma unroll
        for (int r = 0; r < 4; r++)
            #pragma unroll
            for (int s = 0; s < 4; s++) acc3[r][s] += a[r]*b[s];
    }
    #pragma unroll
    for (int r = 0; r < 4; r++)
        *(float4*)&Sg[(size_t)blk * 4096 + (ty*4 + r)*64 + tx*4] =
            make_float4(acc3[r][0], acc3[r][1], acc3[r][2], acc3[r][3]);
}

// ------------------------- inter-chunk scan (8-way partitioned) -------------------------
__global__ __launch_bounds__(256) void ssd_scan8(float* __restrict__ Sg,
                                                 const float* __restrict__ cd)
{
    int blk = blockIdx.x;
    int part = blk & 7;
    int bh = blk >> 3;
    int h = bh % NHEADS, b = bh / NHEADS;
    int tid = threadIdx.x;
    int e0 = part * 512 + tid;
    float st0 = 0.f, st1 = 0.f;
    for (int c = 0; c < NCHUNK; c++) {
        int bidx = (b * NCHUNK + c) * NHEADS + h;
        size_t base = (size_t)bidx * 4096;
        float d = cd[bidx];
        float s0 = Sg[base + e0];
        float s1 = Sg[base + e0 + 256];
        Sg[base + e0]       = st0;
        Sg[base + e0 + 256] = st1;
        st0 = st0 * d + s0;
        st1 = st1 * d + s1;
    }
}

// ------------------------- SSD final: y_diag + y_inter + D*x, single ys write -------------------------
__global__ __launch_bounds__(256) void ssd_final(
    const float* __restrict__ xBC, const float* __restrict__ dt,
    const float* __restrict__ sc, const float* __restrict__ Sg,
    const float* __restrict__ segin, const float* __restrict__ Dv,
    float* __restrict__ ys)
{
    extern __shared__ float sm[];
    float* aT  = sm;              // [j][i] att transposed
    float* Ds  = aT + 64*SMT;     // [j][p] dtx
    float* CsT = Ds + 64*SMT;     // [n][i]
    float* HsT = CsT + 64*SMT;    // [n][p]
    float* seg = HsT + 64*SMT;
    float* dts = seg + 64;

    int blk = blockIdx.x;
    int h = blk % NHEADS;
    int bc = blk / NHEADS;
    int t0 = bc * 64;
    int tid = threadIdx.x;

    if (tid < 64) {
        seg[tid] = segin[(size_t)blk * 64 + tid];
        dts[tid] = dt[(size_t)(t0 + tid) * NHEADS + h];
    }
    __syncthreads();
    for (int e = tid; e < 4096; e += 256) {
        int j = e >> 6, n = e & 63;
        const float* row = xBC + (size_t)(t0 + j) * CONVDIM;
        Ds[j*SMT + n] = dts[j] * row[h*64 + n];
        CsT[n*SMT + j] = row[DINNER + DSTATE + n];
        HsT[n*SMT + j] = Sg[(size_t)blk * 4096 + j*64 + n];
        float v = 0.f;
        if (n >= j) v = expf(seg[n] - seg[j]) * sc[(size_t)bc*4096 + e];
        aT[j*SMT + n] = v;     // aT[j][i], i = n index here
    }
    __syncthreads();

    int tx = tid & 15, ty = tid >> 4;
    float acc2[4][4] = {};
    #pragma unroll 4
    for (int j = 0; j < 64; j++) {
        float4 a4 = *(const float4*)&aT[j*SMT + ty*4];
        float4 b4 = *(const float4*)&Ds[j*SMT + tx*4];
        float a[4] = {a4.x,a4.y,a4.z,a4.w};
        float b[4] = {b4.x,b4.y,b4.z,b4.w};
        #pragma unroll
        for (int r = 0; r < 4; r++)
            #pragma unroll
            for (int s = 0; s < 4; s++) acc2[r][s] += a[r]*b[s];
    }
    float acc[4][4] = {};
    #pragma unroll 4
    for (int n = 0; n < 64; n++) {
        float4 a4 = *(const float4*)&CsT[n*SMT + ty*4];
        float4 b4 = *(const float4*)&HsT[n*SMT + tx*4];
        float a[4] = {a4.x,a4.y,a4.z,a4.w};
        float b[4] = {b4.x,b4.y,b4.z,b4.w};
        #pragma unroll
        for (int r = 0; r < 4; r++)
            #pragma unroll
            for (int s = 0; s < 4; s++) acc[r][s] += a[r]*b[s];
    }
    float Dh = Dv[h];
    #pragma unroll
    for (int r = 0; r < 4; r++) {
        int i = t0 + ty*4 + r;
        float ei = expf(seg[ty*4 + r]);
        float4 xs = *(const float4*)&xBC[(size_t)i * CONVDIM + h*64 + tx*4];
        float4 o = make_float4(acc2[r][0] + acc[r][0]*ei + Dh*xs.x,
                               acc2[r][1] + acc[r][1]*ei + Dh*xs.y,
                               acc2[r][2] + acc[r][2]*ei + Dh*xs.z,
                               acc2[r][3] + acc[r][3]*ei + Dh*xs.w);
        *(float4*)&ys[(size_t)i * DINNER + h*64 + tx*4] = o;
    }
}

// ------------------------- gating + RMSNorm (float4, 128 thr, writes fp16 split) ------------------
__global__ __launch_bounds__(128) void gate_rms(
    const float* __restrict__ ys, const float* __restrict__ zx,
    const float* __restrict__ nw,
    __half* __restrict__ ohi, __half* __restrict__ olo)
{
    __shared__ float red[32];
    int t = blockIdx.x, tid = threadIdx.x;
    float4 v[3];
    float ss = 0.f;
    #pragma unroll
    for (int r = 0; r < 3; r++) {
        int i = (tid + r*128) * 4;
        float4 yv = *(const float4*)&ys[(size_t)t * DINNER + i];
        float4 zv = *(const float4*)&zx[(size_t)t * DINPROJ + i];
        float4 val;
        val.x = yv.x * (zv.x / (1.f + expf(-zv.x)));
        val.y = yv.y * (zv.y / (1.f + expf(-zv.y)));
        val.z = yv.z * (zv.z / (1.f + expf(-zv.z)));
        val.w = yv.w * (zv.w / (1.f + expf(-zv.w)));
        v[r] = val;
        ss += val.x*val.x + val.y*val.y + val.z*val.z + val.w*val.w;
    }
    ss = blockReduceSumT<4>(ss, red);
    float sc = rsqrtf(ss / (float)DINNER + 1e-5f);
    #pragma unroll
    for (int r = 0; r < 3; r++) {
        int i = (tid + r*128) * 4;
        float4 wv = *(const float4*)&nw[i];
        __half h4[4], l4[4];
        split1(v[r].x * sc * wv.x, h4[0], l4[0]);
        split1(v[r].y * sc * wv.y, h4[1], l4[1]);
        split1(v[r].z * sc * wv.z, h4[2], l4[2]);
        split1(v[r].w * sc * wv.w, h4[3], l4[3]);
        size_t idx = (size_t)t * DINNER + i;
        *reinterpret_cast<uint2*>(ohi + idx) = make_uint2(pack2(h4[0], h4[1]), pack2(h4[2], h4[3]));
        *reinterpret_cast<uint2*>(olo + idx) = make_uint2(pack2(l4[0], l4[1]), pack2(l4[2], l4[3]));
    }
}

// ------------------------- residual + layernorm (float4, 192 thr, writes h + split) ---------------
__global__ __launch_bounds__(192) void resid_ln(
    const float* __restrict__ y2, float* __restrict__ hio,
    const float* __restrict__ w, const float* __restrict__ b,
    __half* __restrict__ ohi, __half* __restrict__ olo)
{
    __shared__ float red[32];
    int t = blockIdx.x, tid = threadIdx.x;
    int i = tid * 4;
    float4 a = *(const float4*)&y2[(size_t)t * DMODEL + i];
    float4 hh = *(const float4*)&hio[(size_t)t * DMODEL + i];
    float4 v = make_float4(a.x + hh.x, a.y + hh.y, a.z + hh.z, a.w + hh.w);
    float s = v.x + v.y + v.z + v.w;
    s = blockReduceSumT<6>(s, red);
    float mean = s / (float)DMODEL;
    v.x -= mean; v.y -= mean; v.z -= mean; v.w -= mean;
    float q = v.x*v.x + v.y*v.y + v.z*v.z + v.w*v.w;
    q = blockReduceSumT<6>(q, red);
    float inv = rsqrtf(q / (float)DMODEL + 1e-5f);
    float4 wv = *(const float4*)&w[i];
    float4 bv = *(const float4*)&b[i];
    float4 val = make_float4(v.x*inv*wv.x + bv.x, v.y*inv*wv.y + bv.y,
                             v.z*inv*wv.z + bv.z, v.w*inv*wv.w + bv.w);
    size_t idx = (size_t)t * DMODEL + i;
    *(float4*)&hio[idx] = val;
    __half h4[4], l4[4];
    split1(val.x, h4[0], l4[0]);
    split1(val.y, h4[1], l4[1]);
    split1(val.z, h4[2], l4[2]);
    split1(val.w, h4[3], l4[3]);
    *reinterpret_cast<uint2*>(ohi + idx) = make_uint2(pack2(h4[0], h4[1]), pack2(h4[2], h4[3]));
    *reinterpret_cast<uint2*>(olo + idx) = make_uint2(pack2(l4[0], l4[1]), pack2(l4[2], l4[3]));
}

// ------------------------- final layernorm + logits -------------------------
__global__ __launch_bounds__(256) void head_kernel(
    const float* __restrict__ hin,
    const float* __restrict__ fw, const float* __restrict__ fb,
    const float* __restrict__ lw, const float* __restrict__ lb,
    float* __restrict__ out)
{
    __shared__ float red[32];
    __shared__ float buf[DMODEL];
    int t = blockIdx.x, tid = threadIdx.x;
    float v[3];
    float s = 0.f;
    #pragma unroll
    for (int r = 0; r < 3; r++) {
        int i = tid + r*256;
        v[r] = hin[(size_t)t * DMODEL + i];
        s += v[r];
    }
    s = blockReduceSumT<8>(s, red);
    float mean = s / (float)DMODEL;
    float q = 0.f;
    #pragma unroll
    for (int r = 0; r < 3; r++) { v[r] -= mean; q += v[r]*v[r]; }
    q = blockReduceSumT<8>(q, red);
    float inv = rsqrtf(q / (float)DMODEL + 1e-5f);
    #pragma unroll
    for (int r = 0; r < 3; r++) {
        int i = tid + r*256;
        buf[i] = v[r] * inv * fw[i] + fb[i];
    }
    __syncthreads();
    for (int cls = 0; cls < 10; cls++) {
        float p = 0.f;
        #pragma unroll
        for (int r = 0; r < 3; r++) {
            int i = tid + r*256;
            p += buf[i] * lw[(size_t)cls * DMODEL + i];
        }
        p = blockReduceSumT<8>(p, red);
        if (tid == 0) out[(size_t)t * 10 + cls] = p + lb[cls];
    }
}

// ------------------------- launch -------------------------
extern "C" void kernel_launch(void* const* d_in, const int* in_sizes, int n_in,
                              void* d_out, int out_size)
{
    const float* x       = (const float*)d_in[0];
    const float* pc_w    = (const float*)d_in[1];
    const float* pc_b    = (const float*)d_in[2];
    const float* c1_w    = (const float*)d_in[3];
    const float* c1_b    = (const float*)d_in[4];
    const float* c2_w    = (const float*)d_in[5];
    const float* c2_b    = (const float*)d_in[6];
    const float* c3_w    = (const float*)d_in[7];
    const float* c3_b    = (const float*)d_in[8];
    const float* in_proj = (const float*)d_in[9];
    const float* conv_w  = (const float*)d_in[10];
    const float* conv_b  = (const float*)d_in[11];
    const float* dt_bias = (const float*)d_in[12];
    const float* A_log   = (const float*)d_in[13];
    const float* Dvec    = (const float*)d_in[14];
    const float* norm_w  = (const float*)d_in[15];
    const float* out_proj= (const float*)d_in[16];
    const float* ln_w    = (const float*)d_in[17];
    const float* ln_b    = (const float*)d_in[18];
    const float* fn_w    = (const float*)d_in[19];
    const float* fn_b    = (const float*)d_in[20];
    const float* lo_w    = (const float*)d_in[21];
    const float* lo_b    = (const float*)d_in[22];
    float* out = (float*)d_out;

    float *h, *zx, *xBC, *dtb, *ys, *y2, *S, *segb, *cdb, *scb, *wt;
    __half *ahi, *alo, *hmh, *hml, *wch, *wih, *woh;
    cudaGetSymbolAddress((void**)&h,    g_h);
    cudaGetSymbolAddress((void**)&zx,   g_zx);
    cudaGetSymbolAddress((void**)&xBC,  g_xBC);
    cudaGetSymbolAddress((void**)&dtb,  g_dt);
    cudaGetSymbolAddress((void**)&ys,   g_ys);
    cudaGetSymbolAddress((void**)&y2,   g_y2);
    cudaGetSymbolAddress((void**)&S,    g_S);
    cudaGetSymbolAddress((void**)&segb, g_seg);
    cudaGetSymbolAddress((void**)&cdb,  g_cd);
    cudaGetSymbolAddress((void**)&scb,  g_sc);
    cudaGetSymbolAddress((void**)&wt,   g_wt);
    cudaGetSymbolAddress((void**)&ahi,  g_ahi);
    cudaGetSymbolAddress((void**)&alo,  g_alo);
    cudaGetSymbolAddress((void**)&hmh,  g_hmh);
    cudaGetSymbolAddress((void**)&hml,  g_hml);
    cudaGetSymbolAddress((void**)&wch,  g_wch);
    cudaGetSymbolAddress((void**)&wih,  g_wih);
    cudaGetSymbolAddress((void**)&woh,  g_woh);

    const int STATE_SMEM = (2 * 64 * SMT + 3 * 64) * (int)sizeof(float);  // 35584
    const int FINAL_SMEM = (4 * 64 * SMT + 2 * 64) * (int)sizeof(float);  // 70144
    cudaFuncSetAttribute(ssd_state, cudaFuncAttributeMaxDynamicSharedMemorySize, STATE_SMEM);
    cudaFuncSetAttribute(ssd_final, cudaFuncAttributeMaxDynamicSharedMemorySize, FINAL_SMEM);
    const int MG_SMEM = 3 * MG_STAGE;   // 61440
    cudaFuncSetAttribute(mma_gemm, cudaFuncAttributeMaxDynamicSharedMemorySize, MG_SMEM);
    cudaFuncSetAttribute(mma_conv<3>,  cudaFuncAttributeMaxDynamicSharedMemorySize, MG_SMEM);
    cudaFuncSetAttribute(mma_conv<9>,  cudaFuncAttributeMaxDynamicSharedMemorySize, MG_SMEM);
    cudaFuncSetAttribute(mma_conv<27>, cudaFuncAttributeMaxDynamicSharedMemorySize, MG_SMEM);

    // ---- front ----
    gemm128_nt<<<dim3(1, NTOK/128), 256>>>(x, pc_w, 128, 64, pc_b, hmh, hml);
    transpose_wc<<<(256*384  + 255)/256, 256>>>(c1_w, wt,           3);
    transpose_wc<<<(256*1152 + 255)/256, 256>>>(c2_w, wt + 98304,   9);
    transpose_wc<<<(256*3456 + 255)/256, 256>>>(c3_w, wt + 393216, 27);
    to_half<<<(1277952/4 + 255)/256, 256>>>((const float4*)wt, wch, 1277952/4);
    mma_conv<3> <<<dim3(2, NTOK/64), 128, MG_SMEM>>>(hmh, hml, wch,          c1_b, h, ahi, alo, 0);
    mma_conv<9> <<<dim3(2, NTOK/64), 128, MG_SMEM>>>(hmh, hml, wch + 98304,  c2_b, h, ahi, alo, 256);
    mma_conv<27><<<dim3(2, NTOK/64), 128, MG_SMEM>>>(hmh, hml, wch + 393216, c3_b, h, ahi, alo, 512);

    // ---- weight fp16 conversion ----
    {
        int n4 = 4 * DINPROJ * DMODEL / 4;
        to_half<<<(n4 + 255)/256, 256>>>((const float4*)in_proj, wih, n4);
        int m4 = 4 * DMODEL * DINNER / 4;
        to_half<<<(m4 + 255)/256, 256>>>((const float4*)out_proj, woh, m4);
    }

    // ---- layers ----
    for (int l = 0; l < 4; l++) {
        mma_gemm<<<dim3((DINPROJ + 127)/128, NTOK/64), 128, MG_SMEM>>>(
            ahi, alo, wih + (size_t)l * DINPROJ * DMODEL,
            zx, DINPROJ, DMODEL);
        dwconv4<<<dim3((CONVDIM + 4*NHEADS + 255)/256, NTOK/4), 256>>>(
            zx, conv_w + (size_t)l * CONVDIM * 4, conv_b + (size_t)l * CONVDIM, xBC,
            dt_bias + l*NHEADS, dtb);
        ssd_scores<<<NBC, 256>>>(xBC, scb);
        ssd_state<<<NBLK_SSD, 256, STATE_SMEM>>>(
            xBC, dtb, A_log + l*NHEADS, S, segb, cdb);
        ssd_scan8<<<8*NHEADS*8, 256>>>(S, cdb);
        ssd_final<<<NBLK_SSD, 256, FINAL_SMEM>>>(
            xBC, dtb, scb, S, segb, Dvec + l*NHEADS, ys);
        gate_rms<<<NTOK, 128>>>(ys, zx, norm_w + (size_t)l * DINNER, ahi, alo);
        mma_gemm<<<dim3(DMODEL/128, NTOK/64), 128, MG_SMEM>>>(
            ahi, alo, woh + (size_t)l * DMODEL * DINNER,
            y2, DMODEL, DINNER);
        resid_ln<<<NTOK, 192>>>(y2, h, ln_w + (size_t)l * DMODEL, ln_b + (size_t)l * DMODEL,
                                ahi, alo);
    }

    // ---- head ----
    head_kernel<<<NTOK, 256>>>(h, fn_w, fn_b, lo_w, lo_b, out);
    (void)in_sizes; (void)n_in; (void)out_size;
}